// round 1
// baseline (speedup 1.0000x reference)
#include <cuda_runtime.h>
#include <math.h>

// Problem constants
#define BROWS 16384
#define D     1024

// Output layout: retrieved (B*D) | loss (1) | new_weight (D*D) | new_momentum (D*D) | gates (3)
#define RET_OFF   0
#define LOSS_OFF  (BROWS * D)                 // 16777216
#define W_OFF     (LOSS_OFF + 1)              // 16777217 (odd -> scalar stores only)
#define NM_OFF    (W_OFF + D * D)             // 17825793 (odd -> scalar stores only)
#define GATES_OFF (NM_OFF + D * D)            // 18874369

#define MEM_MAX_NORM 5.0f
#define TTT_LR 0.005f
#define TWO_OVER_N (2.0f / (float)(BROWS * D))

// ---------------- device scratch (static, no runtime allocation) ----------------
__device__ float g_kagg_part[64][D];
__device__ float g_kagg[D];
__device__ float g_scalars[8];        // 0:alpha 1:eta 2:theta 4:scale_m 5:scale_w
__device__ float g_loss_part[1024];
__device__ float g_grad_part[4][D * D];   // split-B partials for GEMM2 (16 MB)
__device__ float g_nm_raw[D * D];
__device__ float g_w_raw[D * D];
__device__ float g_norm_part[2][256];

// ---------------- k_agg: column sums of k ----------------
__global__ void colsum_kernel(const float* __restrict__ K) {
    int c  = blockIdx.x * 128 + threadIdx.x;   // column
    int r0 = blockIdx.y * 256;                 // row chunk
    float s = 0.f;
    #pragma unroll 4
    for (int r = r0; r < r0 + 256; ++r) s += K[r * D + c];
    g_kagg_part[blockIdx.y][c] = s;
}

__global__ void kagg_reduce_kernel() {
    int c = blockIdx.x * 256 + threadIdx.x;
    float s = 0.f;
    #pragma unroll
    for (int p = 0; p < 64; ++p) s += g_kagg_part[p][c];
    g_kagg[c] = s * (1.0f / (float)BROWS);
}

// ---------------- gates = sigmoid(gate_w @ k_agg + gate_b) ----------------
__global__ void gates_kernel(const float* __restrict__ GW, const float* __restrict__ GB,
                             float* __restrict__ out) {
    __shared__ float red[128];
    int tid = threadIdx.x;
    for (int g = 0; g < 3; ++g) {
        float p = 0.f;
        for (int c = tid; c < D; c += 128) p += GW[g * D + c] * g_kagg[c];
        red[tid] = p;
        __syncthreads();
        for (int s = 64; s > 0; s >>= 1) {
            if (tid < s) red[tid] += red[tid + s];
            __syncthreads();
        }
        if (tid == 0) {
            float z  = red[0] + GB[g];
            float sg = 1.0f / (1.0f + expf(-z));
            g_scalars[g] = sg;
            out[GATES_OFF + g] = sg;
        }
        __syncthreads();
    }
}

// ---------------- GEMM1: retrieved = K @ W^T, fused loss partial ----------------
// C[m][n] = sum_k K[m][k]*W[n][k].  Tiles 128x128x8, 256 threads, 8x8 microtile.
__global__ __launch_bounds__(256) void gemm1_kernel(
    const float* __restrict__ K, const float* __restrict__ W,
    const float* __restrict__ V, float* __restrict__ out) {
    __shared__ float As[8][128];
    __shared__ float Bs[8][128];
    __shared__ float red[256];

    const int n0 = blockIdx.x * 128;
    const int m0 = blockIdx.y * 128;
    const int tid = threadIdx.x;
    const int tx = tid & 15, ty = tid >> 4;
    const int lrow = tid >> 1;
    const int lk4  = (tid & 1) * 4;

    float acc[8][8];
    #pragma unroll
    for (int i = 0; i < 8; ++i)
        #pragma unroll
        for (int j = 0; j < 8; ++j) acc[i][j] = 0.f;

    const float* Aptr = K + (m0 + lrow) * D + lk4;
    const float* Bptr = W + (n0 + lrow) * D + lk4;

    for (int k0 = 0; k0 < D; k0 += 8) {
        float4 av = *(const float4*)(Aptr + k0);
        float4 bv = *(const float4*)(Bptr + k0);
        As[lk4 + 0][lrow] = av.x; As[lk4 + 1][lrow] = av.y;
        As[lk4 + 2][lrow] = av.z; As[lk4 + 3][lrow] = av.w;
        Bs[lk4 + 0][lrow] = bv.x; Bs[lk4 + 1][lrow] = bv.y;
        Bs[lk4 + 2][lrow] = bv.z; Bs[lk4 + 3][lrow] = bv.w;
        __syncthreads();
        #pragma unroll
        for (int kk = 0; kk < 8; ++kk) {
            float a[8], b[8];
            #pragma unroll
            for (int i = 0; i < 8; ++i) a[i] = As[kk][ty * 8 + i];
            #pragma unroll
            for (int j = 0; j < 8; ++j) b[j] = Bs[kk][tx * 8 + j];
            #pragma unroll
            for (int i = 0; i < 8; ++i)
                #pragma unroll
                for (int j = 0; j < 8; ++j)
                    acc[i][j] = fmaf(a[i], b[j], acc[i][j]);
        }
        __syncthreads();
    }

    // Epilogue: write retrieved (float4), accumulate (r - v)^2 partial
    float lsum = 0.f;
    #pragma unroll
    for (int i = 0; i < 8; ++i) {
        int m = m0 + ty * 8 + i;
        int base = m * D + n0 + tx * 8;
        float4 v0 = *(const float4*)(V + base);
        float4 v1 = *(const float4*)(V + base + 4);
        float4 c0 = make_float4(acc[i][0], acc[i][1], acc[i][2], acc[i][3]);
        float4 c1 = make_float4(acc[i][4], acc[i][5], acc[i][6], acc[i][7]);
        *(float4*)(out + RET_OFF + base)     = c0;
        *(float4*)(out + RET_OFF + base + 4) = c1;
        float d;
        d = c0.x - v0.x; lsum += d * d;
        d = c0.y - v0.y; lsum += d * d;
        d = c0.z - v0.z; lsum += d * d;
        d = c0.w - v0.w; lsum += d * d;
        d = c1.x - v1.x; lsum += d * d;
        d = c1.y - v1.y; lsum += d * d;
        d = c1.z - v1.z; lsum += d * d;
        d = c1.w - v1.w; lsum += d * d;
    }
    red[tid] = lsum;
    __syncthreads();
    for (int s = 128; s > 0; s >>= 1) {
        if (tid < s) red[tid] += red[tid + s];
        __syncthreads();
    }
    if (tid == 0) g_loss_part[blockIdx.y * gridDim.x + blockIdx.x] = red[0];
}

__global__ void loss_reduce_kernel(float* __restrict__ out) {
    __shared__ float red[1024];
    int tid = threadIdx.x;
    red[tid] = g_loss_part[tid];
    __syncthreads();
    for (int s = 512; s > 0; s >>= 1) {
        if (tid < s) red[tid] += red[tid + s];
        __syncthreads();
    }
    if (tid == 0) out[LOSS_OFF] = red[0] / (float)(BROWS * D);
}

// ---------------- GEMM2: grad_part[z][i][j] = sum_{b in slice z} (R[b][i]-V[b][i]) * K[b][j] ----------------
__global__ __launch_bounds__(256) void gemm2_kernel(
    const float* __restrict__ R, const float* __restrict__ V,
    const float* __restrict__ K) {
    __shared__ float Ds[8][128];
    __shared__ float Ks[8][128];

    const int j0 = blockIdx.x * 128;  // key dim
    const int i0 = blockIdx.y * 128;  // val dim
    const int z  = blockIdx.z;
    const int tid = threadIdx.x;
    const int tx = tid & 15, ty = tid >> 4;
    const int lr  = tid >> 5;         // 0..7
    const int lc4 = (tid & 31) * 4;   // 0..124

    float acc[8][8];
    #pragma unroll
    for (int i = 0; i < 8; ++i)
        #pragma unroll
        for (int j = 0; j < 8; ++j) acc[i][j] = 0.f;

    const int b0 = z * (BROWS / 4);
    const int b1 = b0 + (BROWS / 4);
    for (int b = b0; b < b1; b += 8) {
        int rowbase = (b + lr) * D;
        float4 rv = *(const float4*)(R + rowbase + i0 + lc4);
        float4 vv = *(const float4*)(V + rowbase + i0 + lc4);
        float4 kv = *(const float4*)(K + rowbase + j0 + lc4);
        Ds[lr][lc4 + 0] = rv.x - vv.x; Ds[lr][lc4 + 1] = rv.y - vv.y;
        Ds[lr][lc4 + 2] = rv.z - vv.z; Ds[lr][lc4 + 3] = rv.w - vv.w;
        *(float4*)&Ks[lr][lc4] = kv;
        __syncthreads();
        #pragma unroll
        for (int kk = 0; kk < 8; ++kk) {
            float a[8], bb[8];
            #pragma unroll
            for (int i = 0; i < 8; ++i) a[i] = Ds[kk][ty * 8 + i];
            #pragma unroll
            for (int j = 0; j < 8; ++j) bb[j] = Ks[kk][tx * 8 + j];
            #pragma unroll
            for (int i = 0; i < 8; ++i)
                #pragma unroll
                for (int j = 0; j < 8; ++j)
                    acc[i][j] = fmaf(a[i], bb[j], acc[i][j]);
        }
        __syncthreads();
    }

    float* gp = g_grad_part[z];
    #pragma unroll
    for (int i = 0; i < 8; ++i) {
        int base = (i0 + ty * 8 + i) * D + j0 + tx * 8;
        *(float4*)(gp + base)     = make_float4(acc[i][0], acc[i][1], acc[i][2], acc[i][3]);
        *(float4*)(gp + base + 4) = make_float4(acc[i][4], acc[i][5], acc[i][6], acc[i][7]);
    }
}

// ---------------- momentum: nm_raw = eta*mom - lr*theta*clip(grad), norm partial ----------------
__global__ void momentum_prep_kernel(const float* __restrict__ MOM) {
    __shared__ float red[256];
    int tid = threadIdx.x;
    int t = blockIdx.x * 256 + tid;  // 65536 threads total
    float eta = g_scalars[1], theta = g_scalars[2];
    float lr_th = TTT_LR * theta;
    float nsum = 0.f;
    #pragma unroll
    for (int it = 0; it < 16; ++it) {
        int e = t + it * 65536;
        float g = (g_grad_part[0][e] + g_grad_part[1][e] +
                   g_grad_part[2][e] + g_grad_part[3][e]) * TWO_OVER_N;
        float gc = fminf(1.0f, fmaxf(-1.0f, g));
        float nm = eta * MOM[e] - lr_th * gc;
        g_nm_raw[e] = nm;
        nsum += nm * nm;
    }
    red[tid] = nsum;
    __syncthreads();
    for (int s = 128; s > 0; s >>= 1) {
        if (tid < s) red[tid] += red[tid + s];
        __syncthreads();
    }
    if (tid == 0) g_norm_part[0][blockIdx.x] = red[0];
}

__global__ void norm_scale_kernel(int which) {
    __shared__ float red[256];
    int tid = threadIdx.x;
    red[tid] = g_norm_part[which][tid];
    __syncthreads();
    for (int s = 128; s > 0; s >>= 1) {
        if (tid < s) red[tid] += red[tid + s];
        __syncthreads();
    }
    if (tid == 0) {
        float n = sqrtf(red[0]);
        g_scalars[4 + which] = (n > MEM_MAX_NORM) ? (MEM_MAX_NORM / (n + 1e-8f)) : 1.0f;
    }
}

// ---------------- weight: nm final -> out, w_raw = (1-alpha)*W + nm, norm partial ----------------
__global__ void weight_prep_kernel(const float* __restrict__ MW, float* __restrict__ out) {
    __shared__ float red[256];
    int tid = threadIdx.x;
    int t = blockIdx.x * 256 + tid;
    float alpha = g_scalars[0];
    float sm = g_scalars[4];
    float one_m_a = 1.0f - alpha;
    float wsum = 0.f;
    #pragma unroll
    for (int it = 0; it < 16; ++it) {
        int e = t + it * 65536;
        float nm = g_nm_raw[e] * sm;
        out[NM_OFF + e] = nm;                 // odd offset -> scalar store
        float w = one_m_a * MW[e] + nm;
        g_w_raw[e] = w;
        wsum += w * w;
    }
    red[tid] = wsum;
    __syncthreads();
    for (int s = 128; s > 0; s >>= 1) {
        if (tid < s) red[tid] += red[tid + s];
        __syncthreads();
    }
    if (tid == 0) g_norm_part[1][blockIdx.x] = red[0];
}

__global__ void final_w_kernel(float* __restrict__ out) {
    int t = blockIdx.x * 256 + threadIdx.x;
    float sw = g_scalars[5];
    #pragma unroll
    for (int it = 0; it < 16; ++it) {
        int e = t + it * 65536;
        out[W_OFF + e] = g_w_raw[e] * sw;     // odd offset -> scalar store
    }
}

// ---------------- launch ----------------
extern "C" void kernel_launch(void* const* d_in, const int* in_sizes, int n_in,
                              void* d_out, int out_size) {
    const float* k    = (const float*)d_in[0];
    const float* v    = (const float*)d_in[1];
    const float* memw = (const float*)d_in[2];
    const float* gw   = (const float*)d_in[3];
    const float* gb   = (const float*)d_in[4];
    const float* mom  = (const float*)d_in[5];
    float* out = (float*)d_out;

    // k_agg + gates
    colsum_kernel<<<dim3(8, 64), 128>>>(k);
    kagg_reduce_kernel<<<4, 256>>>();
    gates_kernel<<<1, 128>>>(gw, gb, out);

    // retrieved + loss
    gemm1_kernel<<<dim3(8, 128), 256>>>(k, memw, v, out);
    loss_reduce_kernel<<<1, 1024>>>(out);

    // grad (split-B x4)
    gemm2_kernel<<<dim3(8, 8, 4), 256>>>(out + RET_OFF, v, k);

    // momentum / weight updates with norm clips
    momentum_prep_kernel<<<256, 256>>>(mom);
    norm_scale_kernel<<<1, 256>>>(0);
    weight_prep_kernel<<<256, 256>>>(memw, out);
    norm_scale_kernel<<<1, 256>>>(1);
    final_w_kernel<<<256, 256>>>(out);
}

// round 3
// speedup vs baseline: 2.6990x; 2.6990x over previous
#include <cuda_runtime.h>
#include <math.h>
#include <stdint.h>

// Problem constants
#define BROWS 16384
#define D     1024

// Output layout: retrieved (B*D) | loss (1) | new_weight (D*D) | new_momentum (D*D) | gates (3)
#define RET_OFF   0
#define LOSS_OFF  (BROWS * D)
#define W_OFF     (LOSS_OFF + 1)              // odd -> scalar stores only
#define NM_OFF    (W_OFF + D * D)             // odd -> scalar stores only
#define GATES_OFF (NM_OFF + D * D)

#define MEM_MAX_NORM 5.0f
#define TTT_LR 0.005f
#define TWO_OVER_N (2.0f / (float)(BROWS * D))

// ---------------- device scratch (static, no runtime allocation) ----------------
__device__ float g_kagg_part[64][D];
__device__ float g_kagg[D];
__device__ float g_scalars[8];        // 0:alpha 1:eta 2:theta 4:scale_m 5:scale_w
__device__ float g_loss_part[1024];
__device__ float g_grad_part[4][D * D];   // split-B partials for GEMM2 (16 MB)
__device__ float g_nm_raw[D * D];
__device__ float g_w_raw[D * D];
__device__ float g_norm_part[2][256];

// ================= tf32 mma.sync helpers (family-portable PTX, sm_80+) =================
__device__ __forceinline__ uint32_t f2tf32(float f) {
    uint32_t u;
    asm("cvt.rna.tf32.f32 %0, %1;" : "=r"(u) : "f"(f));
    return u;
}
__device__ __forceinline__ void mma_tf32(float& c0, float& c1, float& c2, float& c3,
                                         uint32_t a0, uint32_t a1, uint32_t a2, uint32_t a3,
                                         uint32_t b0, uint32_t b1) {
    asm volatile(
        "mma.sync.aligned.m16n8k8.row.col.f32.tf32.tf32.f32 "
        "{%0,%1,%2,%3}, {%4,%5,%6,%7}, {%8,%9}, {%0,%1,%2,%3};"
        : "+f"(c0), "+f"(c1), "+f"(c2), "+f"(c3)
        : "r"(a0), "r"(a1), "r"(a2), "r"(a3), "r"(b0), "r"(b1));
}

// ---------------- GEMM1 (tf32 mma): retrieved = K @ W^T, fused loss partial ----------------
// C[m][n] = sum_k K[m][k]*W[n][k]. CTA 128x128, 8 warps (2m x 4n), warp tile 64x32.
#define G1_STRIDE 36   // 32 + 4 pad: frag LDS bank = (4*row+col)&31, conflict-free
__global__ __launch_bounds__(256, 2) void gemm1_mma_kernel(
    const float* __restrict__ K, const float* __restrict__ W,
    const float* __restrict__ V, float* __restrict__ out) {
    __shared__ float As[128 * G1_STRIDE];
    __shared__ float Bs[128 * G1_STRIDE];
    __shared__ float red[256];

    const int tid = threadIdx.x;
    const int warp = tid >> 5, lane = tid & 31;
    const int t4 = lane >> 2, tm4 = lane & 3;
    const int n0 = blockIdx.x * 128;
    const int m0 = blockIdx.y * 128;
    const int wm = (warp >> 2) * 64;
    const int wn = (warp & 3) * 32;

    float acc[4][4][4];
    #pragma unroll
    for (int i = 0; i < 4; ++i)
        #pragma unroll
        for (int j = 0; j < 4; ++j)
            #pragma unroll
            for (int r = 0; r < 4; ++r) acc[i][j][r] = 0.f;

    for (int kc = 0; kc < D; kc += 32) {
        __syncthreads();
        // stage A (K rows m0..m0+127, cols kc..kc+31) and B (W rows n0..)
        #pragma unroll
        for (int it = 0; it < 4; ++it) {
            int f = it * 256 + tid;
            int row = f >> 3, c4 = (f & 7) * 4;
            float4 av = *(const float4*)(K + (size_t)(m0 + row) * D + kc + c4);
            float4 bv = *(const float4*)(W + (size_t)(n0 + row) * D + kc + c4);
            uint32_t* ad = (uint32_t*)&As[row * G1_STRIDE + c4];
            uint32_t* bd = (uint32_t*)&Bs[row * G1_STRIDE + c4];
            ad[0] = f2tf32(av.x); ad[1] = f2tf32(av.y); ad[2] = f2tf32(av.z); ad[3] = f2tf32(av.w);
            bd[0] = f2tf32(bv.x); bd[1] = f2tf32(bv.y); bd[2] = f2tf32(bv.z); bd[3] = f2tf32(bv.w);
        }
        __syncthreads();
        #pragma unroll
        for (int kk = 0; kk < 4; ++kk) {
            const int k8 = kk * 8;
            uint32_t a[4][4], b[4][2];
            #pragma unroll
            for (int mt = 0; mt < 4; ++mt) {
                const uint32_t* ap = (const uint32_t*)&As[(wm + mt * 16 + t4) * G1_STRIDE + k8 + tm4];
                a[mt][0] = ap[0];
                a[mt][1] = ap[8 * G1_STRIDE];
                a[mt][2] = ap[4];
                a[mt][3] = ap[8 * G1_STRIDE + 4];
            }
            #pragma unroll
            for (int nt = 0; nt < 4; ++nt) {
                const uint32_t* bp = (const uint32_t*)&Bs[(wn + nt * 8 + t4) * G1_STRIDE + k8 + tm4];
                b[nt][0] = bp[0];
                b[nt][1] = bp[4];
            }
            #pragma unroll
            for (int mt = 0; mt < 4; ++mt)
                #pragma unroll
                for (int nt = 0; nt < 4; ++nt)
                    mma_tf32(acc[mt][nt][0], acc[mt][nt][1], acc[mt][nt][2], acc[mt][nt][3],
                             a[mt][0], a[mt][1], a[mt][2], a[mt][3], b[nt][0], b[nt][1]);
        }
    }

    // Epilogue: write retrieved (float2 pairs), accumulate loss partial
    float lsum = 0.f;
    #pragma unroll
    for (int mt = 0; mt < 4; ++mt) {
        #pragma unroll
        for (int nt = 0; nt < 4; ++nt) {
            int r  = m0 + wm + mt * 16 + t4;
            int cc = n0 + wn + nt * 8 + 2 * tm4;
            size_t e0 = (size_t)r * D + cc;
            size_t e1 = (size_t)(r + 8) * D + cc;
            float2 v0 = *(const float2*)(V + e0);
            float2 v1 = *(const float2*)(V + e1);
            float2 c0 = make_float2(acc[mt][nt][0], acc[mt][nt][1]);
            float2 c1 = make_float2(acc[mt][nt][2], acc[mt][nt][3]);
            *(float2*)(out + RET_OFF + e0) = c0;
            *(float2*)(out + RET_OFF + e1) = c1;
            float d0 = c0.x - v0.x, d1 = c0.y - v0.y;
            float d2 = c1.x - v1.x, d3 = c1.y - v1.y;
            lsum += d0 * d0 + d1 * d1 + d2 * d2 + d3 * d3;
        }
    }
    red[tid] = lsum;
    __syncthreads();
    for (int s = 128; s > 0; s >>= 1) {
        if (tid < s) red[tid] += red[tid + s];
        __syncthreads();
    }
    if (tid == 0) g_loss_part[blockIdx.y * 8 + blockIdx.x] = red[0];
}

// ---------------- GEMM2 (tf32 mma): grad_part[z][i][j] = sum_b diff[b][i]*K[b][j] ----------------
// A = diff^T (m=i, k=b), B = K (n=j, k=b). Staged as Db[32][i128], Kb[32][j128].
#define G2_STRIDE 136  // 128 + 8 pad: frag LDS bank = (8*row+col)&31, conflict-free
__global__ __launch_bounds__(256, 2) void gemm2_mma_kernel(
    const float* __restrict__ R, const float* __restrict__ V,
    const float* __restrict__ K) {
    __shared__ float Db[32 * G2_STRIDE];
    __shared__ float Kb[32 * G2_STRIDE];

    const int tid = threadIdx.x;
    const int warp = tid >> 5, lane = tid & 31;
    const int t4 = lane >> 2, tm4 = lane & 3;
    const int j0 = blockIdx.x * 128;
    const int i0 = blockIdx.y * 128;
    const int z  = blockIdx.z;
    const int wm = (warp >> 2) * 64;   // i within tile
    const int wn = (warp & 3) * 32;    // j within tile

    float acc[4][4][4];
    #pragma unroll
    for (int i = 0; i < 4; ++i)
        #pragma unroll
        for (int j = 0; j < 4; ++j)
            #pragma unroll
            for (int r = 0; r < 4; ++r) acc[i][j][r] = 0.f;

    const int b0 = z * (BROWS / 4);
    for (int bc = 0; bc < BROWS / 4; bc += 32) {
        __syncthreads();
        #pragma unroll
        for (int it = 0; it < 4; ++it) {
            int f = it * 256 + tid;
            int brow = f >> 5, c4 = (f & 31) * 4;
            size_t gbase = (size_t)(b0 + bc + brow) * D;
            float4 rv = *(const float4*)(R + gbase + i0 + c4);
            float4 vv = *(const float4*)(V + gbase + i0 + c4);
            float4 kv = *(const float4*)(K + gbase + j0 + c4);
            uint32_t* dd = (uint32_t*)&Db[brow * G2_STRIDE + c4];
            uint32_t* kd = (uint32_t*)&Kb[brow * G2_STRIDE + c4];
            dd[0] = f2tf32(rv.x - vv.x); dd[1] = f2tf32(rv.y - vv.y);
            dd[2] = f2tf32(rv.z - vv.z); dd[3] = f2tf32(rv.w - vv.w);
            kd[0] = f2tf32(kv.x); kd[1] = f2tf32(kv.y);
            kd[2] = f2tf32(kv.z); kd[3] = f2tf32(kv.w);
        }
        __syncthreads();
        #pragma unroll
        for (int kk = 0; kk < 4; ++kk) {
            const int k8 = kk * 8;
            uint32_t a[4][4], b[4][2];
            #pragma unroll
            for (int mt = 0; mt < 4; ++mt) {
                // A[m=i][k=b] = Db[b][i]; a0:(m=t4, k=tm4) a1:(m+8) a2:(k+4) a3:(m+8,k+4)
                const uint32_t* ap = (const uint32_t*)&Db[(k8 + tm4) * G2_STRIDE + wm + mt * 16 + t4];
                a[mt][0] = ap[0];
                a[mt][1] = ap[8];
                a[mt][2] = ap[4 * G2_STRIDE];
                a[mt][3] = ap[4 * G2_STRIDE + 8];
            }
            #pragma unroll
            for (int nt = 0; nt < 4; ++nt) {
                // B[k=b][n=j] = Kb[b][j]; b0:(k=tm4, n=t4) b1:(k+4)
                const uint32_t* bp = (const uint32_t*)&Kb[(k8 + tm4) * G2_STRIDE + wn + nt * 8 + t4];
                b[nt][0] = bp[0];
                b[nt][1] = bp[4 * G2_STRIDE];
            }
            #pragma unroll
            for (int mt = 0; mt < 4; ++mt)
                #pragma unroll
                for (int nt = 0; nt < 4; ++nt)
                    mma_tf32(acc[mt][nt][0], acc[mt][nt][1], acc[mt][nt][2], acc[mt][nt][3],
                             a[mt][0], a[mt][1], a[mt][2], a[mt][3], b[nt][0], b[nt][1]);
        }
    }

    float* gp = g_grad_part[z];
    #pragma unroll
    for (int mt = 0; mt < 4; ++mt) {
        #pragma unroll
        for (int nt = 0; nt < 4; ++nt) {
            int r  = i0 + wm + mt * 16 + t4;
            int cc = j0 + wn + nt * 8 + 2 * tm4;
            *(float2*)(gp + (size_t)r * D + cc)       = make_float2(acc[mt][nt][0], acc[mt][nt][1]);
            *(float2*)(gp + (size_t)(r + 8) * D + cc) = make_float2(acc[mt][nt][2], acc[mt][nt][3]);
        }
    }
}

// ---------------- k_agg: column sums of k ----------------
__global__ void colsum_kernel(const float* __restrict__ K) {
    int c  = blockIdx.x * 128 + threadIdx.x;
    int r0 = blockIdx.y * 256;
    float s = 0.f;
    #pragma unroll 4
    for (int r = r0; r < r0 + 256; ++r) s += K[r * D + c];
    g_kagg_part[blockIdx.y][c] = s;
}

__global__ void kagg_reduce_kernel() {
    int c = blockIdx.x * 256 + threadIdx.x;
    float s = 0.f;
    #pragma unroll
    for (int p = 0; p < 64; ++p) s += g_kagg_part[p][c];
    g_kagg[c] = s * (1.0f / (float)BROWS);
}

// ---------------- gates ----------------
__global__ void gates_kernel(const float* __restrict__ GW, const float* __restrict__ GB,
                             float* __restrict__ out) {
    __shared__ float red[128];
    int tid = threadIdx.x;
    for (int g = 0; g < 3; ++g) {
        float p = 0.f;
        for (int c = tid; c < D; c += 128) p += GW[g * D + c] * g_kagg[c];
        red[tid] = p;
        __syncthreads();
        for (int s = 64; s > 0; s >>= 1) {
            if (tid < s) red[tid] += red[tid + s];
            __syncthreads();
        }
        if (tid == 0) {
            float z  = red[0] + GB[g];
            float sg = 1.0f / (1.0f + expf(-z));
            g_scalars[g] = sg;
            out[GATES_OFF + g] = sg;
        }
        __syncthreads();
    }
}

__global__ void loss_reduce_kernel(float* __restrict__ out) {
    __shared__ float red[1024];
    int tid = threadIdx.x;
    red[tid] = g_loss_part[tid];
    __syncthreads();
    for (int s = 512; s > 0; s >>= 1) {
        if (tid < s) red[tid] += red[tid + s];
        __syncthreads();
    }
    if (tid == 0) out[LOSS_OFF] = red[0] / (float)(BROWS * D);
}

// ---------------- momentum / weight updates ----------------
__global__ void momentum_prep_kernel(const float* __restrict__ MOM) {
    __shared__ float red[256];
    int tid = threadIdx.x;
    int t = blockIdx.x * 256 + tid;
    float eta = g_scalars[1], theta = g_scalars[2];
    float lr_th = TTT_LR * theta;
    float nsum = 0.f;
    #pragma unroll
    for (int it = 0; it < 16; ++it) {
        int e = t + it * 65536;
        float g = (g_grad_part[0][e] + g_grad_part[1][e] +
                   g_grad_part[2][e] + g_grad_part[3][e]) * TWO_OVER_N;
        float gc = fminf(1.0f, fmaxf(-1.0f, g));
        float nm = eta * MOM[e] - lr_th * gc;
        g_nm_raw[e] = nm;
        nsum += nm * nm;
    }
    red[tid] = nsum;
    __syncthreads();
    for (int s = 128; s > 0; s >>= 1) {
        if (tid < s) red[tid] += red[tid + s];
        __syncthreads();
    }
    if (tid == 0) g_norm_part[0][blockIdx.x] = red[0];
}

__global__ void norm_scale_kernel(int which) {
    __shared__ float red[256];
    int tid = threadIdx.x;
    red[tid] = g_norm_part[which][tid];
    __syncthreads();
    for (int s = 128; s > 0; s >>= 1) {
        if (tid < s) red[tid] += red[tid + s];
        __syncthreads();
    }
    if (tid == 0) {
        float n = sqrtf(red[0]);
        g_scalars[4 + which] = (n > MEM_MAX_NORM) ? (MEM_MAX_NORM / (n + 1e-8f)) : 1.0f;
    }
}

__global__ void weight_prep_kernel(const float* __restrict__ MW, float* __restrict__ out) {
    __shared__ float red[256];
    int tid = threadIdx.x;
    int t = blockIdx.x * 256 + tid;
    float alpha = g_scalars[0];
    float sm = g_scalars[4];
    float one_m_a = 1.0f - alpha;
    float wsum = 0.f;
    #pragma unroll
    for (int it = 0; it < 16; ++it) {
        int e = t + it * 65536;
        float nm = g_nm_raw[e] * sm;
        out[NM_OFF + e] = nm;
        float w = one_m_a * MW[e] + nm;
        g_w_raw[e] = w;
        wsum += w * w;
    }
    red[tid] = wsum;
    __syncthreads();
    for (int s = 128; s > 0; s >>= 1) {
        if (tid < s) red[tid] += red[tid + s];
        __syncthreads();
    }
    if (tid == 0) g_norm_part[1][blockIdx.x] = red[0];
}

__global__ void final_w_kernel(float* __restrict__ out) {
    int t = blockIdx.x * 256 + threadIdx.x;
    float sw = g_scalars[5];
    #pragma unroll
    for (int it = 0; it < 16; ++it) {
        int e = t + it * 65536;
        out[W_OFF + e] = g_w_raw[e] * sw;
    }
}

// ---------------- launch ----------------
extern "C" void kernel_launch(void* const* d_in, const int* in_sizes, int n_in,
                              void* d_out, int out_size) {
    const float* k    = (const float*)d_in[0];
    const float* v    = (const float*)d_in[1];
    const float* memw = (const float*)d_in[2];
    const float* gw   = (const float*)d_in[3];
    const float* gb   = (const float*)d_in[4];
    const float* mom  = (const float*)d_in[5];
    float* out = (float*)d_out;

    // k_agg + gates
    colsum_kernel<<<dim3(8, 64), 128>>>(k);
    kagg_reduce_kernel<<<4, 256>>>();
    gates_kernel<<<1, 128>>>(gw, gb, out);

    // retrieved + loss (tf32 mma.sync)
    gemm1_mma_kernel<<<dim3(8, 128), 256>>>(k, memw, v, out);
    loss_reduce_kernel<<<1, 1024>>>(out);

    // grad (split-B x4, tf32 mma.sync)
    gemm2_mma_kernel<<<dim3(8, 8, 4), 256>>>(out + RET_OFF, v, k);

    // momentum / weight updates with norm clips
    momentum_prep_kernel<<<256, 256>>>(mom);
    norm_scale_kernel<<<1, 256>>>(0);
    weight_prep_kernel<<<256, 256>>>(memw, out);
    norm_scale_kernel<<<1, 256>>>(1);
    final_w_kernel<<<256, 256>>>(out);
}

// round 4
// speedup vs baseline: 3.8984x; 1.4444x over previous
#include <cuda_runtime.h>
#include <math.h>
#include <stdint.h>

// Problem constants
#define BROWS 16384
#define D     1024

// Output layout: retrieved (B*D) | loss (1) | new_weight (D*D) | new_momentum (D*D) | gates (3)
#define RET_OFF   0
#define LOSS_OFF  (BROWS * D)
#define W_OFF     (LOSS_OFF + 1)              // odd -> scalar stores only
#define NM_OFF    (W_OFF + D * D)             // odd -> scalar stores only
#define GATES_OFF (NM_OFF + D * D)

#define MEM_MAX_NORM 5.0f
#define TTT_LR 0.005f
#define TWO_OVER_N (2.0f / (float)(BROWS * D))

// ---------------- device scratch (static, no runtime allocation) ----------------
__device__ float g_kagg_part[64][D];
__device__ float g_kagg[D];
__device__ float g_scalars[8];        // 0:alpha 1:eta 2:theta 4:scale_m 5:scale_w
__device__ float g_loss_part[1024];
__device__ float g_grad_part[4][D * D];   // split-B partials for GEMM2 (16 MB)
__device__ float g_nm_raw[D * D];
__device__ float g_w_raw[D * D];
__device__ float g_norm_part[2][256];
__device__ float g_k_tf32[BROWS * D];     // rna-rounded K (64 MB)
__device__ float g_w_tf32[D * D];         // rna-rounded W (4 MB)
__device__ float g_diff[BROWS * D];       // rna-rounded (retrieved - V) (64 MB)

// ================= PTX helpers (family-portable, sm_80+) =================
__device__ __forceinline__ uint32_t f2tf32(float f) {
    uint32_t u;
    asm("cvt.rna.tf32.f32 %0, %1;" : "=r"(u) : "f"(f));
    return u;
}
__device__ __forceinline__ void mma_tf32(float& c0, float& c1, float& c2, float& c3,
                                         uint32_t a0, uint32_t a1, uint32_t a2, uint32_t a3,
                                         uint32_t b0, uint32_t b1) {
    asm volatile(
        "mma.sync.aligned.m16n8k8.row.col.f32.tf32.tf32.f32 "
        "{%0,%1,%2,%3}, {%4,%5,%6,%7}, {%8,%9}, {%0,%1,%2,%3};"
        : "+f"(c0), "+f"(c1), "+f"(c2), "+f"(c3)
        : "r"(a0), "r"(a1), "r"(a2), "r"(a3), "r"(b0), "r"(b1));
}
__device__ __forceinline__ uint32_t smem_u32(const void* p) {
    uint32_t a;
    asm("{ .reg .u64 t; cvta.to.shared.u64 t, %1; cvt.u32.u64 %0, t; }" : "=r"(a) : "l"(p));
    return a;
}
__device__ __forceinline__ void cp16(uint32_t dst, const void* src) {
    asm volatile("cp.async.cg.shared.global [%0], [%1], 16;" :: "r"(dst), "l"(src));
}
#define CP_COMMIT() asm volatile("cp.async.commit_group;" ::: "memory")
#define CP_WAIT2()  asm volatile("cp.async.wait_group 2;" ::: "memory")

// ---------------- prepass: colsum + rna(K) ----------------
__global__ void colsum_prep_kernel(const float* __restrict__ K) {
    int c  = blockIdx.x * 128 + threadIdx.x;
    int r0 = blockIdx.y * 256;
    float s = 0.f;
    #pragma unroll 4
    for (int r = r0; r < r0 + 256; ++r) {
        float kv = K[(size_t)r * D + c];
        s += kv;
        g_k_tf32[(size_t)r * D + c] = __uint_as_float(f2tf32(kv));
    }
    g_kagg_part[blockIdx.y][c] = s;
}

__global__ void prep_w_kernel(const float* __restrict__ W) {
    int e = blockIdx.x * 256 + threadIdx.x;
    g_w_tf32[e] = __uint_as_float(f2tf32(W[e]));
}

__global__ void kagg_reduce_kernel() {
    int c = blockIdx.x * 256 + threadIdx.x;
    float s = 0.f;
    #pragma unroll
    for (int p = 0; p < 64; ++p) s += g_kagg_part[p][c];
    g_kagg[c] = s * (1.0f / (float)BROWS);
}

__global__ void gates_kernel(const float* __restrict__ GW, const float* __restrict__ GB,
                             float* __restrict__ out) {
    __shared__ float red[128];
    int tid = threadIdx.x;
    for (int g = 0; g < 3; ++g) {
        float p = 0.f;
        for (int c = tid; c < D; c += 128) p += GW[g * D + c] * g_kagg[c];
        red[tid] = p;
        __syncthreads();
        for (int s = 64; s > 0; s >>= 1) {
            if (tid < s) red[tid] += red[tid + s];
            __syncthreads();
        }
        if (tid == 0) {
            float z  = red[0] + GB[g];
            float sg = 1.0f / (1.0f + expf(-z));
            g_scalars[g] = sg;
            out[GATES_OFF + g] = sg;
        }
        __syncthreads();
    }
}

// ---------------- GEMM1 (tf32 mma + cp.async 3-stage): retrieved = K @ W^T ----------------
// SMEM: As[3][128x32] then Bs[3][128x32], XOR swizzle chunk^(row&7).
#define G1_TILE 4096          // floats per stage per array
__global__ __launch_bounds__(256, 2) void gemm1_mma_kernel(
    const float* __restrict__ V, float* __restrict__ out) {
    extern __shared__ float sm[];
    __shared__ float wred[8];
    const uint32_t sb = smem_u32(sm);

    const int tid = threadIdx.x;
    const int warp = tid >> 5, lane = tid & 31;
    const int t4 = lane >> 2, tm4 = lane & 3;
    const int n0 = blockIdx.x * 128;
    const int m0 = blockIdx.y * 128;
    const int wm = (warp >> 2) * 64;
    const int wn = (warp & 3) * 32;

    float acc[4][4][4];
    #pragma unroll
    for (int i = 0; i < 4; ++i)
        #pragma unroll
        for (int j = 0; j < 4; ++j)
            #pragma unroll
            for (int r = 0; r < 4; ++r) acc[i][j][r] = 0.f;

    const int lrow = tid >> 3, lch = tid & 7;                 // staging: 4 iters of (row+=32)
    const int ldst = (lrow * 32 + ((lch ^ (lrow & 7)) << 2)) * 4;  // byte offset, +32row = +4096B
    const float* gA0 = g_k_tf32 + (size_t)(m0 + lrow) * D + lch * 4;
    const float* gB0 = g_w_tf32 + (size_t)(n0 + lrow) * D + lch * 4;

    // prologue: stages 0..2
    #pragma unroll
    for (int s = 0; s < 3; ++s) {
        uint32_t dA = sb + s * (G1_TILE * 4) + ldst;
        uint32_t dB = sb + (3 + s) * (G1_TILE * 4) + ldst;
        #pragma unroll
        for (int it = 0; it < 4; ++it) {
            cp16(dA + it * 4096, gA0 + (size_t)it * 32 * D + s * 32);
            cp16(dB + it * 4096, gB0 + (size_t)it * 32 * D + s * 32);
        }
        CP_COMMIT();
    }

    for (int c = 0; c < 32; ++c) {
        const int buf = c % 3;
        CP_WAIT2();
        __syncthreads();
        const float* As = sm + buf * G1_TILE;
        const float* Bs = sm + (3 + buf) * G1_TILE;
        #pragma unroll
        for (int kk = 0; kk < 4; ++kk) {
            const int ch0 = kk * 2;   // k8>>2
            uint32_t a[4][4], b[4][2];
            #pragma unroll
            for (int mt = 0; mt < 4; ++mt) {
                int r = wm + mt * 16 + t4;
                int i0a = r * 32 + (((ch0) ^ (r & 7)) << 2) + tm4;
                int i2a = r * 32 + (((ch0 + 1) ^ (r & 7)) << 2) + tm4;
                a[mt][0] = __float_as_uint(As[i0a]);
                a[mt][1] = __float_as_uint(As[i0a + 256]);
                a[mt][2] = __float_as_uint(As[i2a]);
                a[mt][3] = __float_as_uint(As[i2a + 256]);
            }
            #pragma unroll
            for (int nt = 0; nt < 4; ++nt) {
                int r = wn + nt * 8 + t4;
                int i0b = r * 32 + (((ch0) ^ (r & 7)) << 2) + tm4;
                int i2b = r * 32 + (((ch0 + 1) ^ (r & 7)) << 2) + tm4;
                b[nt][0] = __float_as_uint(Bs[i0b]);
                b[nt][1] = __float_as_uint(Bs[i2b]);
            }
            #pragma unroll
            for (int mt = 0; mt < 4; ++mt)
                #pragma unroll
                for (int nt = 0; nt < 4; ++nt)
                    mma_tf32(acc[mt][nt][0], acc[mt][nt][1], acc[mt][nt][2], acc[mt][nt][3],
                             a[mt][0], a[mt][1], a[mt][2], a[mt][3], b[nt][0], b[nt][1]);
        }
        __syncthreads();
        if (c + 3 < 32) {
            uint32_t dA = sb + buf * (G1_TILE * 4) + ldst;
            uint32_t dB = sb + (3 + buf) * (G1_TILE * 4) + ldst;
            #pragma unroll
            for (int it = 0; it < 4; ++it) {
                cp16(dA + it * 4096, gA0 + (size_t)it * 32 * D + (c + 3) * 32);
                cp16(dB + it * 4096, gB0 + (size_t)it * 32 * D + (c + 3) * 32);
            }
        }
        CP_COMMIT();
    }

    // Epilogue: write retrieved + diff (rna), accumulate loss partial
    float lsum = 0.f;
    #pragma unroll
    for (int mt = 0; mt < 4; ++mt) {
        #pragma unroll
        for (int nt = 0; nt < 4; ++nt) {
            int r  = m0 + wm + mt * 16 + t4;
            int cc = n0 + wn + nt * 8 + 2 * tm4;
            size_t e0 = (size_t)r * D + cc;
            size_t e1 = (size_t)(r + 8) * D + cc;
            float2 v0 = *(const float2*)(V + e0);
            float2 v1 = *(const float2*)(V + e1);
            float2 c0 = make_float2(acc[mt][nt][0], acc[mt][nt][1]);
            float2 c1 = make_float2(acc[mt][nt][2], acc[mt][nt][3]);
            *(float2*)(out + RET_OFF + e0) = c0;
            *(float2*)(out + RET_OFF + e1) = c1;
            float d0 = c0.x - v0.x, d1 = c0.y - v0.y;
            float d2 = c1.x - v1.x, d3 = c1.y - v1.y;
            *(float2*)(g_diff + e0) = make_float2(__uint_as_float(f2tf32(d0)), __uint_as_float(f2tf32(d1)));
            *(float2*)(g_diff + e1) = make_float2(__uint_as_float(f2tf32(d2)), __uint_as_float(f2tf32(d3)));
            lsum += d0 * d0 + d1 * d1 + d2 * d2 + d3 * d3;
        }
    }
    #pragma unroll
    for (int o = 16; o > 0; o >>= 1) lsum += __shfl_xor_sync(0xffffffffu, lsum, o);
    if (lane == 0) wred[warp] = lsum;
    __syncthreads();
    if (tid == 0) {
        float t = 0.f;
        #pragma unroll
        for (int w = 0; w < 8; ++w) t += wred[w];
        g_loss_part[blockIdx.y * 8 + blockIdx.x] = t;
    }
}

__global__ void loss_reduce_kernel(float* __restrict__ out) {
    __shared__ float red[1024];
    int tid = threadIdx.x;
    red[tid] = g_loss_part[tid];
    __syncthreads();
    for (int s = 512; s > 0; s >>= 1) {
        if (tid < s) red[tid] += red[tid + s];
        __syncthreads();
    }
    if (tid == 0) out[LOSS_OFF] = red[0] / (float)(BROWS * D);
}

// ---------------- GEMM2 (tf32 mma + cp.async 3-stage): grad_part ----------------
// SMEM: Db[3][32x128], Kb[3][32x128]. XOR swizzle chunk^((row&3)<<1).
#define G2_TILE 4096
__global__ __launch_bounds__(256, 2) void gemm2_mma_kernel() {
    extern __shared__ float sm[];
    const uint32_t sb = smem_u32(sm);

    const int tid = threadIdx.x;
    const int warp = tid >> 5, lane = tid & 31;
    const int t4 = lane >> 2, tm4 = lane & 3;
    const int j0 = blockIdx.x * 128;
    const int i0 = blockIdx.y * 128;
    const int z  = blockIdx.z;
    const int wm = (warp >> 2) * 64;   // i within tile
    const int wn = (warp & 3) * 32;    // j within tile

    float acc[4][4][4];
    #pragma unroll
    for (int i = 0; i < 4; ++i)
        #pragma unroll
        for (int j = 0; j < 4; ++j)
            #pragma unroll
            for (int r = 0; r < 4; ++r) acc[i][j][r] = 0.f;

    const int b0 = z * (BROWS / 4);
    const int lrow = tid >> 5, lch = tid & 31;                // staging: 4 iters of (row+=8)
    const int ldst = (lrow * 128 + ((lch ^ ((lrow & 3) << 1)) << 2)) * 4;  // +8row = +4096B
    const float* gD0 = g_diff   + (size_t)(b0 + lrow) * D + i0 + lch * 4;
    const float* gK0 = g_k_tf32 + (size_t)(b0 + lrow) * D + j0 + lch * 4;

    #pragma unroll
    for (int s = 0; s < 3; ++s) {
        uint32_t dA = sb + s * (G2_TILE * 4) + ldst;
        uint32_t dB = sb + (3 + s) * (G2_TILE * 4) + ldst;
        #pragma unroll
        for (int it = 0; it < 4; ++it) {
            cp16(dA + it * 4096, gD0 + ((size_t)it * 8 + (size_t)s * 32) * D);
            cp16(dB + it * 4096, gK0 + ((size_t)it * 8 + (size_t)s * 32) * D);
        }
        CP_COMMIT();
    }

    for (int c = 0; c < BROWS / 4 / 32; ++c) {
        const int buf = c % 3;
        CP_WAIT2();
        __syncthreads();
        const float* Db = sm + buf * G2_TILE;
        const float* Kb = sm + (3 + buf) * G2_TILE;
        #pragma unroll
        for (int kk = 0; kk < 4; ++kk) {
            const int rr = kk * 8 + tm4;     // b-row
            const int sw = (rr & 3) << 1;
            uint32_t a[4][4], b[4][2];
            #pragma unroll
            for (int mt = 0; mt < 4; ++mt) {
                int colA = wm + mt * 16 + t4;
                int ia0 = rr * 128 + ((((colA >> 2) ^ sw) << 2) | (colA & 3));
                int ia1 = rr * 128 + (((((colA + 8) >> 2) ^ sw) << 2) | (colA & 3));
                a[mt][0] = __float_as_uint(Db[ia0]);
                a[mt][1] = __float_as_uint(Db[ia1]);
                a[mt][2] = __float_as_uint(Db[ia0 + 512]);
                a[mt][3] = __float_as_uint(Db[ia1 + 512]);
            }
            #pragma unroll
            for (int nt = 0; nt < 4; ++nt) {
                int colB = wn + nt * 8 + t4;
                int ib0 = rr * 128 + ((((colB >> 2) ^ sw) << 2) | (colB & 3));
                b[nt][0] = __float_as_uint(Kb[ib0]);
                b[nt][1] = __float_as_uint(Kb[ib0 + 512]);
            }
            #pragma unroll
            for (int mt = 0; mt < 4; ++mt)
                #pragma unroll
                for (int nt = 0; nt < 4; ++nt)
                    mma_tf32(acc[mt][nt][0], acc[mt][nt][1], acc[mt][nt][2], acc[mt][nt][3],
                             a[mt][0], a[mt][1], a[mt][2], a[mt][3], b[nt][0], b[nt][1]);
        }
        __syncthreads();
        if (c + 3 < BROWS / 4 / 32) {
            uint32_t dA = sb + buf * (G2_TILE * 4) + ldst;
            uint32_t dB = sb + (3 + buf) * (G2_TILE * 4) + ldst;
            #pragma unroll
            for (int it = 0; it < 4; ++it) {
                cp16(dA + it * 4096, gD0 + ((size_t)it * 8 + (size_t)(c + 3) * 32) * D);
                cp16(dB + it * 4096, gK0 + ((size_t)it * 8 + (size_t)(c + 3) * 32) * D);
            }
        }
        CP_COMMIT();
    }

    float* gp = g_grad_part[z];
    #pragma unroll
    for (int mt = 0; mt < 4; ++mt) {
        #pragma unroll
        for (int nt = 0; nt < 4; ++nt) {
            int r  = i0 + wm + mt * 16 + t4;
            int cc = j0 + wn + nt * 8 + 2 * tm4;
            *(float2*)(gp + (size_t)r * D + cc)       = make_float2(acc[mt][nt][0], acc[mt][nt][1]);
            *(float2*)(gp + (size_t)(r + 8) * D + cc) = make_float2(acc[mt][nt][2], acc[mt][nt][3]);
        }
    }
}

// ---------------- momentum / weight updates ----------------
__global__ void momentum_prep_kernel(const float* __restrict__ MOM) {
    __shared__ float red[256];
    int tid = threadIdx.x;
    int t = blockIdx.x * 256 + tid;
    float eta = g_scalars[1], theta = g_scalars[2];
    float lr_th = TTT_LR * theta;
    float nsum = 0.f;
    #pragma unroll
    for (int it = 0; it < 16; ++it) {
        int e = t + it * 65536;
        float g = (g_grad_part[0][e] + g_grad_part[1][e] +
                   g_grad_part[2][e] + g_grad_part[3][e]) * TWO_OVER_N;
        float gc = fminf(1.0f, fmaxf(-1.0f, g));
        float nm = eta * MOM[e] - lr_th * gc;
        g_nm_raw[e] = nm;
        nsum += nm * nm;
    }
    red[tid] = nsum;
    __syncthreads();
    for (int s = 128; s > 0; s >>= 1) {
        if (tid < s) red[tid] += red[tid + s];
        __syncthreads();
    }
    if (tid == 0) g_norm_part[0][blockIdx.x] = red[0];
}

__global__ void norm_scale_kernel(int which) {
    __shared__ float red[256];
    int tid = threadIdx.x;
    red[tid] = g_norm_part[which][tid];
    __syncthreads();
    for (int s = 128; s > 0; s >>= 1) {
        if (tid < s) red[tid] += red[tid + s];
        __syncthreads();
    }
    if (tid == 0) {
        float n = sqrtf(red[0]);
        g_scalars[4 + which] = (n > MEM_MAX_NORM) ? (MEM_MAX_NORM / (n + 1e-8f)) : 1.0f;
    }
}

__global__ void weight_prep_kernel(const float* __restrict__ MW, float* __restrict__ out) {
    __shared__ float red[256];
    int tid = threadIdx.x;
    int t = blockIdx.x * 256 + tid;
    float alpha = g_scalars[0];
    float sm = g_scalars[4];
    float one_m_a = 1.0f - alpha;
    float wsum = 0.f;
    #pragma unroll
    for (int it = 0; it < 16; ++it) {
        int e = t + it * 65536;
        float nm = g_nm_raw[e] * sm;
        out[NM_OFF + e] = nm;
        float w = one_m_a * MW[e] + nm;
        g_w_raw[e] = w;
        wsum += w * w;
    }
    red[tid] = wsum;
    __syncthreads();
    for (int s = 128; s > 0; s >>= 1) {
        if (tid < s) red[tid] += red[tid + s];
        __syncthreads();
    }
    if (tid == 0) g_norm_part[1][blockIdx.x] = red[0];
}

__global__ void final_w_kernel(float* __restrict__ out) {
    int t = blockIdx.x * 256 + threadIdx.x;
    float sw = g_scalars[5];
    #pragma unroll
    for (int it = 0; it < 16; ++it) {
        int e = t + it * 65536;
        out[W_OFF + e] = g_w_raw[e] * sw;
    }
}

// ---------------- launch ----------------
extern "C" void kernel_launch(void* const* d_in, const int* in_sizes, int n_in,
                              void* d_out, int out_size) {
    const float* k    = (const float*)d_in[0];
    const float* v    = (const float*)d_in[1];
    const float* memw = (const float*)d_in[2];
    const float* gw   = (const float*)d_in[3];
    const float* gb   = (const float*)d_in[4];
    const float* mom  = (const float*)d_in[5];
    float* out = (float*)d_out;

    const int g1_smem = 6 * G1_TILE * 4;   // 98304
    const int g2_smem = 6 * G2_TILE * 4;   // 98304
    static int attr_done = 0;
    cudaFuncSetAttribute(gemm1_mma_kernel, cudaFuncAttributeMaxDynamicSharedMemorySize, g1_smem);
    cudaFuncSetAttribute(gemm2_mma_kernel, cudaFuncAttributeMaxDynamicSharedMemorySize, g2_smem);
    (void)attr_done;

    // prepass: rna(K) + colsums, rna(W), gates
    colsum_prep_kernel<<<dim3(8, 64), 128>>>(k);
    kagg_reduce_kernel<<<4, 256>>>();
    gates_kernel<<<1, 128>>>(gw, gb, out);
    prep_w_kernel<<<4096, 256>>>(memw);

    // retrieved + loss + diff (tf32 mma, cp.async pipeline)
    gemm1_mma_kernel<<<dim3(8, 128), 256, g1_smem>>>(v, out);
    loss_reduce_kernel<<<1, 1024>>>(out);

    // grad (split-B x4, tf32 mma, cp.async pipeline)
    gemm2_mma_kernel<<<dim3(8, 8, 4), 256, g2_smem>>>();

    // momentum / weight updates with norm clips
    momentum_prep_kernel<<<256, 256>>>(mom);
    norm_scale_kernel<<<1, 256>>>(0);
    weight_prep_kernel<<<256, 256>>>(memw, out);
    norm_scale_kernel<<<1, 256>>>(1);
    final_w_kernel<<<256, 256>>>(out);
}

// round 5
// speedup vs baseline: 4.6432x; 1.1910x over previous
#include <cuda_runtime.h>
#include <cuda_bf16.h>
#include <math.h>
#include <stdint.h>

// Problem constants
#define BROWS 16384
#define D     1024

// Output layout: retrieved (B*D) | loss (1) | new_weight (D*D) | new_momentum (D*D) | gates (3)
#define RET_OFF   0
#define LOSS_OFF  (BROWS * D)
#define W_OFF     (LOSS_OFF + 1)              // odd -> scalar stores only
#define NM_OFF    (W_OFF + D * D)             // odd -> scalar stores only
#define GATES_OFF (NM_OFF + D * D)

#define MEM_MAX_NORM 5.0f
#define TTT_LR 0.005f
#define TWO_OVER_N (2.0f / (float)(BROWS * D))

// ---------------- device scratch (static, no runtime allocation) ----------------
__device__ float g_kagg_part[128][D];
__device__ float g_scalars[8];        // 0:alpha 1:eta 2:theta 4:scale_m 5:scale_w
__device__ float g_loss_part[1024];
__device__ float g_grad_part[4][D * D];   // split-B partials for GEMM2 (16 MB)
__device__ float g_nm_raw[D * D];
__device__ float g_w_raw[D * D];
__device__ float g_norm_part[2][256];
__device__ int   g_ctr[2];
__device__ float g_k_tf32[BROWS * D];             // rna-rounded K (64 MB), [b][c]
__device__ float g_w_tf32[D * D];                 // rna-rounded W (4 MB)
__device__ __nv_bfloat16 g_kT[D * BROWS];         // bf16 K^T (32 MB), [c][b]
__device__ __nv_bfloat16 g_diffT[D * BROWS];      // bf16 (retrieved-V)^T (32 MB), [i][b]

// ================= PTX helpers (family-portable, sm_80+) =================
__device__ __forceinline__ uint32_t f2tf32(float f) {
    uint32_t u;
    asm("cvt.rna.tf32.f32 %0, %1;" : "=r"(u) : "f"(f));
    return u;
}
__device__ __forceinline__ uint32_t pack_bf16(float a, float b) {
    __nv_bfloat162 h = __floats2bfloat162_rn(a, b);   // .x = a (low), .y = b (high)
    return *(uint32_t*)&h;
}
__device__ __forceinline__ void mma_tf32(float& c0, float& c1, float& c2, float& c3,
                                         uint32_t a0, uint32_t a1, uint32_t a2, uint32_t a3,
                                         uint32_t b0, uint32_t b1) {
    asm volatile(
        "mma.sync.aligned.m16n8k8.row.col.f32.tf32.tf32.f32 "
        "{%0,%1,%2,%3}, {%4,%5,%6,%7}, {%8,%9}, {%0,%1,%2,%3};"
        : "+f"(c0), "+f"(c1), "+f"(c2), "+f"(c3)
        : "r"(a0), "r"(a1), "r"(a2), "r"(a3), "r"(b0), "r"(b1));
}
__device__ __forceinline__ void mma_bf16(float& c0, float& c1, float& c2, float& c3,
                                         uint32_t a0, uint32_t a1, uint32_t a2, uint32_t a3,
                                         uint32_t b0, uint32_t b1) {
    asm volatile(
        "mma.sync.aligned.m16n8k16.row.col.f32.bf16.bf16.f32 "
        "{%0,%1,%2,%3}, {%4,%5,%6,%7}, {%8,%9}, {%0,%1,%2,%3};"
        : "+f"(c0), "+f"(c1), "+f"(c2), "+f"(c3)
        : "r"(a0), "r"(a1), "r"(a2), "r"(a3), "r"(b0), "r"(b1));
}
__device__ __forceinline__ uint32_t smem_u32(const void* p) {
    uint32_t a;
    asm("{ .reg .u64 t; cvta.to.shared.u64 t, %1; cvt.u32.u64 %0, t; }" : "=r"(a) : "l"(p));
    return a;
}
__device__ __forceinline__ void cp16(uint32_t dst, const void* src) {
    asm volatile("cp.async.cg.shared.global [%0], [%1], 16;" :: "r"(dst), "l"(src));
}
#define CP_COMMIT() asm volatile("cp.async.commit_group;" ::: "memory")
#define CP_WAIT2()  asm volatile("cp.async.wait_group 2;" ::: "memory")

// ---------------- prep: rna(W) ----------------
__global__ void prep_w_kernel(const float* __restrict__ W) {
    int e = blockIdx.x * 256 + threadIdx.x;
    g_w_tf32[e] = __uint_as_float(f2tf32(W[e]));
}

// ---------------- colsum + rna(K) + bf16 K^T (smem-tiled transpose) ----------------
__global__ __launch_bounds__(256) void colsum_prep_kernel(const float* __restrict__ K) {
    __shared__ uint32_t st[128 * 64];
    __shared__ float red2[256];
    const int t  = threadIdx.x;
    const int cl = t & 127, rq = t >> 7;
    const int c  = blockIdx.x * 128 + cl;
    const int r0 = blockIdx.y * 128;

    float s = 0.f, prev = 0.f;
    #pragma unroll 4
    for (int i = 0; i < 64; ++i) {
        int r = r0 + rq * 64 + i;
        float kv = K[(size_t)r * D + c];
        s += kv;
        g_k_tf32[(size_t)r * D + c] = __uint_as_float(f2tf32(kv));
        if (i & 1) {
            int r2 = rq * 32 + (i >> 1);
            st[cl * 64 + (r2 ^ (cl & 31))] = pack_bf16(prev, kv);
        } else prev = kv;
    }
    red2[t] = s;
    __syncthreads();
    if (t < 128) g_kagg_part[blockIdx.y][blockIdx.x * 128 + t] = red2[t] + red2[t + 128];

    // write kT rows: thread (cl=row, rq=half) -> 32 u32 = 128B contiguous
    uint32_t* kTw = (uint32_t*)g_kT;
    size_t dstbase = ((size_t)(blockIdx.x * 128 + cl) * BROWS + r0) / 2 + rq * 32;
    #pragma unroll
    for (int q4 = 0; q4 < 32; q4 += 4) {
        uint4 vv;
        vv.x = st[cl * 64 + ((rq * 32 + q4 + 0) ^ (cl & 31))];
        vv.y = st[cl * 64 + ((rq * 32 + q4 + 1) ^ (cl & 31))];
        vv.z = st[cl * 64 + ((rq * 32 + q4 + 2) ^ (cl & 31))];
        vv.w = st[cl * 64 + ((rq * 32 + q4 + 3) ^ (cl & 31))];
        *(uint4*)(kTw + dstbase + q4) = vv;
    }
}

// ---------------- GEMM1 (tf32 mma + cp.async 3-stage): retrieved = K @ W^T ----------------
#define G1_TILE 4096          // floats per stage per array
__global__ __launch_bounds__(256, 2) void gemm1_mma_kernel(
    const float* __restrict__ V, float* __restrict__ out) {
    extern __shared__ float sm[];
    __shared__ float wred[8];
    const uint32_t sb = smem_u32(sm);

    const int tid = threadIdx.x;
    const int warp = tid >> 5, lane = tid & 31;
    const int t4 = lane >> 2, tm4 = lane & 3;
    const int n0 = blockIdx.x * 128;
    const int m0 = blockIdx.y * 128;
    const int wm = (warp >> 2) * 64;
    const int wn = (warp & 3) * 32;

    float acc[4][4][4];
    #pragma unroll
    for (int i = 0; i < 4; ++i)
        #pragma unroll
        for (int j = 0; j < 4; ++j)
            #pragma unroll
            for (int r = 0; r < 4; ++r) acc[i][j][r] = 0.f;

    const int lrow = tid >> 3, lch = tid & 7;
    const int ldst = (lrow * 32 + ((lch ^ (lrow & 7)) << 2)) * 4;
    const float* gA0 = g_k_tf32 + (size_t)(m0 + lrow) * D + lch * 4;
    const float* gB0 = g_w_tf32 + (size_t)(n0 + lrow) * D + lch * 4;

    #pragma unroll
    for (int s = 0; s < 3; ++s) {
        uint32_t dA = sb + s * (G1_TILE * 4) + ldst;
        uint32_t dB = sb + (3 + s) * (G1_TILE * 4) + ldst;
        #pragma unroll
        for (int it = 0; it < 4; ++it) {
            cp16(dA + it * 4096, gA0 + (size_t)it * 32 * D + s * 32);
            cp16(dB + it * 4096, gB0 + (size_t)it * 32 * D + s * 32);
        }
        CP_COMMIT();
    }

    for (int c = 0; c < 32; ++c) {
        const int buf = c % 3;
        CP_WAIT2();
        __syncthreads();
        const float* As = sm + buf * G1_TILE;
        const float* Bs = sm + (3 + buf) * G1_TILE;
        #pragma unroll
        for (int kk = 0; kk < 4; ++kk) {
            const int ch0 = kk * 2;
            uint32_t a[4][4], b[4][2];
            #pragma unroll
            for (int mt = 0; mt < 4; ++mt) {
                int r = wm + mt * 16 + t4;
                int i0a = r * 32 + (((ch0) ^ (r & 7)) << 2) + tm4;
                int i2a = r * 32 + (((ch0 + 1) ^ (r & 7)) << 2) + tm4;
                a[mt][0] = __float_as_uint(As[i0a]);
                a[mt][1] = __float_as_uint(As[i0a + 256]);
                a[mt][2] = __float_as_uint(As[i2a]);
                a[mt][3] = __float_as_uint(As[i2a + 256]);
            }
            #pragma unroll
            for (int nt = 0; nt < 4; ++nt) {
                int r = wn + nt * 8 + t4;
                int i0b = r * 32 + (((ch0) ^ (r & 7)) << 2) + tm4;
                int i2b = r * 32 + (((ch0 + 1) ^ (r & 7)) << 2) + tm4;
                b[nt][0] = __float_as_uint(Bs[i0b]);
                b[nt][1] = __float_as_uint(Bs[i2b]);
            }
            #pragma unroll
            for (int mt = 0; mt < 4; ++mt)
                #pragma unroll
                for (int nt = 0; nt < 4; ++nt)
                    mma_tf32(acc[mt][nt][0], acc[mt][nt][1], acc[mt][nt][2], acc[mt][nt][3],
                             a[mt][0], a[mt][1], a[mt][2], a[mt][3], b[nt][0], b[nt][1]);
        }
        __syncthreads();
        if (c + 3 < 32) {
            uint32_t dA = sb + buf * (G1_TILE * 4) + ldst;
            uint32_t dB = sb + (3 + buf) * (G1_TILE * 4) + ldst;
            #pragma unroll
            for (int it = 0; it < 4; ++it) {
                cp16(dA + it * 4096, gA0 + (size_t)it * 32 * D + (c + 3) * 32);
                cp16(dB + it * 4096, gB0 + (size_t)it * 32 * D + (c + 3) * 32);
            }
        }
        CP_COMMIT();
    }

    // Epilogue: retrieved (fp32) + diffT (bf16, transposed) + loss partial
    float lsum = 0.f;
    #pragma unroll
    for (int mt = 0; mt < 4; ++mt) {
        #pragma unroll
        for (int nt = 0; nt < 4; ++nt) {
            int r  = m0 + wm + mt * 16 + t4;
            int cc = n0 + wn + nt * 8 + 2 * tm4;
            size_t e0 = (size_t)r * D + cc;
            size_t e1 = (size_t)(r + 8) * D + cc;
            float2 v0 = *(const float2*)(V + e0);
            float2 v1 = *(const float2*)(V + e1);
            float2 c0 = make_float2(acc[mt][nt][0], acc[mt][nt][1]);
            float2 c1 = make_float2(acc[mt][nt][2], acc[mt][nt][3]);
            *(float2*)(out + RET_OFF + e0) = c0;
            *(float2*)(out + RET_OFF + e1) = c1;
            float d0 = c0.x - v0.x, d1 = c0.y - v0.y;
            float d2 = c1.x - v1.x, d3 = c1.y - v1.y;
            g_diffT[(size_t)cc * BROWS + r]           = __float2bfloat16_rn(d0);
            g_diffT[(size_t)(cc + 1) * BROWS + r]     = __float2bfloat16_rn(d1);
            g_diffT[(size_t)cc * BROWS + r + 8]       = __float2bfloat16_rn(d2);
            g_diffT[(size_t)(cc + 1) * BROWS + r + 8] = __float2bfloat16_rn(d3);
            lsum += d0 * d0 + d1 * d1 + d2 * d2 + d3 * d3;
        }
    }
    #pragma unroll
    for (int o = 16; o > 0; o >>= 1) lsum += __shfl_xor_sync(0xffffffffu, lsum, o);
    if (lane == 0) wred[warp] = lsum;
    __syncthreads();
    if (tid == 0) {
        float t = 0.f;
        #pragma unroll
        for (int w = 0; w < 8; ++w) t += wred[w];
        g_loss_part[blockIdx.y * 8 + blockIdx.x] = t;
    }
}

// ---------------- GEMM2 (bf16 mma m16n8k16 + cp.async 3-stage) ----------------
// grad[i][j] = sum_b diffT[i][b] * kT[j][b]; tiles staged [row][32 b] bf16 (64B/row).
#define G2_STAGE_WORDS 4096   // A(2048) + B(2048) u32 words per stage
__global__ __launch_bounds__(256, 2) void gemm2_bf16_kernel() {
    extern __shared__ uint32_t sm2[];
    const uint32_t sb = smem_u32(sm2);

    const int tid = threadIdx.x;
    const int warp = tid >> 5, lane = tid & 31;
    const int t4 = lane >> 2, tm4 = lane & 3;
    const int j0 = blockIdx.x * 128;
    const int i0 = blockIdx.y * 128;
    const int z  = blockIdx.z;
    const int b0z = z * (BROWS / 4);
    const int wm = (warp >> 2) * 64;   // i
    const int wn = (warp & 3) * 32;    // j

    float acc[4][4][4];
    #pragma unroll
    for (int i = 0; i < 4; ++i)
        #pragma unroll
        for (int j = 0; j < 4; ++j)
            #pragma unroll
            for (int r = 0; r < 4; ++r) acc[i][j][r] = 0.f;

    const int srow = tid >> 2, sg = tid & 3;   // staging: rows srow, srow+64

    // prologue
    #pragma unroll
    for (int s = 0; s < 3; ++s) {
        #pragma unroll
        for (int it = 0; it < 2; ++it) {
            int row = it * 64 + srow;
            int swz = (sg ^ ((row + (row >> 2)) & 3)) << 2;
            uint32_t dA = sb + (s * G2_STAGE_WORDS + row * 16 + swz) * 4;
            uint32_t dB = dA + 2048 * 4;
            cp16(dA, g_diffT + (size_t)(i0 + row) * BROWS + b0z + s * 32 + sg * 8);
            cp16(dB, g_kT    + (size_t)(j0 + row) * BROWS + b0z + s * 32 + sg * 8);
        }
        CP_COMMIT();
    }

    for (int c = 0; c < BROWS / 4 / 32; ++c) {
        const int buf = c % 3;
        CP_WAIT2();
        __syncthreads();
        const uint32_t* As = sm2 + buf * G2_STAGE_WORDS;
        const uint32_t* Bs = As + 2048;
        #pragma unroll
        for (int ks = 0; ks < 2; ++ks) {
            const int g0 = ks * 2;
            uint32_t a[4][4], b[4][2];
            #pragma unroll
            for (int mt = 0; mt < 4; ++mt) {
                int r0a = wm + mt * 16 + t4;
                int r1a = r0a + 8;
                int s0 = (r0a + (r0a >> 2)) & 3;
                int s1 = (r1a + (r1a >> 2)) & 3;
                a[mt][0] = As[r0a * 16 + (((g0)     ^ s0) << 2) + tm4];
                a[mt][1] = As[r1a * 16 + (((g0)     ^ s1) << 2) + tm4];
                a[mt][2] = As[r0a * 16 + (((g0 + 1) ^ s0) << 2) + tm4];
                a[mt][3] = As[r1a * 16 + (((g0 + 1) ^ s1) << 2) + tm4];
            }
            #pragma unroll
            for (int nt = 0; nt < 4; ++nt) {
                int rb = wn + nt * 8 + t4;
                int sbw = (rb + (rb >> 2)) & 3;
                b[nt][0] = Bs[rb * 16 + (((g0)     ^ sbw) << 2) + tm4];
                b[nt][1] = Bs[rb * 16 + (((g0 + 1) ^ sbw) << 2) + tm4];
            }
            #pragma unroll
            for (int mt = 0; mt < 4; ++mt)
                #pragma unroll
                for (int nt = 0; nt < 4; ++nt)
                    mma_bf16(acc[mt][nt][0], acc[mt][nt][1], acc[mt][nt][2], acc[mt][nt][3],
                             a[mt][0], a[mt][1], a[mt][2], a[mt][3], b[nt][0], b[nt][1]);
        }
        __syncthreads();
        if (c + 3 < BROWS / 4 / 32) {
            #pragma unroll
            for (int it = 0; it < 2; ++it) {
                int row = it * 64 + srow;
                int swz = (sg ^ ((row + (row >> 2)) & 3)) << 2;
                uint32_t dA = sb + (buf * G2_STAGE_WORDS + row * 16 + swz) * 4;
                uint32_t dB = dA + 2048 * 4;
                cp16(dA, g_diffT + (size_t)(i0 + row) * BROWS + b0z + (c + 3) * 32 + sg * 8);
                cp16(dB, g_kT    + (size_t)(j0 + row) * BROWS + b0z + (c + 3) * 32 + sg * 8);
            }
        }
        CP_COMMIT();
    }

    float* gp = g_grad_part[z];
    #pragma unroll
    for (int mt = 0; mt < 4; ++mt) {
        #pragma unroll
        for (int nt = 0; nt < 4; ++nt) {
            int r  = i0 + wm + mt * 16 + t4;
            int cc = j0 + wn + nt * 8 + 2 * tm4;
            *(float2*)(gp + (size_t)r * D + cc)       = make_float2(acc[mt][nt][0], acc[mt][nt][1]);
            *(float2*)(gp + (size_t)(r + 8) * D + cc) = make_float2(acc[mt][nt][2], acc[mt][nt][3]);
        }
    }
}

// ---------------- fused kagg + gates ----------------
__global__ void kagg_gates_kernel(const float* __restrict__ GW, const float* __restrict__ GB,
                                  float* __restrict__ out) {
    __shared__ float red[1024];
    __shared__ float kag[1024];
    int t = threadIdx.x;
    float s = 0.f;
    #pragma unroll 8
    for (int p = 0; p < 128; ++p) s += g_kagg_part[p][t];
    kag[t] = s * (1.0f / (float)BROWS);
    __syncthreads();
    for (int g = 0; g < 3; ++g) {
        red[t] = kag[t] * GW[g * D + t];
        __syncthreads();
        for (int st = 512; st > 0; st >>= 1) {
            if (t < st) red[t] += red[t + st];
            __syncthreads();
        }
        if (t == 0) {
            float z  = red[0] + GB[g];
            float sg = 1.0f / (1.0f + expf(-z));
            g_scalars[g] = sg;
            out[GATES_OFF + g] = sg;
        }
        __syncthreads();
    }
}

__global__ void loss_reduce_kernel(float* __restrict__ out) {
    __shared__ float red[1024];
    int tid = threadIdx.x;
    red[tid] = g_loss_part[tid];
    __syncthreads();
    for (int s = 512; s > 0; s >>= 1) {
        if (tid < s) red[tid] += red[tid + s];
        __syncthreads();
    }
    if (tid == 0) out[LOSS_OFF] = red[0] / (float)(BROWS * D);
}

// ---------------- momentum (+ fused norm via deterministic last-block) ----------------
__global__ void momentum_prep_kernel(const float* __restrict__ MOM) {
    __shared__ float red[256];
    __shared__ int amLast;
    int tid = threadIdx.x;
    int t = blockIdx.x * 256 + tid;
    float eta = g_scalars[1], theta = g_scalars[2];
    float lr_th = TTT_LR * theta;
    float nsum = 0.f;
    #pragma unroll
    for (int it = 0; it < 16; ++it) {
        int e = t + it * 65536;
        float g = (g_grad_part[0][e] + g_grad_part[1][e] +
                   g_grad_part[2][e] + g_grad_part[3][e]) * TWO_OVER_N;
        float gc = fminf(1.0f, fmaxf(-1.0f, g));
        float nm = eta * MOM[e] - lr_th * gc;
        g_nm_raw[e] = nm;
        nsum += nm * nm;
    }
    red[tid] = nsum;
    __syncthreads();
    for (int s = 128; s > 0; s >>= 1) {
        if (tid < s) red[tid] += red[tid + s];
        __syncthreads();
    }
    if (tid == 0) g_norm_part[0][blockIdx.x] = red[0];
    __threadfence();
    if (tid == 0) amLast = (atomicAdd(&g_ctr[0], 1) == 255);
    __syncthreads();
    if (amLast) {
        red[tid] = g_norm_part[0][tid];
        __syncthreads();
        for (int s = 128; s > 0; s >>= 1) {
            if (tid < s) red[tid] += red[tid + s];
            __syncthreads();
        }
        if (tid == 0) {
            float n = sqrtf(red[0]);
            g_scalars[4] = (n > MEM_MAX_NORM) ? (MEM_MAX_NORM / (n + 1e-8f)) : 1.0f;
            g_ctr[0] = 0;
        }
    }
}

// ---------------- weight (+ fused norm) ----------------
__global__ void weight_prep_kernel(const float* __restrict__ MW, float* __restrict__ out) {
    __shared__ float red[256];
    __shared__ int amLast;
    int tid = threadIdx.x;
    int t = blockIdx.x * 256 + tid;
    float alpha = g_scalars[0];
    float sm = g_scalars[4];
    float one_m_a = 1.0f - alpha;
    float wsum = 0.f;
    #pragma unroll
    for (int it = 0; it < 16; ++it) {
        int e = t + it * 65536;
        float nm = g_nm_raw[e] * sm;
        out[NM_OFF + e] = nm;
        float w = one_m_a * MW[e] + nm;
        g_w_raw[e] = w;
        wsum += w * w;
    }
    red[tid] = wsum;
    __syncthreads();
    for (int s = 128; s > 0; s >>= 1) {
        if (tid < s) red[tid] += red[tid + s];
        __syncthreads();
    }
    if (tid == 0) g_norm_part[1][blockIdx.x] = red[0];
    __threadfence();
    if (tid == 0) amLast = (atomicAdd(&g_ctr[1], 1) == 255);
    __syncthreads();
    if (amLast) {
        red[tid] = g_norm_part[1][tid];
        __syncthreads();
        for (int s = 128; s > 0; s >>= 1) {
            if (tid < s) red[tid] += red[tid + s];
            __syncthreads();
        }
        if (tid == 0) {
            float n = sqrtf(red[0]);
            g_scalars[5] = (n > MEM_MAX_NORM) ? (MEM_MAX_NORM / (n + 1e-8f)) : 1.0f;
            g_ctr[1] = 0;
        }
    }
}

__global__ void final_w_kernel(float* __restrict__ out) {
    int t = blockIdx.x * 256 + threadIdx.x;
    float sw = g_scalars[5];
    #pragma unroll
    for (int it = 0; it < 16; ++it) {
        int e = t + it * 65536;
        out[W_OFF + e] = g_w_raw[e] * sw;
    }
}

// ---------------- launch ----------------
extern "C" void kernel_launch(void* const* d_in, const int* in_sizes, int n_in,
                              void* d_out, int out_size) {
    const float* k    = (const float*)d_in[0];
    const float* v    = (const float*)d_in[1];
    const float* memw = (const float*)d_in[2];
    const float* gw   = (const float*)d_in[3];
    const float* gb   = (const float*)d_in[4];
    const float* mom  = (const float*)d_in[5];
    float* out = (float*)d_out;

    const int g1_smem = 6 * G1_TILE * 4;            // 98304
    const int g2_smem = 3 * G2_STAGE_WORDS * 4;     // 49152
    cudaFuncSetAttribute(gemm1_mma_kernel, cudaFuncAttributeMaxDynamicSharedMemorySize, g1_smem);
    cudaFuncSetAttribute(gemm2_bf16_kernel, cudaFuncAttributeMaxDynamicSharedMemorySize, g2_smem);

    prep_w_kernel<<<4096, 256>>>(memw);
    colsum_prep_kernel<<<dim3(8, 128), 256>>>(k);
    gemm1_mma_kernel<<<dim3(8, 128), 256, g1_smem>>>(v, out);
    gemm2_bf16_kernel<<<dim3(8, 8, 4), 256, g2_smem>>>();   // launch #4 -> ncu capture
    kagg_gates_kernel<<<1, 1024>>>(gw, gb, out);
    loss_reduce_kernel<<<1, 1024>>>(out);
    momentum_prep_kernel<<<256, 256>>>(mom);
    weight_prep_kernel<<<256, 256>>>(memw, out);
    final_w_kernel<<<256, 256>>>(out);
}

// round 6
// speedup vs baseline: 4.8271x; 1.0396x over previous
#include <cuda_runtime.h>
#include <cuda_bf16.h>
#include <math.h>
#include <stdint.h>

// Problem constants
#define BROWS 16384
#define D     1024

// Output layout: retrieved (B*D) | loss (1) | new_weight (D*D) | new_momentum (D*D) | gates (3)
#define RET_OFF   0
#define LOSS_OFF  (BROWS * D)
#define W_OFF     (LOSS_OFF + 1)              // odd -> scalar stores only
#define NM_OFF    (W_OFF + D * D)             // odd -> scalar stores only
#define GATES_OFF (NM_OFF + D * D)

#define MEM_MAX_NORM 5.0f
#define TTT_LR 0.005f
#define TWO_OVER_N (2.0f / (float)(BROWS * D))

// ---------------- device scratch (static, no runtime allocation) ----------------
__device__ float g_kagg_part[128][D];
__device__ float g_scalars[8];        // 0:alpha 1:eta 2:theta 4:scale_m 5:scale_w
__device__ float g_loss_part[1024];
__device__ float g_grad_part[4][D * D];   // split-B partials for GEMM2 (16 MB)
__device__ float g_nm_raw[D * D];
__device__ float g_w_raw[D * D];
__device__ float g_norm_part[2][256];
__device__ int   g_ctr[2];
__device__ float g_k_tf32[BROWS * D];             // rna-rounded K (64 MB), [b][c]
__device__ float g_w_tf32[D * D];                 // rna-rounded W (4 MB)
__device__ __nv_bfloat16 g_kT[D * BROWS];         // bf16 K^T (32 MB), [c][b]
__device__ __nv_bfloat16 g_diffT[D * BROWS];      // bf16 (retrieved-V)^T (32 MB), [i][b]

// ================= PTX helpers (family-portable, sm_80+) =================
__device__ __forceinline__ uint32_t f2tf32(float f) {
    uint32_t u;
    asm("cvt.rna.tf32.f32 %0, %1;" : "=r"(u) : "f"(f));
    return u;
}
__device__ __forceinline__ uint32_t pack_bf16(float a, float b) {
    __nv_bfloat162 h = __floats2bfloat162_rn(a, b);
    return *(uint32_t*)&h;
}
__device__ __forceinline__ void mma_tf32(float& c0, float& c1, float& c2, float& c3,
                                         uint32_t a0, uint32_t a1, uint32_t a2, uint32_t a3,
                                         uint32_t b0, uint32_t b1) {
    asm volatile(
        "mma.sync.aligned.m16n8k8.row.col.f32.tf32.tf32.f32 "
        "{%0,%1,%2,%3}, {%4,%5,%6,%7}, {%8,%9}, {%0,%1,%2,%3};"
        : "+f"(c0), "+f"(c1), "+f"(c2), "+f"(c3)
        : "r"(a0), "r"(a1), "r"(a2), "r"(a3), "r"(b0), "r"(b1));
}
__device__ __forceinline__ void mma_bf16(float& c0, float& c1, float& c2, float& c3,
                                         uint32_t a0, uint32_t a1, uint32_t a2, uint32_t a3,
                                         uint32_t b0, uint32_t b1) {
    asm volatile(
        "mma.sync.aligned.m16n8k16.row.col.f32.bf16.bf16.f32 "
        "{%0,%1,%2,%3}, {%4,%5,%6,%7}, {%8,%9}, {%0,%1,%2,%3};"
        : "+f"(c0), "+f"(c1), "+f"(c2), "+f"(c3)
        : "r"(a0), "r"(a1), "r"(a2), "r"(a3), "r"(b0), "r"(b1));
}
__device__ __forceinline__ void ldsm_x4(uint32_t& r0, uint32_t& r1, uint32_t& r2, uint32_t& r3,
                                        uint32_t addr) {
    asm volatile("ldmatrix.sync.aligned.m8n8.x4.shared.b16 {%0,%1,%2,%3}, [%4];"
                 : "=r"(r0), "=r"(r1), "=r"(r2), "=r"(r3) : "r"(addr));
}
__device__ __forceinline__ uint32_t smem_u32(const void* p) {
    uint32_t a;
    asm("{ .reg .u64 t; cvta.to.shared.u64 t, %1; cvt.u32.u64 %0, t; }" : "=r"(a) : "l"(p));
    return a;
}
__device__ __forceinline__ void cp16(uint32_t dst, const void* src) {
    asm volatile("cp.async.cg.shared.global [%0], [%1], 16;" :: "r"(dst), "l"(src));
}
#define CP_COMMIT() asm volatile("cp.async.commit_group;" ::: "memory")
#define CP_WAIT1()  asm volatile("cp.async.wait_group 1;" ::: "memory")

// ---------------- prep: rna(W) ----------------
__global__ void prep_w_kernel(const float* __restrict__ W) {
    int e = blockIdx.x * 256 + threadIdx.x;
    g_w_tf32[e] = __uint_as_float(f2tf32(W[e]));
}

// ---------------- colsum + rna(K) + bf16 K^T (smem-tiled transpose) ----------------
__global__ __launch_bounds__(256) void colsum_prep_kernel(const float* __restrict__ K) {
    __shared__ uint32_t st[128 * 64];
    __shared__ float red2[256];
    const int t  = threadIdx.x;
    const int cl = t & 127, rq = t >> 7;
    const int c  = blockIdx.x * 128 + cl;
    const int r0 = blockIdx.y * 128;

    float s = 0.f, prev = 0.f;
    #pragma unroll 4
    for (int i = 0; i < 64; ++i) {
        int r = r0 + rq * 64 + i;
        float kv = K[(size_t)r * D + c];
        s += kv;
        g_k_tf32[(size_t)r * D + c] = __uint_as_float(f2tf32(kv));
        if (i & 1) {
            int r2 = rq * 32 + (i >> 1);
            st[cl * 64 + (r2 ^ (cl & 31))] = pack_bf16(prev, kv);
        } else prev = kv;
    }
    red2[t] = s;
    __syncthreads();
    if (t < 128) g_kagg_part[blockIdx.y][blockIdx.x * 128 + t] = red2[t] + red2[t + 128];

    uint32_t* kTw = (uint32_t*)g_kT;
    size_t dstbase = ((size_t)(blockIdx.x * 128 + cl) * BROWS + r0) / 2 + rq * 32;
    #pragma unroll
    for (int q4 = 0; q4 < 32; q4 += 4) {
        uint4 vv;
        vv.x = st[cl * 64 + ((rq * 32 + q4 + 0) ^ (cl & 31))];
        vv.y = st[cl * 64 + ((rq * 32 + q4 + 1) ^ (cl & 31))];
        vv.z = st[cl * 64 + ((rq * 32 + q4 + 2) ^ (cl & 31))];
        vv.w = st[cl * 64 + ((rq * 32 + q4 + 3) ^ (cl & 31))];
        *(uint4*)(kTw + dstbase + q4) = vv;
    }
}

// ---------------- GEMM1 (tf32 mma + cp.async, single-barrier 3-stage) ----------------
#define G1_TILE 4096          // floats per stage per array
__global__ __launch_bounds__(256, 2) void gemm1_mma_kernel(
    const float* __restrict__ V, float* __restrict__ out) {
    extern __shared__ float sm[];
    __shared__ float wred[8];
    const uint32_t sb = smem_u32(sm);

    const int tid = threadIdx.x;
    const int warp = tid >> 5, lane = tid & 31;
    const int t4 = lane >> 2, tm4 = lane & 3;
    const int n0 = blockIdx.x * 128;
    const int m0 = blockIdx.y * 128;
    const int wm = (warp >> 2) * 64;
    const int wn = (warp & 3) * 32;

    float acc[4][4][4];
    #pragma unroll
    for (int i = 0; i < 4; ++i)
        #pragma unroll
        for (int j = 0; j < 4; ++j)
            #pragma unroll
            for (int r = 0; r < 4; ++r) acc[i][j][r] = 0.f;

    const int lrow = tid >> 3, lch = tid & 7;
    const int ldst = (lrow * 32 + ((lch ^ (lrow & 7)) << 2)) * 4;
    const float* gA0 = g_k_tf32 + (size_t)(m0 + lrow) * D + lch * 4;
    const float* gB0 = g_w_tf32 + (size_t)(n0 + lrow) * D + lch * 4;

    // prologue: stages 0,1
    #pragma unroll
    for (int s = 0; s < 2; ++s) {
        uint32_t dA = sb + s * (G1_TILE * 4) + ldst;
        uint32_t dB = sb + (3 + s) * (G1_TILE * 4) + ldst;
        #pragma unroll
        for (int it = 0; it < 4; ++it) {
            cp16(dA + it * 4096, gA0 + (size_t)it * 32 * D + s * 32);
            cp16(dB + it * 4096, gB0 + (size_t)it * 32 * D + s * 32);
        }
        CP_COMMIT();
    }

    for (int c = 0; c < 32; ++c) {
        const int buf = c % 3;
        CP_WAIT1();
        __syncthreads();
        if (c + 2 < 32) {
            const int nb = (c + 2) % 3;
            uint32_t dA = sb + nb * (G1_TILE * 4) + ldst;
            uint32_t dB = sb + (3 + nb) * (G1_TILE * 4) + ldst;
            #pragma unroll
            for (int it = 0; it < 4; ++it) {
                cp16(dA + it * 4096, gA0 + (size_t)it * 32 * D + (c + 2) * 32);
                cp16(dB + it * 4096, gB0 + (size_t)it * 32 * D + (c + 2) * 32);
            }
        }
        CP_COMMIT();

        const float* As = sm + buf * G1_TILE;
        const float* Bs = sm + (3 + buf) * G1_TILE;
        #pragma unroll
        for (int kk = 0; kk < 4; ++kk) {
            const int ch0 = kk * 2;
            uint32_t a[4][4], b[4][2];
            #pragma unroll
            for (int mt = 0; mt < 4; ++mt) {
                int r = wm + mt * 16 + t4;
                int i0a = r * 32 + (((ch0) ^ (r & 7)) << 2) + tm4;
                int i2a = r * 32 + (((ch0 + 1) ^ (r & 7)) << 2) + tm4;
                a[mt][0] = __float_as_uint(As[i0a]);
                a[mt][1] = __float_as_uint(As[i0a + 256]);
                a[mt][2] = __float_as_uint(As[i2a]);
                a[mt][3] = __float_as_uint(As[i2a + 256]);
            }
            #pragma unroll
            for (int nt = 0; nt < 4; ++nt) {
                int r = wn + nt * 8 + t4;
                int i0b = r * 32 + (((ch0) ^ (r & 7)) << 2) + tm4;
                int i2b = r * 32 + (((ch0 + 1) ^ (r & 7)) << 2) + tm4;
                b[nt][0] = __float_as_uint(Bs[i0b]);
                b[nt][1] = __float_as_uint(Bs[i2b]);
            }
            #pragma unroll
            for (int mt = 0; mt < 4; ++mt)
                #pragma unroll
                for (int nt = 0; nt < 4; ++nt)
                    mma_tf32(acc[mt][nt][0], acc[mt][nt][1], acc[mt][nt][2], acc[mt][nt][3],
                             a[mt][0], a[mt][1], a[mt][2], a[mt][3], b[nt][0], b[nt][1]);
        }
    }

    // Epilogue: retrieved (fp32) + diffT (bf16, transposed) + loss partial
    float lsum = 0.f;
    #pragma unroll
    for (int mt = 0; mt < 4; ++mt) {
        #pragma unroll
        for (int nt = 0; nt < 4; ++nt) {
            int r  = m0 + wm + mt * 16 + t4;
            int cc = n0 + wn + nt * 8 + 2 * tm4;
            size_t e0 = (size_t)r * D + cc;
            size_t e1 = (size_t)(r + 8) * D + cc;
            float2 v0 = *(const float2*)(V + e0);
            float2 v1 = *(const float2*)(V + e1);
            float2 c0 = make_float2(acc[mt][nt][0], acc[mt][nt][1]);
            float2 c1 = make_float2(acc[mt][nt][2], acc[mt][nt][3]);
            *(float2*)(out + RET_OFF + e0) = c0;
            *(float2*)(out + RET_OFF + e1) = c1;
            float d0 = c0.x - v0.x, d1 = c0.y - v0.y;
            float d2 = c1.x - v1.x, d3 = c1.y - v1.y;
            g_diffT[(size_t)cc * BROWS + r]           = __float2bfloat16_rn(d0);
            g_diffT[(size_t)(cc + 1) * BROWS + r]     = __float2bfloat16_rn(d1);
            g_diffT[(size_t)cc * BROWS + r + 8]       = __float2bfloat16_rn(d2);
            g_diffT[(size_t)(cc + 1) * BROWS + r + 8] = __float2bfloat16_rn(d3);
            lsum += d0 * d0 + d1 * d1 + d2 * d2 + d3 * d3;
        }
    }
    #pragma unroll
    for (int o = 16; o > 0; o >>= 1) lsum += __shfl_xor_sync(0xffffffffu, lsum, o);
    if (lane == 0) wred[warp] = lsum;
    __syncthreads();
    if (tid == 0) {
        float t = 0.f;
        #pragma unroll
        for (int w = 0; w < 8; ++w) t += wred[w];
        g_loss_part[blockIdx.y * 8 + blockIdx.x] = t;
    }
}

// ---------------- GEMM2 (bf16 mma + ldmatrix + cp.async, single-barrier 3-stage) ----------------
#define G2_STAGE_WORDS 4096   // A(2048) + B(2048) u32 words per stage
__global__ __launch_bounds__(256, 2) void gemm2_bf16_kernel() {
    extern __shared__ uint32_t sm2[];
    const uint32_t sb = smem_u32(sm2);

    const int tid = threadIdx.x;
    const int warp = tid >> 5, lane = tid & 31;
    const int t4 = lane >> 2, tm4 = lane & 3;
    const int j0 = blockIdx.x * 128;
    const int i0 = blockIdx.y * 128;
    const int z  = blockIdx.z;
    const int b0z = z * (BROWS / 4);
    const int wm = (warp >> 2) * 64;   // i
    const int wn = (warp & 3) * 32;    // j

    float acc[4][4][4];
    #pragma unroll
    for (int i = 0; i < 4; ++i)
        #pragma unroll
        for (int j = 0; j < 4; ++j)
            #pragma unroll
            for (int r = 0; r < 4; ++r) acc[i][j][r] = 0.f;

    // ldmatrix per-lane row/group selectors
    const int laneRowA = (lane & 7) | (lane & 8);          // 0..15
    const int selA = lane >> 4;                             // 0/1 (k-group offset)
    const int laneRowB = (lane & 7) | ((lane & 16) >> 1);  // 0..15
    const int selB = (lane >> 3) & 1;

    uint32_t offA[4], swA[4];
    #pragma unroll
    for (int mt = 0; mt < 4; ++mt) {
        int row = wm + mt * 16 + laneRowA;
        offA[mt] = row * 64;                // bytes (16 u32 per row)
        swA[mt]  = (row + (row >> 2)) & 3;
    }
    uint32_t offB[2], swB[2];
    #pragma unroll
    for (int np = 0; np < 2; ++np) {
        int row = wn + np * 16 + laneRowB;
        offB[np] = row * 64;
        swB[np]  = (row + (row >> 2)) & 3;
    }

    const int srow = tid >> 2, sg = tid & 3;   // staging: rows srow, srow+64

    // prologue: stages 0,1
    #pragma unroll
    for (int s = 0; s < 2; ++s) {
        #pragma unroll
        for (int it = 0; it < 2; ++it) {
            int row = it * 64 + srow;
            int swz = (sg ^ ((row + (row >> 2)) & 3)) << 2;
            uint32_t dA = sb + (s * G2_STAGE_WORDS + row * 16 + swz) * 4;
            uint32_t dB = dA + 2048 * 4;
            cp16(dA, g_diffT + (size_t)(i0 + row) * BROWS + b0z + s * 32 + sg * 8);
            cp16(dB, g_kT    + (size_t)(j0 + row) * BROWS + b0z + s * 32 + sg * 8);
        }
        CP_COMMIT();
    }

    const int NCH = BROWS / 4 / 32;   // 128 chunks
    for (int c = 0; c < NCH; ++c) {
        const int buf = c % 3;
        CP_WAIT1();
        __syncthreads();
        if (c + 2 < NCH) {
            const int nb = (c + 2) % 3;
            #pragma unroll
            for (int it = 0; it < 2; ++it) {
                int row = it * 64 + srow;
                int swz = (sg ^ ((row + (row >> 2)) & 3)) << 2;
                uint32_t dA = sb + (nb * G2_STAGE_WORDS + row * 16 + swz) * 4;
                uint32_t dB = dA + 2048 * 4;
                cp16(dA, g_diffT + (size_t)(i0 + row) * BROWS + b0z + (c + 2) * 32 + sg * 8);
                cp16(dB, g_kT    + (size_t)(j0 + row) * BROWS + b0z + (c + 2) * 32 + sg * 8);
            }
        }
        CP_COMMIT();

        const uint32_t abase = sb + buf * (G2_STAGE_WORDS * 4);
        const uint32_t bbase = abase + 2048 * 4;
        #pragma unroll
        for (int ks = 0; ks < 2; ++ks) {
            const int g0 = ks * 2;
            uint32_t a[4][4], b[2][4];
            #pragma unroll
            for (int mt = 0; mt < 4; ++mt)
                ldsm_x4(a[mt][0], a[mt][1], a[mt][2], a[mt][3],
                        abase + offA[mt] + ((((uint32_t)(g0 + selA)) ^ swA[mt]) << 4));
            #pragma unroll
            for (int np = 0; np < 2; ++np)
                ldsm_x4(b[np][0], b[np][1], b[np][2], b[np][3],
                        bbase + offB[np] + ((((uint32_t)(g0 + selB)) ^ swB[np]) << 4));
            #pragma unroll
            for (int mt = 0; mt < 4; ++mt)
                #pragma unroll
                for (int nt = 0; nt < 4; ++nt) {
                    const int np = nt >> 1, lo = (nt & 1) * 2;
                    mma_bf16(acc[mt][nt][0], acc[mt][nt][1], acc[mt][nt][2], acc[mt][nt][3],
                             a[mt][0], a[mt][1], a[mt][2], a[mt][3], b[np][lo], b[np][lo + 1]);
                }
        }
    }

    float* gp = g_grad_part[z];
    #pragma unroll
    for (int mt = 0; mt < 4; ++mt) {
        #pragma unroll
        for (int nt = 0; nt < 4; ++nt) {
            int r  = i0 + wm + mt * 16 + t4;
            int cc = j0 + wn + nt * 8 + 2 * tm4;
            *(float2*)(gp + (size_t)r * D + cc)       = make_float2(acc[mt][nt][0], acc[mt][nt][1]);
            *(float2*)(gp + (size_t)(r + 8) * D + cc) = make_float2(acc[mt][nt][2], acc[mt][nt][3]);
        }
    }
}

// ---------------- fused kagg + gates ----------------
__global__ void kagg_gates_kernel(const float* __restrict__ GW, const float* __restrict__ GB,
                                  float* __restrict__ out) {
    __shared__ float red[1024];
    __shared__ float kag[1024];
    int t = threadIdx.x;
    float s = 0.f;
    #pragma unroll 8
    for (int p = 0; p < 128; ++p) s += g_kagg_part[p][t];
    kag[t] = s * (1.0f / (float)BROWS);
    __syncthreads();
    for (int g = 0; g < 3; ++g) {
        red[t] = kag[t] * GW[g * D + t];
        __syncthreads();
        for (int st = 512; st > 0; st >>= 1) {
            if (t < st) red[t] += red[t + st];
            __syncthreads();
        }
        if (t == 0) {
            float z  = red[0] + GB[g];
            float sg = 1.0f / (1.0f + expf(-z));
            g_scalars[g] = sg;
            out[GATES_OFF + g] = sg;
        }
        __syncthreads();
    }
}

__global__ void loss_reduce_kernel(float* __restrict__ out) {
    __shared__ float red[1024];
    int tid = threadIdx.x;
    red[tid] = g_loss_part[tid];
    __syncthreads();
    for (int s = 512; s > 0; s >>= 1) {
        if (tid < s) red[tid] += red[tid + s];
        __syncthreads();
    }
    if (tid == 0) out[LOSS_OFF] = red[0] / (float)(BROWS * D);
}

// ---------------- momentum (+ fused norm via deterministic last-block) ----------------
__global__ void momentum_prep_kernel(const float* __restrict__ MOM) {
    __shared__ float red[256];
    __shared__ int amLast;
    int tid = threadIdx.x;
    int t = blockIdx.x * 256 + tid;
    float eta = g_scalars[1], theta = g_scalars[2];
    float lr_th = TTT_LR * theta;
    float nsum = 0.f;
    #pragma unroll
    for (int it = 0; it < 16; ++it) {
        int e = t + it * 65536;
        float g = (g_grad_part[0][e] + g_grad_part[1][e] +
                   g_grad_part[2][e] + g_grad_part[3][e]) * TWO_OVER_N;
        float gc = fminf(1.0f, fmaxf(-1.0f, g));
        float nm = eta * MOM[e] - lr_th * gc;
        g_nm_raw[e] = nm;
        nsum += nm * nm;
    }
    red[tid] = nsum;
    __syncthreads();
    for (int s = 128; s > 0; s >>= 1) {
        if (tid < s) red[tid] += red[tid + s];
        __syncthreads();
    }
    if (tid == 0) g_norm_part[0][blockIdx.x] = red[0];
    __threadfence();
    if (tid == 0) amLast = (atomicAdd(&g_ctr[0], 1) == 255);
    __syncthreads();
    if (amLast) {
        red[tid] = g_norm_part[0][tid];
        __syncthreads();
        for (int s = 128; s > 0; s >>= 1) {
            if (tid < s) red[tid] += red[tid + s];
            __syncthreads();
        }
        if (tid == 0) {
            float n = sqrtf(red[0]);
            g_scalars[4] = (n > MEM_MAX_NORM) ? (MEM_MAX_NORM / (n + 1e-8f)) : 1.0f;
            g_ctr[0] = 0;
        }
    }
}

// ---------------- weight (+ fused norm) ----------------
__global__ void weight_prep_kernel(const float* __restrict__ MW, float* __restrict__ out) {
    __shared__ float red[256];
    __shared__ int amLast;
    int tid = threadIdx.x;
    int t = blockIdx.x * 256 + tid;
    float alpha = g_scalars[0];
    float sm = g_scalars[4];
    float one_m_a = 1.0f - alpha;
    float wsum = 0.f;
    #pragma unroll
    for (int it = 0; it < 16; ++it) {
        int e = t + it * 65536;
        float nm = g_nm_raw[e] * sm;
        out[NM_OFF + e] = nm;
        float w = one_m_a * MW[e] + nm;
        g_w_raw[e] = w;
        wsum += w * w;
    }
    red[tid] = wsum;
    __syncthreads();
    for (int s = 128; s > 0; s >>= 1) {
        if (tid < s) red[tid] += red[tid + s];
        __syncthreads();
    }
    if (tid == 0) g_norm_part[1][blockIdx.x] = red[0];
    __threadfence();
    if (tid == 0) amLast = (atomicAdd(&g_ctr[1], 1) == 255);
    __syncthreads();
    if (amLast) {
        red[tid] = g_norm_part[1][tid];
        __syncthreads();
        for (int s = 128; s > 0; s >>= 1) {
            if (tid < s) red[tid] += red[tid + s];
            __syncthreads();
        }
        if (tid == 0) {
            float n = sqrtf(red[0]);
            g_scalars[5] = (n > MEM_MAX_NORM) ? (MEM_MAX_NORM / (n + 1e-8f)) : 1.0f;
            g_ctr[1] = 0;
        }
    }
}

__global__ void final_w_kernel(float* __restrict__ out) {
    int t = blockIdx.x * 256 + threadIdx.x;
    float sw = g_scalars[5];
    #pragma unroll
    for (int it = 0; it < 16; ++it) {
        int e = t + it * 65536;
        out[W_OFF + e] = g_w_raw[e] * sw;
    }
}

// ---------------- launch ----------------
extern "C" void kernel_launch(void* const* d_in, const int* in_sizes, int n_in,
                              void* d_out, int out_size) {
    const float* k    = (const float*)d_in[0];
    const float* v    = (const float*)d_in[1];
    const float* memw = (const float*)d_in[2];
    const float* gw   = (const float*)d_in[3];
    const float* gb   = (const float*)d_in[4];
    const float* mom  = (const float*)d_in[5];
    float* out = (float*)d_out;

    const int g1_smem = 6 * G1_TILE * 4;            // 98304
    const int g2_smem = 3 * G2_STAGE_WORDS * 4;     // 49152
    cudaFuncSetAttribute(gemm1_mma_kernel, cudaFuncAttributeMaxDynamicSharedMemorySize, g1_smem);
    cudaFuncSetAttribute(gemm2_bf16_kernel, cudaFuncAttributeMaxDynamicSharedMemorySize, g2_smem);

    prep_w_kernel<<<4096, 256>>>(memw);
    colsum_prep_kernel<<<dim3(8, 128), 256>>>(k);
    gemm1_mma_kernel<<<dim3(8, 128), 256, g1_smem>>>(v, out);
    gemm2_bf16_kernel<<<dim3(8, 8, 4), 256, g2_smem>>>();   // launch #4 -> ncu capture
    kagg_gates_kernel<<<1, 1024>>>(gw, gb, out);
    loss_reduce_kernel<<<1, 1024>>>(out);
    momentum_prep_kernel<<<256, 256>>>(mom);
    weight_prep_kernel<<<256, 256>>>(memw, out);
    final_w_kernel<<<256, 256>>>(out);
}

// round 7
// speedup vs baseline: 6.5423x; 1.3553x over previous
#include <cuda_runtime.h>
#include <cuda_fp16.h>
#include <math.h>
#include <stdint.h>

// Problem constants
#define BROWS 16384
#define D     1024

// Output layout: retrieved (B*D) | loss (1) | new_weight (D*D) | new_momentum (D*D) | gates (3)
#define RET_OFF   0
#define LOSS_OFF  (BROWS * D)
#define W_OFF     (LOSS_OFF + 1)              // odd -> scalar stores only
#define NM_OFF    (W_OFF + D * D)             // odd -> scalar stores only
#define GATES_OFF (NM_OFF + D * D)

#define MEM_MAX_NORM 5.0f
#define TTT_LR 0.005f
#define TWO_OVER_N (2.0f / (float)(BROWS * D))

// ---------------- device scratch (static, no runtime allocation) ----------------
__device__ float g_kagg_part[128][D];
__device__ float g_scalars[8];        // 0:alpha 1:eta 2:theta 4:scale_m 5:scale_w
__device__ float g_loss_part[1024];
__device__ float g_grad_part[4][D * D];   // split-B partials for GEMM2 (16 MB)
__device__ float g_nm_raw[D * D];
__device__ float g_w_raw[D * D];
__device__ float g_norm_part[2][256];
__device__ int   g_ctr[2];
__device__ __half g_k_h[BROWS * D];        // fp16 K, row-major [b][c] (32 MB)
__device__ __half g_w_h[D * D];            // fp16 W, row-major [n][k] (2 MB)
__device__ __half g_kT_h[D * BROWS];       // fp16 K^T [c][b] (32 MB)
__device__ __half g_diffT_h[D * BROWS];    // fp16 (retrieved-V)^T [i][b] (32 MB)

// ================= PTX helpers (family-portable, sm_80+) =================
__device__ __forceinline__ uint32_t pack_half(float a, float b) {
    __half2 h = __floats2half2_rn(a, b);
    return *(uint32_t*)&h;
}
__device__ __forceinline__ void mma_f16(float& c0, float& c1, float& c2, float& c3,
                                        uint32_t a0, uint32_t a1, uint32_t a2, uint32_t a3,
                                        uint32_t b0, uint32_t b1) {
    asm volatile(
        "mma.sync.aligned.m16n8k16.row.col.f32.f16.f16.f32 "
        "{%0,%1,%2,%3}, {%4,%5,%6,%7}, {%8,%9}, {%0,%1,%2,%3};"
        : "+f"(c0), "+f"(c1), "+f"(c2), "+f"(c3)
        : "r"(a0), "r"(a1), "r"(a2), "r"(a3), "r"(b0), "r"(b1));
}
__device__ __forceinline__ void ldsm_x4(uint32_t& r0, uint32_t& r1, uint32_t& r2, uint32_t& r3,
                                        uint32_t addr) {
    asm volatile("ldmatrix.sync.aligned.m8n8.x4.shared.b16 {%0,%1,%2,%3}, [%4];"
                 : "=r"(r0), "=r"(r1), "=r"(r2), "=r"(r3) : "r"(addr));
}
__device__ __forceinline__ uint32_t smem_u32(const void* p) {
    uint32_t a;
    asm("{ .reg .u64 t; cvta.to.shared.u64 t, %1; cvt.u32.u64 %0, t; }" : "=r"(a) : "l"(p));
    return a;
}
__device__ __forceinline__ void cp16(uint32_t dst, const void* src) {
    asm volatile("cp.async.cg.shared.global [%0], [%1], 16;" :: "r"(dst), "l"(src));
}
#define CP_COMMIT() asm volatile("cp.async.commit_group;" ::: "memory")
#define CP_WAIT1()  asm volatile("cp.async.wait_group 1;" ::: "memory")

#define STAGE_WORDS 4096   // A(2048) + B(2048) u32 words per stage (16 KB)

// ---------------- prep: fp16(W) ----------------
__global__ void prep_w_kernel(const float* __restrict__ W) {
    int e = (blockIdx.x * 256 + threadIdx.x) * 2;
    float2 w2 = *(const float2*)(W + e);
    *(uint32_t*)(&g_w_h[e]) = pack_half(w2.x, w2.y);
}

// ---------------- colsum + fp16(K) + fp16 K^T (smem-tiled transpose) ----------------
__global__ __launch_bounds__(256) void colsum_prep_kernel(const float* __restrict__ K) {
    __shared__ uint32_t st[128 * 64];
    __shared__ float red2[256];
    const int t  = threadIdx.x;
    const int cl = t & 127, rq = t >> 7;
    const int c  = blockIdx.x * 128 + cl;
    const int r0 = blockIdx.y * 128;

    float s = 0.f, prev = 0.f;
    #pragma unroll 4
    for (int i = 0; i < 64; ++i) {
        int r = r0 + rq * 64 + i;
        float kv = K[(size_t)r * D + c];
        s += kv;
        g_k_h[(size_t)r * D + c] = __float2half_rn(kv);
        if (i & 1) {
            int r2 = rq * 32 + (i >> 1);
            st[cl * 64 + (r2 ^ (cl & 31))] = pack_half(prev, kv);
        } else prev = kv;
    }
    red2[t] = s;
    __syncthreads();
    if (t < 128) g_kagg_part[blockIdx.y][blockIdx.x * 128 + t] = red2[t] + red2[t + 128];

    uint32_t* kTw = (uint32_t*)g_kT_h;
    size_t dstbase = ((size_t)(blockIdx.x * 128 + cl) * BROWS + r0) / 2 + rq * 32;
    #pragma unroll
    for (int q4 = 0; q4 < 32; q4 += 4) {
        uint4 vv;
        vv.x = st[cl * 64 + ((rq * 32 + q4 + 0) ^ (cl & 31))];
        vv.y = st[cl * 64 + ((rq * 32 + q4 + 1) ^ (cl & 31))];
        vv.z = st[cl * 64 + ((rq * 32 + q4 + 2) ^ (cl & 31))];
        vv.w = st[cl * 64 + ((rq * 32 + q4 + 3) ^ (cl & 31))];
        *(uint4*)(kTw + dstbase + q4) = vv;
    }
}

// ---------------- fused kagg + gates ----------------
__global__ void kagg_gates_kernel(const float* __restrict__ GW, const float* __restrict__ GB,
                                  float* __restrict__ out) {
    __shared__ float red[1024];
    __shared__ float kag[1024];
    int t = threadIdx.x;
    float s = 0.f;
    #pragma unroll 8
    for (int p = 0; p < 128; ++p) s += g_kagg_part[p][t];
    kag[t] = s * (1.0f / (float)BROWS);
    __syncthreads();
    for (int g = 0; g < 3; ++g) {
        red[t] = kag[t] * GW[g * D + t];
        __syncthreads();
        for (int st = 512; st > 0; st >>= 1) {
            if (t < st) red[t] += red[t + st];
            __syncthreads();
        }
        if (t == 0) {
            float z  = red[0] + GB[g];
            float sg = 1.0f / (1.0f + expf(-z));
            g_scalars[g] = sg;
            out[GATES_OFF + g] = sg;
        }
        __syncthreads();
    }
}

// ---------------- GEMM1 (fp16 mma + ldmatrix + cp.async, single-barrier 3-stage) ----------------
// retrieved[m][n] = sum_k K[m][k]*W[n][k]; A = k_h [m][k], B = w_h [n][k], both k-contiguous.
__global__ __launch_bounds__(256, 2) void gemm1_f16_kernel(
    const float* __restrict__ V, float* __restrict__ out) {
    extern __shared__ uint32_t sm1[];
    __shared__ float wred[8];
    const uint32_t sb = smem_u32(sm1);

    const int tid = threadIdx.x;
    const int warp = tid >> 5, lane = tid & 31;
    const int t4 = lane >> 2, tm4 = lane & 3;
    const int n0 = blockIdx.x * 128;
    const int m0 = blockIdx.y * 128;
    const int wm = (warp >> 2) * 64;
    const int wn = (warp & 3) * 32;

    float acc[4][4][4];
    #pragma unroll
    for (int i = 0; i < 4; ++i)
        #pragma unroll
        for (int j = 0; j < 4; ++j)
            #pragma unroll
            for (int r = 0; r < 4; ++r) acc[i][j][r] = 0.f;

    const int laneRowA = (lane & 7) | (lane & 8);
    const int selA = lane >> 4;
    const int laneRowB = (lane & 7) | ((lane & 16) >> 1);
    const int selB = (lane >> 3) & 1;

    uint32_t offA[4], swA[4];
    #pragma unroll
    for (int mt = 0; mt < 4; ++mt) {
        int row = wm + mt * 16 + laneRowA;
        offA[mt] = row * 64;
        swA[mt]  = (row + (row >> 2)) & 3;
    }
    uint32_t offB[2], swB[2];
    #pragma unroll
    for (int np = 0; np < 2; ++np) {
        int row = wn + np * 16 + laneRowB;
        offB[np] = row * 64;
        swB[np]  = (row + (row >> 2)) & 3;
    }

    const int srow = tid >> 2, sg = tid & 3;

    // prologue: stages 0,1
    #pragma unroll
    for (int s = 0; s < 2; ++s) {
        #pragma unroll
        for (int it = 0; it < 2; ++it) {
            int row = it * 64 + srow;
            int swz = (sg ^ ((row + (row >> 2)) & 3)) << 2;
            uint32_t dA = sb + (s * STAGE_WORDS + row * 16 + swz) * 4;
            uint32_t dB = dA + 2048 * 4;
            cp16(dA, g_k_h + (size_t)(m0 + row) * D + s * 32 + sg * 8);
            cp16(dB, g_w_h + (size_t)(n0 + row) * D + s * 32 + sg * 8);
        }
        CP_COMMIT();
    }

    const int NCH = D / 32;   // 32 chunks
    for (int c = 0; c < NCH; ++c) {
        const int buf = c % 3;
        CP_WAIT1();
        __syncthreads();
        if (c + 2 < NCH) {
            const int nb = (c + 2) % 3;
            #pragma unroll
            for (int it = 0; it < 2; ++it) {
                int row = it * 64 + srow;
                int swz = (sg ^ ((row + (row >> 2)) & 3)) << 2;
                uint32_t dA = sb + (nb * STAGE_WORDS + row * 16 + swz) * 4;
                uint32_t dB = dA + 2048 * 4;
                cp16(dA, g_k_h + (size_t)(m0 + row) * D + (c + 2) * 32 + sg * 8);
                cp16(dB, g_w_h + (size_t)(n0 + row) * D + (c + 2) * 32 + sg * 8);
            }
        }
        CP_COMMIT();

        const uint32_t abase = sb + buf * (STAGE_WORDS * 4);
        const uint32_t bbase = abase + 2048 * 4;
        #pragma unroll
        for (int ks = 0; ks < 2; ++ks) {
            const int g0 = ks * 2;
            uint32_t a[4][4], b[2][4];
            #pragma unroll
            for (int mt = 0; mt < 4; ++mt)
                ldsm_x4(a[mt][0], a[mt][1], a[mt][2], a[mt][3],
                        abase + offA[mt] + ((((uint32_t)(g0 + selA)) ^ swA[mt]) << 4));
            #pragma unroll
            for (int np = 0; np < 2; ++np)
                ldsm_x4(b[np][0], b[np][1], b[np][2], b[np][3],
                        bbase + offB[np] + ((((uint32_t)(g0 + selB)) ^ swB[np]) << 4));
            #pragma unroll
            for (int mt = 0; mt < 4; ++mt)
                #pragma unroll
                for (int nt = 0; nt < 4; ++nt) {
                    const int np = nt >> 1, lo = (nt & 1) * 2;
                    mma_f16(acc[mt][nt][0], acc[mt][nt][1], acc[mt][nt][2], acc[mt][nt][3],
                            a[mt][0], a[mt][1], a[mt][2], a[mt][3], b[np][lo], b[np][lo + 1]);
                }
        }
    }

    // Epilogue: retrieved (fp32) + diffT (fp16, transposed) + loss partial
    float lsum = 0.f;
    #pragma unroll
    for (int mt = 0; mt < 4; ++mt) {
        #pragma unroll
        for (int nt = 0; nt < 4; ++nt) {
            int r  = m0 + wm + mt * 16 + t4;
            int cc = n0 + wn + nt * 8 + 2 * tm4;
            size_t e0 = (size_t)r * D + cc;
            size_t e1 = (size_t)(r + 8) * D + cc;
            float2 v0 = *(const float2*)(V + e0);
            float2 v1 = *(const float2*)(V + e1);
            float2 c0 = make_float2(acc[mt][nt][0], acc[mt][nt][1]);
            float2 c1 = make_float2(acc[mt][nt][2], acc[mt][nt][3]);
            *(float2*)(out + RET_OFF + e0) = c0;
            *(float2*)(out + RET_OFF + e1) = c1;
            float d0 = c0.x - v0.x, d1 = c0.y - v0.y;
            float d2 = c1.x - v1.x, d3 = c1.y - v1.y;
            g_diffT_h[(size_t)cc * BROWS + r]           = __float2half_rn(d0);
            g_diffT_h[(size_t)(cc + 1) * BROWS + r]     = __float2half_rn(d1);
            g_diffT_h[(size_t)cc * BROWS + r + 8]       = __float2half_rn(d2);
            g_diffT_h[(size_t)(cc + 1) * BROWS + r + 8] = __float2half_rn(d3);
            lsum += d0 * d0 + d1 * d1 + d2 * d2 + d3 * d3;
        }
    }
    #pragma unroll
    for (int o = 16; o > 0; o >>= 1) lsum += __shfl_xor_sync(0xffffffffu, lsum, o);
    if (lane == 0) wred[warp] = lsum;
    __syncthreads();
    if (tid == 0) {
        float t = 0.f;
        #pragma unroll
        for (int w = 0; w < 8; ++w) t += wred[w];
        g_loss_part[blockIdx.y * 8 + blockIdx.x] = t;
    }
}

// ---------------- GEMM2 (fp16 mma + ldmatrix + cp.async, single-barrier 3-stage) ----------------
__global__ __launch_bounds__(256, 2) void gemm2_f16_kernel() {
    extern __shared__ uint32_t sm2[];
    const uint32_t sb = smem_u32(sm2);

    const int tid = threadIdx.x;
    const int warp = tid >> 5, lane = tid & 31;
    const int t4 = lane >> 2, tm4 = lane & 3;
    const int j0 = blockIdx.x * 128;
    const int i0 = blockIdx.y * 128;
    const int z  = blockIdx.z;
    const int b0z = z * (BROWS / 4);
    const int wm = (warp >> 2) * 64;   // i
    const int wn = (warp & 3) * 32;    // j

    float acc[4][4][4];
    #pragma unroll
    for (int i = 0; i < 4; ++i)
        #pragma unroll
        for (int j = 0; j < 4; ++j)
            #pragma unroll
            for (int r = 0; r < 4; ++r) acc[i][j][r] = 0.f;

    const int laneRowA = (lane & 7) | (lane & 8);
    const int selA = lane >> 4;
    const int laneRowB = (lane & 7) | ((lane & 16) >> 1);
    const int selB = (lane >> 3) & 1;

    uint32_t offA[4], swA[4];
    #pragma unroll
    for (int mt = 0; mt < 4; ++mt) {
        int row = wm + mt * 16 + laneRowA;
        offA[mt] = row * 64;
        swA[mt]  = (row + (row >> 2)) & 3;
    }
    uint32_t offB[2], swB[2];
    #pragma unroll
    for (int np = 0; np < 2; ++np) {
        int row = wn + np * 16 + laneRowB;
        offB[np] = row * 64;
        swB[np]  = (row + (row >> 2)) & 3;
    }

    const int srow = tid >> 2, sg = tid & 3;

    #pragma unroll
    for (int s = 0; s < 2; ++s) {
        #pragma unroll
        for (int it = 0; it < 2; ++it) {
            int row = it * 64 + srow;
            int swz = (sg ^ ((row + (row >> 2)) & 3)) << 2;
            uint32_t dA = sb + (s * STAGE_WORDS + row * 16 + swz) * 4;
            uint32_t dB = dA + 2048 * 4;
            cp16(dA, g_diffT_h + (size_t)(i0 + row) * BROWS + b0z + s * 32 + sg * 8);
            cp16(dB, g_kT_h    + (size_t)(j0 + row) * BROWS + b0z + s * 32 + sg * 8);
        }
        CP_COMMIT();
    }

    const int NCH = BROWS / 4 / 32;   // 128 chunks
    for (int c = 0; c < NCH; ++c) {
        const int buf = c % 3;
        CP_WAIT1();
        __syncthreads();
        if (c + 2 < NCH) {
            const int nb = (c + 2) % 3;
            #pragma unroll
            for (int it = 0; it < 2; ++it) {
                int row = it * 64 + srow;
                int swz = (sg ^ ((row + (row >> 2)) & 3)) << 2;
                uint32_t dA = sb + (nb * STAGE_WORDS + row * 16 + swz) * 4;
                uint32_t dB = dA + 2048 * 4;
                cp16(dA, g_diffT_h + (size_t)(i0 + row) * BROWS + b0z + (c + 2) * 32 + sg * 8);
                cp16(dB, g_kT_h    + (size_t)(j0 + row) * BROWS + b0z + (c + 2) * 32 + sg * 8);
            }
        }
        CP_COMMIT();

        const uint32_t abase = sb + buf * (STAGE_WORDS * 4);
        const uint32_t bbase = abase + 2048 * 4;
        #pragma unroll
        for (int ks = 0; ks < 2; ++ks) {
            const int g0 = ks * 2;
            uint32_t a[4][4], b[2][4];
            #pragma unroll
            for (int mt = 0; mt < 4; ++mt)
                ldsm_x4(a[mt][0], a[mt][1], a[mt][2], a[mt][3],
                        abase + offA[mt] + ((((uint32_t)(g0 + selA)) ^ swA[mt]) << 4));
            #pragma unroll
            for (int np = 0; np < 2; ++np)
                ldsm_x4(b[np][0], b[np][1], b[np][2], b[np][3],
                        bbase + offB[np] + ((((uint32_t)(g0 + selB)) ^ swB[np]) << 4));
            #pragma unroll
            for (int mt = 0; mt < 4; ++mt)
                #pragma unroll
                for (int nt = 0; nt < 4; ++nt) {
                    const int np = nt >> 1, lo = (nt & 1) * 2;
                    mma_f16(acc[mt][nt][0], acc[mt][nt][1], acc[mt][nt][2], acc[mt][nt][3],
                            a[mt][0], a[mt][1], a[mt][2], a[mt][3], b[np][lo], b[np][lo + 1]);
                }
        }
    }

    float* gp = g_grad_part[z];
    #pragma unroll
    for (int mt = 0; mt < 4; ++mt) {
        #pragma unroll
        for (int nt = 0; nt < 4; ++nt) {
            int r  = i0 + wm + mt * 16 + t4;
            int cc = j0 + wn + nt * 8 + 2 * tm4;
            *(float2*)(gp + (size_t)r * D + cc)       = make_float2(acc[mt][nt][0], acc[mt][nt][1]);
            *(float2*)(gp + (size_t)(r + 8) * D + cc) = make_float2(acc[mt][nt][2], acc[mt][nt][3]);
        }
    }
}

__global__ void loss_reduce_kernel(float* __restrict__ out) {
    __shared__ float red[1024];
    int tid = threadIdx.x;
    red[tid] = g_loss_part[tid];
    __syncthreads();
    for (int s = 512; s > 0; s >>= 1) {
        if (tid < s) red[tid] += red[tid + s];
        __syncthreads();
    }
    if (tid == 0) out[LOSS_OFF] = red[0] / (float)(BROWS * D);
}

// ---------------- momentum (+ fused norm via deterministic last-block) ----------------
__global__ void momentum_prep_kernel(const float* __restrict__ MOM) {
    __shared__ float red[256];
    __shared__ int amLast;
    int tid = threadIdx.x;
    int t = blockIdx.x * 256 + tid;
    float eta = g_scalars[1], theta = g_scalars[2];
    float lr_th = TTT_LR * theta;
    float nsum = 0.f;
    #pragma unroll
    for (int it = 0; it < 16; ++it) {
        int e = t + it * 65536;
        float g = (g_grad_part[0][e] + g_grad_part[1][e] +
                   g_grad_part[2][e] + g_grad_part[3][e]) * TWO_OVER_N;
        float gc = fminf(1.0f, fmaxf(-1.0f, g));
        float nm = eta * MOM[e] - lr_th * gc;
        g_nm_raw[e] = nm;
        nsum += nm * nm;
    }
    red[tid] = nsum;
    __syncthreads();
    for (int s = 128; s > 0; s >>= 1) {
        if (tid < s) red[tid] += red[tid + s];
        __syncthreads();
    }
    if (tid == 0) g_norm_part[0][blockIdx.x] = red[0];
    __threadfence();
    if (tid == 0) amLast = (atomicAdd(&g_ctr[0], 1) == 255);
    __syncthreads();
    if (amLast) {
        red[tid] = g_norm_part[0][tid];
        __syncthreads();
        for (int s = 128; s > 0; s >>= 1) {
            if (tid < s) red[tid] += red[tid + s];
            __syncthreads();
        }
        if (tid == 0) {
            float n = sqrtf(red[0]);
            g_scalars[4] = (n > MEM_MAX_NORM) ? (MEM_MAX_NORM / (n + 1e-8f)) : 1.0f;
            g_ctr[0] = 0;
        }
    }
}

// ---------------- weight (+ fused norm) ----------------
__global__ void weight_prep_kernel(const float* __restrict__ MW, float* __restrict__ out) {
    __shared__ float red[256];
    __shared__ int amLast;
    int tid = threadIdx.x;
    int t = blockIdx.x * 256 + tid;
    float alpha = g_scalars[0];
    float sm = g_scalars[4];
    float one_m_a = 1.0f - alpha;
    float wsum = 0.f;
    #pragma unroll
    for (int it = 0; it < 16; ++it) {
        int e = t + it * 65536;
        float nm = g_nm_raw[e] * sm;
        out[NM_OFF + e] = nm;
        float w = one_m_a * MW[e] + nm;
        g_w_raw[e] = w;
        wsum += w * w;
    }
    red[tid] = wsum;
    __syncthreads();
    for (int s = 128; s > 0; s >>= 1) {
        if (tid < s) red[tid] += red[tid + s];
        __syncthreads();
    }
    if (tid == 0) g_norm_part[1][blockIdx.x] = red[0];
    __threadfence();
    if (tid == 0) amLast = (atomicAdd(&g_ctr[1], 1) == 255);
    __syncthreads();
    if (amLast) {
        red[tid] = g_norm_part[1][tid];
        __syncthreads();
        for (int s = 128; s > 0; s >>= 1) {
            if (tid < s) red[tid] += red[tid + s];
            __syncthreads();
        }
        if (tid == 0) {
            float n = sqrtf(red[0]);
            g_scalars[5] = (n > MEM_MAX_NORM) ? (MEM_MAX_NORM / (n + 1e-8f)) : 1.0f;
            g_ctr[1] = 0;
        }
    }
}

__global__ void final_w_kernel(float* __restrict__ out) {
    int t = blockIdx.x * 256 + threadIdx.x;
    float sw = g_scalars[5];
    #pragma unroll
    for (int it = 0; it < 16; ++it) {
        int e = t + it * 65536;
        out[W_OFF + e] = g_w_raw[e] * sw;
    }
}

// ---------------- launch ----------------
extern "C" void kernel_launch(void* const* d_in, const int* in_sizes, int n_in,
                              void* d_out, int out_size) {
    const float* k    = (const float*)d_in[0];
    const float* v    = (const float*)d_in[1];
    const float* memw = (const float*)d_in[2];
    const float* gw   = (const float*)d_in[3];
    const float* gb   = (const float*)d_in[4];
    const float* mom  = (const float*)d_in[5];
    float* out = (float*)d_out;

    const int g_smem = 3 * STAGE_WORDS * 4;   // 49152
    cudaFuncSetAttribute(gemm1_f16_kernel, cudaFuncAttributeMaxDynamicSharedMemorySize, g_smem);
    cudaFuncSetAttribute(gemm2_f16_kernel, cudaFuncAttributeMaxDynamicSharedMemorySize, g_smem);

    prep_w_kernel<<<2048, 256>>>(memw);
    colsum_prep_kernel<<<dim3(8, 128), 256>>>(k);
    kagg_gates_kernel<<<1, 1024>>>(gw, gb, out);
    gemm1_f16_kernel<<<dim3(8, 128), 256, g_smem>>>(v, out);   // launch #4 -> ncu capture
    gemm2_f16_kernel<<<dim3(8, 8, 4), 256, g_smem>>>();
    loss_reduce_kernel<<<1, 1024>>>(out);
    momentum_prep_kernel<<<256, 256>>>(mom);
    weight_prep_kernel<<<256, 256>>>(memw, out);
    final_w_kernel<<<256, 256>>>(out);
}

// round 8
// speedup vs baseline: 6.8534x; 1.0475x over previous
#include <cuda_runtime.h>
#include <cuda_fp16.h>
#include <math.h>
#include <stdint.h>

// Problem constants
#define BROWS 16384
#define D     1024

// Output layout: retrieved (B*D) | loss (1) | new_weight (D*D) | new_momentum (D*D) | gates (3)
#define RET_OFF   0
#define LOSS_OFF  (BROWS * D)
#define W_OFF     (LOSS_OFF + 1)              // odd -> scalar stores only
#define NM_OFF    (W_OFF + D * D)             // odd -> scalar stores only
#define GATES_OFF (NM_OFF + D * D)

#define MEM_MAX_NORM 5.0f
#define TTT_LR 0.005f
#define TWO_OVER_N (2.0f / (float)(BROWS * D))

// ---------------- device scratch (static, no runtime allocation) ----------------
__device__ float g_kagg_part[128][D];
__device__ float g_scalars[8];        // 0:alpha 1:eta 2:theta 4:scale_m 5:scale_w
__device__ float g_loss_part[1024];
__device__ float g_loss_total[1];
__device__ float g_grad_part[4][D * D];   // split-B partials for GEMM2 (16 MB)
__device__ float g_nm_raw[D * D];
__device__ float g_w_raw[D * D];
__device__ float g_norm_part[2][256];
__device__ int   g_ctr[2];
__device__ __half g_k_h[BROWS * D];        // fp16 K, row-major [b][c] (32 MB)
__device__ __half g_w_h[D * D];            // fp16 W, row-major [n][k] (2 MB)
__device__ __half g_kT_h[D * BROWS];       // fp16 K^T [c][b] (32 MB)
__device__ __half g_diffT_h[D * BROWS];    // fp16 (retrieved-V)^T [i][b] (32 MB)

// ================= PTX helpers (family-portable, sm_80+) =================
__device__ __forceinline__ uint32_t pack_half(float a, float b) {
    __half2 h = __floats2half2_rn(a, b);
    return *(uint32_t*)&h;
}
__device__ __forceinline__ void mma_f16(float& c0, float& c1, float& c2, float& c3,
                                        uint32_t a0, uint32_t a1, uint32_t a2, uint32_t a3,
                                        uint32_t b0, uint32_t b1) {
    asm volatile(
        "mma.sync.aligned.m16n8k16.row.col.f32.f16.f16.f32 "
        "{%0,%1,%2,%3}, {%4,%5,%6,%7}, {%8,%9}, {%0,%1,%2,%3};"
        : "+f"(c0), "+f"(c1), "+f"(c2), "+f"(c3)
        : "r"(a0), "r"(a1), "r"(a2), "r"(a3), "r"(b0), "r"(b1));
}
__device__ __forceinline__ void ldsm_x4(uint32_t& r0, uint32_t& r1, uint32_t& r2, uint32_t& r3,
                                        uint32_t addr) {
    asm volatile("ldmatrix.sync.aligned.m8n8.x4.shared.b16 {%0,%1,%2,%3}, [%4];"
                 : "=r"(r0), "=r"(r1), "=r"(r2), "=r"(r3) : "r"(addr));
}
__device__ __forceinline__ uint32_t smem_u32(const void* p) {
    uint32_t a;
    asm("{ .reg .u64 t; cvta.to.shared.u64 t, %1; cvt.u32.u64 %0, t; }" : "=r"(a) : "l"(p));
    return a;
}
__device__ __forceinline__ void cp16(uint32_t dst, const void* src) {
    asm volatile("cp.async.cg.shared.global [%0], [%1], 16;" :: "r"(dst), "l"(src));
}
#define CP_COMMIT() asm volatile("cp.async.commit_group;" ::: "memory")
#define CP_WAIT1()  asm volatile("cp.async.wait_group 1;" ::: "memory")

// K-chunk 64: stage = A(128x64 half = 16KB) + B(16KB) = 32KB = 8192 words
#define STAGE_WORDS 8192
#define B_OFF_WORDS 4096

// ---------------- prep: fp16(W) ----------------
__global__ void prep_w_kernel(const float* __restrict__ W) {
    int e = (blockIdx.x * 256 + threadIdx.x) * 2;
    float2 w2 = *(const float2*)(W + e);
    *(uint32_t*)(&g_w_h[e]) = pack_half(w2.x, w2.y);
}

// ---------------- colsum + fp16(K) + fp16 K^T (smem-tiled transpose) ----------------
__global__ __launch_bounds__(256) void colsum_prep_kernel(const float* __restrict__ K) {
    __shared__ uint32_t st[128 * 64];
    __shared__ float red2[256];
    const int t  = threadIdx.x;
    const int cl = t & 127, rq = t >> 7;
    const int c  = blockIdx.x * 128 + cl;
    const int r0 = blockIdx.y * 128;

    float s = 0.f, prev = 0.f;
    #pragma unroll 4
    for (int i = 0; i < 64; ++i) {
        int r = r0 + rq * 64 + i;
        float kv = K[(size_t)r * D + c];
        s += kv;
        g_k_h[(size_t)r * D + c] = __float2half_rn(kv);
        if (i & 1) {
            int r2 = rq * 32 + (i >> 1);
            st[cl * 64 + (r2 ^ (cl & 31))] = pack_half(prev, kv);
        } else prev = kv;
    }
    red2[t] = s;
    __syncthreads();
    if (t < 128) g_kagg_part[blockIdx.y][blockIdx.x * 128 + t] = red2[t] + red2[t + 128];

    uint32_t* kTw = (uint32_t*)g_kT_h;
    size_t dstbase = ((size_t)(blockIdx.x * 128 + cl) * BROWS + r0) / 2 + rq * 32;
    #pragma unroll
    for (int q4 = 0; q4 < 32; q4 += 4) {
        uint4 vv;
        vv.x = st[cl * 64 + ((rq * 32 + q4 + 0) ^ (cl & 31))];
        vv.y = st[cl * 64 + ((rq * 32 + q4 + 1) ^ (cl & 31))];
        vv.z = st[cl * 64 + ((rq * 32 + q4 + 2) ^ (cl & 31))];
        vv.w = st[cl * 64 + ((rq * 32 + q4 + 3) ^ (cl & 31))];
        *(uint4*)(kTw + dstbase + q4) = vv;
    }
}

// ---------------- fused kagg + gates ----------------
__global__ void kagg_gates_kernel(const float* __restrict__ GW, const float* __restrict__ GB,
                                  float* __restrict__ out) {
    __shared__ float red[1024];
    __shared__ float kag[1024];
    int t = threadIdx.x;
    float s = 0.f;
    #pragma unroll 8
    for (int p = 0; p < 128; ++p) s += g_kagg_part[p][t];
    kag[t] = s * (1.0f / (float)BROWS);
    __syncthreads();
    for (int g = 0; g < 3; ++g) {
        red[t] = kag[t] * GW[g * D + t];
        __syncthreads();
        for (int st = 512; st > 0; st >>= 1) {
            if (t < st) red[t] += red[t + st];
            __syncthreads();
        }
        if (t == 0) {
            float z  = red[0] + GB[g];
            float sg = 1.0f / (1.0f + expf(-z));
            g_scalars[g] = sg;
            out[GATES_OFF + g] = sg;
        }
        __syncthreads();
    }
}

// ======= shared GEMM body pieces (4 warps, 64x64 warp tile, k64 chunks) =======
// fragment row selectors (standard m16n8k16 / ldmatrix.x4 mapping)
#define FRAG_SETUP()                                              \
    const int laneRowA = (lane & 7) | (lane & 8);                 \
    const int selA = lane >> 4;                                   \
    const int laneRowB = (lane & 7) | ((lane & 16) >> 1);         \
    const int selB = (lane >> 3) & 1;                             \
    uint32_t offA[4], swA4[4];                                    \
    _Pragma("unroll")                                             \
    for (int mt = 0; mt < 4; ++mt) {                              \
        int row = wm + mt * 16 + laneRowA;                        \
        offA[mt] = row * 128;                                     \
        swA4[mt] = row & 7;                                       \
    }                                                             \
    uint32_t offB[4], swB4[4];                                    \
    _Pragma("unroll")                                             \
    for (int np = 0; np < 4; ++np) {                              \
        int row = wn + np * 16 + laneRowB;                        \
        offB[np] = row * 128;                                     \
        swB4[np] = row & 7;                                       \
    }

#define CHUNK_COMPUTE(abase, bbase)                                                   \
    _Pragma("unroll")                                                                 \
    for (int ks = 0; ks < 4; ++ks) {                                                  \
        const int g0 = ks * 2;                                                        \
        uint32_t a[4][4], b[4][4];                                                    \
        _Pragma("unroll")                                                             \
        for (int mt = 0; mt < 4; ++mt)                                                \
            ldsm_x4(a[mt][0], a[mt][1], a[mt][2], a[mt][3],                           \
                    (abase) + offA[mt] + ((((uint32_t)(g0 + selA)) ^ swA4[mt]) << 4));\
        _Pragma("unroll")                                                             \
        for (int np = 0; np < 4; ++np)                                                \
            ldsm_x4(b[np][0], b[np][1], b[np][2], b[np][3],                           \
                    (bbase) + offB[np] + ((((uint32_t)(g0 + selB)) ^ swB4[np]) << 4));\
        _Pragma("unroll")                                                             \
        for (int mt = 0; mt < 4; ++mt)                                                \
            _Pragma("unroll")                                                         \
            for (int nt = 0; nt < 8; ++nt) {                                          \
                const int np = nt >> 1, lo = (nt & 1) * 2;                            \
                mma_f16(acc[mt][nt][0], acc[mt][nt][1], acc[mt][nt][2], acc[mt][nt][3],\
                        a[mt][0], a[mt][1], a[mt][2], a[mt][3], b[np][lo], b[np][lo + 1]);\
            }                                                                         \
    }

// staging: 128 threads, srow = tid>>3 (16 rows/pass, 8 passes), sg = tid&7
#define STAGE_CHUNK(stagebase, srcA, srcB)                                            \
    _Pragma("unroll")                                                                 \
    for (int it = 0; it < 8; ++it) {                                                  \
        int row = it * 16 + srow;                                                     \
        uint32_t wo = (uint32_t)(row * 32 + ((sg ^ (row & 7)) << 2));                 \
        cp16((stagebase) + wo * 4, (srcA) + (size_t)row * srcStrideA);                \
        cp16((stagebase) + (B_OFF_WORDS + wo) * 4, (srcB) + (size_t)row * srcStrideB);\
    }

// ---------------- GEMM1 (fp16, 64x64 warp tile): retrieved = K @ W^T ----------------
__global__ __launch_bounds__(128, 2) void gemm1_f16_kernel(
    const float* __restrict__ V, float* __restrict__ out) {
    extern __shared__ uint32_t sm1[];
    __shared__ float wred[4];
    const uint32_t sb = smem_u32(sm1);

    const int tid = threadIdx.x;
    const int warp = tid >> 5, lane = tid & 31;
    const int t4 = lane >> 2, tm4 = lane & 3;
    const int n0 = blockIdx.x * 128;
    const int m0 = blockIdx.y * 128;
    const int wm = (warp >> 1) * 64;
    const int wn = (warp & 1) * 64;

    float acc[4][8][4];
    #pragma unroll
    for (int i = 0; i < 4; ++i)
        #pragma unroll
        for (int j = 0; j < 8; ++j)
            #pragma unroll
            for (int r = 0; r < 4; ++r) acc[i][j][r] = 0.f;

    FRAG_SETUP();

    const int srow = tid >> 3, sg = tid & 7;
    const size_t srcStrideA = D, srcStrideB = D;
    const __half* gA = g_k_h + (size_t)m0 * D + sg * 8;
    const __half* gB = g_w_h + (size_t)n0 * D + sg * 8;

    // prologue: stages 0,1
    #pragma unroll
    for (int s = 0; s < 2; ++s) {
        STAGE_CHUNK(sb + s * (STAGE_WORDS * 4), gA + s * 64, gB + s * 64);
        CP_COMMIT();
    }

    const int NCH = D / 64;   // 16 chunks
    for (int c = 0; c < NCH; ++c) {
        const int buf = c % 3;
        CP_WAIT1();
        __syncthreads();
        if (c + 2 < NCH) {
            const int nb = (c + 2) % 3;
            STAGE_CHUNK(sb + nb * (STAGE_WORDS * 4), gA + (c + 2) * 64, gB + (c + 2) * 64);
        }
        CP_COMMIT();

        const uint32_t abase = sb + buf * (STAGE_WORDS * 4);
        const uint32_t bbase = abase + B_OFF_WORDS * 4;
        CHUNK_COMPUTE(abase, bbase);
    }

    // Epilogue: retrieved (fp32) + diffT (fp16, transposed) + loss partial
    float lsum = 0.f;
    #pragma unroll
    for (int mt = 0; mt < 4; ++mt) {
        #pragma unroll
        for (int nt = 0; nt < 8; ++nt) {
            int r  = m0 + wm + mt * 16 + t4;
            int cc = n0 + wn + nt * 8 + 2 * tm4;
            size_t e0 = (size_t)r * D + cc;
            size_t e1 = (size_t)(r + 8) * D + cc;
            float2 v0 = *(const float2*)(V + e0);
            float2 v1 = *(const float2*)(V + e1);
            float2 c0 = make_float2(acc[mt][nt][0], acc[mt][nt][1]);
            float2 c1 = make_float2(acc[mt][nt][2], acc[mt][nt][3]);
            *(float2*)(out + RET_OFF + e0) = c0;
            *(float2*)(out + RET_OFF + e1) = c1;
            float d0 = c0.x - v0.x, d1 = c0.y - v0.y;
            float d2 = c1.x - v1.x, d3 = c1.y - v1.y;
            g_diffT_h[(size_t)cc * BROWS + r]           = __float2half_rn(d0);
            g_diffT_h[(size_t)(cc + 1) * BROWS + r]     = __float2half_rn(d1);
            g_diffT_h[(size_t)cc * BROWS + r + 8]       = __float2half_rn(d2);
            g_diffT_h[(size_t)(cc + 1) * BROWS + r + 8] = __float2half_rn(d3);
            lsum += d0 * d0 + d1 * d1 + d2 * d2 + d3 * d3;
        }
    }
    #pragma unroll
    for (int o = 16; o > 0; o >>= 1) lsum += __shfl_xor_sync(0xffffffffu, lsum, o);
    if (lane == 0) wred[warp] = lsum;
    __syncthreads();
    if (tid == 0)
        g_loss_part[blockIdx.y * 8 + blockIdx.x] = wred[0] + wred[1] + wred[2] + wred[3];
}

// ---------------- GEMM2 (fp16, 64x64 warp tile): grad_part[z] = diffT @ kT^T ----------------
__global__ __launch_bounds__(128, 2) void gemm2_f16_kernel() {
    extern __shared__ uint32_t sm2[];
    const uint32_t sb = smem_u32(sm2);

    const int tid = threadIdx.x;
    const int warp = tid >> 5, lane = tid & 31;
    const int t4 = lane >> 2, tm4 = lane & 3;
    const int j0 = blockIdx.x * 128;
    const int i0 = blockIdx.y * 128;
    const int z  = blockIdx.z;
    const int b0z = z * (BROWS / 4);
    const int wm = (warp >> 1) * 64;   // i
    const int wn = (warp & 1) * 64;    // j

    float acc[4][8][4];
    #pragma unroll
    for (int i = 0; i < 4; ++i)
        #pragma unroll
        for (int j = 0; j < 8; ++j)
            #pragma unroll
            for (int r = 0; r < 4; ++r) acc[i][j][r] = 0.f;

    FRAG_SETUP();

    const int srow = tid >> 3, sg = tid & 7;
    const size_t srcStrideA = BROWS, srcStrideB = BROWS;
    const __half* gA = g_diffT_h + (size_t)i0 * BROWS + b0z + sg * 8;
    const __half* gB = g_kT_h    + (size_t)j0 * BROWS + b0z + sg * 8;

    #pragma unroll
    for (int s = 0; s < 2; ++s) {
        STAGE_CHUNK(sb + s * (STAGE_WORDS * 4), gA + s * 64, gB + s * 64);
        CP_COMMIT();
    }

    const int NCH = (BROWS / 4) / 64;   // 64 chunks
    for (int c = 0; c < NCH; ++c) {
        const int buf = c % 3;
        CP_WAIT1();
        __syncthreads();
        if (c + 2 < NCH) {
            const int nb = (c + 2) % 3;
            STAGE_CHUNK(sb + nb * (STAGE_WORDS * 4), gA + (c + 2) * 64, gB + (c + 2) * 64);
        }
        CP_COMMIT();

        const uint32_t abase = sb + buf * (STAGE_WORDS * 4);
        const uint32_t bbase = abase + B_OFF_WORDS * 4;
        CHUNK_COMPUTE(abase, bbase);
    }

    float* gp = g_grad_part[z];
    #pragma unroll
    for (int mt = 0; mt < 4; ++mt) {
        #pragma unroll
        for (int nt = 0; nt < 8; ++nt) {
            int r  = i0 + wm + mt * 16 + t4;
            int cc = j0 + wn + nt * 8 + 2 * tm4;
            *(float2*)(gp + (size_t)r * D + cc)       = make_float2(acc[mt][nt][0], acc[mt][nt][1]);
            *(float2*)(gp + (size_t)(r + 8) * D + cc) = make_float2(acc[mt][nt][2], acc[mt][nt][3]);
        }
    }
}

// ---------------- momentum (+ loss finalize in block 0, + fused norm) ----------------
__global__ void momentum_prep_kernel(const float* __restrict__ MOM, float* __restrict__ out) {
    __shared__ float red[256];
    __shared__ int amLast;
    int tid = threadIdx.x;
    int t = blockIdx.x * 256 + tid;

    if (blockIdx.x == 0) {   // loss reduce (independent work)
        float ls = g_loss_part[tid] + g_loss_part[tid + 256] +
                   g_loss_part[tid + 512] + g_loss_part[tid + 768];
        red[tid] = ls;
        __syncthreads();
        for (int s = 128; s > 0; s >>= 1) {
            if (tid < s) red[tid] += red[tid + s];
            __syncthreads();
        }
        if (tid == 0) out[LOSS_OFF] = red[0] / (float)(BROWS * D);
        __syncthreads();
    }

    float eta = g_scalars[1], theta = g_scalars[2];
    float lr_th = TTT_LR * theta;
    float nsum = 0.f;
    #pragma unroll
    for (int it = 0; it < 16; ++it) {
        int e = t + it * 65536;
        float g = (g_grad_part[0][e] + g_grad_part[1][e] +
                   g_grad_part[2][e] + g_grad_part[3][e]) * TWO_OVER_N;
        float gc = fminf(1.0f, fmaxf(-1.0f, g));
        float nm = eta * MOM[e] - lr_th * gc;
        g_nm_raw[e] = nm;
        nsum += nm * nm;
    }
    red[tid] = nsum;
    __syncthreads();
    for (int s = 128; s > 0; s >>= 1) {
        if (tid < s) red[tid] += red[tid + s];
        __syncthreads();
    }
    if (tid == 0) g_norm_part[0][blockIdx.x] = red[0];
    __threadfence();
    if (tid == 0) amLast = (atomicAdd(&g_ctr[0], 1) == 255);
    __syncthreads();
    if (amLast) {
        red[tid] = g_norm_part[0][tid];
        __syncthreads();
        for (int s = 128; s > 0; s >>= 1) {
            if (tid < s) red[tid] += red[tid + s];
            __syncthreads();
        }
        if (tid == 0) {
            float n = sqrtf(red[0]);
            g_scalars[4] = (n > MEM_MAX_NORM) ? (MEM_MAX_NORM / (n + 1e-8f)) : 1.0f;
            g_ctr[0] = 0;
        }
    }
}

// ---------------- weight (+ fused norm) ----------------
__global__ void weight_prep_kernel(const float* __restrict__ MW, float* __restrict__ out) {
    __shared__ float red[256];
    __shared__ int amLast;
    int tid = threadIdx.x;
    int t = blockIdx.x * 256 + tid;
    float alpha = g_scalars[0];
    float sm = g_scalars[4];
    float one_m_a = 1.0f - alpha;
    float wsum = 0.f;
    #pragma unroll
    for (int it = 0; it < 16; ++it) {
        int e = t + it * 65536;
        float nm = g_nm_raw[e] * sm;
        out[NM_OFF + e] = nm;
        float w = one_m_a * MW[e] + nm;
        g_w_raw[e] = w;
        wsum += w * w;
    }
    red[tid] = wsum;
    __syncthreads();
    for (int s = 128; s > 0; s >>= 1) {
        if (tid < s) red[tid] += red[tid + s];
        __syncthreads();
    }
    if (tid == 0) g_norm_part[1][blockIdx.x] = red[0];
    __threadfence();
    if (tid == 0) amLast = (atomicAdd(&g_ctr[1], 1) == 255);
    __syncthreads();
    if (amLast) {
        red[tid] = g_norm_part[1][tid];
        __syncthreads();
        for (int s = 128; s > 0; s >>= 1) {
            if (tid < s) red[tid] += red[tid + s];
            __syncthreads();
        }
        if (tid == 0) {
            float n = sqrtf(red[0]);
            g_scalars[5] = (n > MEM_MAX_NORM) ? (MEM_MAX_NORM / (n + 1e-8f)) : 1.0f;
            g_ctr[1] = 0;
        }
    }
}

__global__ void final_w_kernel(float* __restrict__ out) {
    int t = blockIdx.x * 256 + threadIdx.x;
    float sw = g_scalars[5];
    #pragma unroll
    for (int it = 0; it < 16; ++it) {
        int e = t + it * 65536;
        out[W_OFF + e] = g_w_raw[e] * sw;
    }
}

// ---------------- launch ----------------
extern "C" void kernel_launch(void* const* d_in, const int* in_sizes, int n_in,
                              void* d_out, int out_size) {
    const float* k    = (const float*)d_in[0];
    const float* v    = (const float*)d_in[1];
    const float* memw = (const float*)d_in[2];
    const float* gw   = (const float*)d_in[3];
    const float* gb   = (const float*)d_in[4];
    const float* mom  = (const float*)d_in[5];
    float* out = (float*)d_out;

    const int g_smem = 3 * STAGE_WORDS * 4;   // 98304
    cudaFuncSetAttribute(gemm1_f16_kernel, cudaFuncAttributeMaxDynamicSharedMemorySize, g_smem);
    cudaFuncSetAttribute(gemm2_f16_kernel, cudaFuncAttributeMaxDynamicSharedMemorySize, g_smem);

    prep_w_kernel<<<2048, 256>>>(memw);
    colsum_prep_kernel<<<dim3(8, 128), 256>>>(k);
    kagg_gates_kernel<<<1, 1024>>>(gw, gb, out);
    gemm1_f16_kernel<<<dim3(8, 128), 128, g_smem>>>(v, out);   // launch #4 -> ncu capture
    gemm2_f16_kernel<<<dim3(8, 8, 4), 128, g_smem>>>();
    momentum_prep_kernel<<<256, 256>>>(mom, out);
    weight_prep_kernel<<<256, 256>>>(memw, out);
    final_w_kernel<<<256, 256>>>(out);
}

// round 9
// speedup vs baseline: 6.9979x; 1.0211x over previous
#include <cuda_runtime.h>
#include <cuda_fp16.h>
#include <math.h>
#include <stdint.h>

// Problem constants
#define BROWS 16384
#define D     1024

// Output layout: retrieved (B*D) | loss (1) | new_weight (D*D) | new_momentum (D*D) | gates (3)
#define RET_OFF   0
#define LOSS_OFF  (BROWS * D)
#define W_OFF     (LOSS_OFF + 1)              // odd -> scalar stores only
#define NM_OFF    (W_OFF + D * D)             // odd -> scalar stores only
#define GATES_OFF (NM_OFF + D * D)

#define MEM_MAX_NORM 5.0f
#define TTT_LR 0.005f
#define TWO_OVER_N (2.0f / (float)(BROWS * D))

// ---------------- device scratch (static, no runtime allocation) ----------------
__device__ float g_kagg_part[128][D];
__device__ float g_scalars[8];        // 0:alpha 1:eta 2:theta 4:scale_m 5:scale_w
__device__ float g_loss_part[1024];
__device__ float g_grad_part[4][D * D];   // split-B partials for GEMM2 (16 MB)
__device__ float g_nm_raw[D * D];
__device__ float g_w_raw[D * D];
__device__ float g_norm_part[2][256];
__device__ int   g_ctr[2];
__device__ __half g_k_h[BROWS * D];        // fp16 K, row-major [b][c] (32 MB)
__device__ __half g_w_h[D * D];            // fp16 W, row-major [n][k] (2 MB)
__device__ __half g_kT_h[D * BROWS];       // fp16 K^T [c][b] (32 MB)
__device__ __half g_diffT_h[D * BROWS];    // fp16 (retrieved-V)^T [i][b] (32 MB)

// ================= PTX helpers (family-portable, sm_80+) =================
__device__ __forceinline__ uint32_t pack_half(float a, float b) {
    __half2 h = __floats2half2_rn(a, b);
    return *(uint32_t*)&h;
}
__device__ __forceinline__ void mma_f16(float& c0, float& c1, float& c2, float& c3,
                                        uint32_t a0, uint32_t a1, uint32_t a2, uint32_t a3,
                                        uint32_t b0, uint32_t b1) {
    asm volatile(
        "mma.sync.aligned.m16n8k16.row.col.f32.f16.f16.f32 "
        "{%0,%1,%2,%3}, {%4,%5,%6,%7}, {%8,%9}, {%0,%1,%2,%3};"
        : "+f"(c0), "+f"(c1), "+f"(c2), "+f"(c3)
        : "r"(a0), "r"(a1), "r"(a2), "r"(a3), "r"(b0), "r"(b1));
}
__device__ __forceinline__ void ldsm_x4(uint32_t& r0, uint32_t& r1, uint32_t& r2, uint32_t& r3,
                                        uint32_t addr) {
    asm volatile("ldmatrix.sync.aligned.m8n8.x4.shared.b16 {%0,%1,%2,%3}, [%4];"
                 : "=r"(r0), "=r"(r1), "=r"(r2), "=r"(r3) : "r"(addr));
}
__device__ __forceinline__ uint32_t smem_u32(const void* p) {
    uint32_t a;
    asm("{ .reg .u64 t; cvta.to.shared.u64 t, %1; cvt.u32.u64 %0, t; }" : "=r"(a) : "l"(p));
    return a;
}
__device__ __forceinline__ void cp16(uint32_t dst, const void* src) {
    asm volatile("cp.async.cg.shared.global [%0], [%1], 16;" :: "r"(dst), "l"(src));
}
#define CP_COMMIT() asm volatile("cp.async.commit_group;" ::: "memory")
#define CP_WAIT1()  asm volatile("cp.async.wait_group 1;" ::: "memory")
#define CP_WAIT0()  asm volatile("cp.async.wait_group 0;" ::: "memory")

// K-chunk 64: stage = A(128x64 half = 16KB) + B(16KB) = 32KB = 8192 words
#define STAGE_WORDS 8192
#define B_OFF_WORDS 4096

// ---------------- prep: fp16(W) ----------------
__global__ void prep_w_kernel(const float* __restrict__ W) {
    int e = (blockIdx.x * 256 + threadIdx.x) * 2;
    float2 w2 = *(const float2*)(W + e);
    *(uint32_t*)(&g_w_h[e]) = pack_half(w2.x, w2.y);
}

// ---------------- colsum + fp16(K) + fp16 K^T (smem-tiled transpose) ----------------
__global__ __launch_bounds__(256) void colsum_prep_kernel(const float* __restrict__ K) {
    __shared__ uint32_t st[128 * 64];
    __shared__ float red2[256];
    const int t  = threadIdx.x;
    const int cl = t & 127, rq = t >> 7;
    const int c  = blockIdx.x * 128 + cl;
    const int r0 = blockIdx.y * 128;

    float s = 0.f, prev = 0.f;
    #pragma unroll 4
    for (int i = 0; i < 64; ++i) {
        int r = r0 + rq * 64 + i;
        float kv = K[(size_t)r * D + c];
        s += kv;
        g_k_h[(size_t)r * D + c] = __float2half_rn(kv);
        if (i & 1) {
            int r2 = rq * 32 + (i >> 1);
            st[cl * 64 + (r2 ^ (cl & 31))] = pack_half(prev, kv);
        } else prev = kv;
    }
    red2[t] = s;
    __syncthreads();
    if (t < 128) g_kagg_part[blockIdx.y][blockIdx.x * 128 + t] = red2[t] + red2[t + 128];

    uint32_t* kTw = (uint32_t*)g_kT_h;
    size_t dstbase = ((size_t)(blockIdx.x * 128 + cl) * BROWS + r0) / 2 + rq * 32;
    #pragma unroll
    for (int q4 = 0; q4 < 32; q4 += 4) {
        uint4 vv;
        vv.x = st[cl * 64 + ((rq * 32 + q4 + 0) ^ (cl & 31))];
        vv.y = st[cl * 64 + ((rq * 32 + q4 + 1) ^ (cl & 31))];
        vv.z = st[cl * 64 + ((rq * 32 + q4 + 2) ^ (cl & 31))];
        vv.w = st[cl * 64 + ((rq * 32 + q4 + 3) ^ (cl & 31))];
        *(uint4*)(kTw + dstbase + q4) = vv;
    }
}

// ---------------- fused kagg + gates ----------------
__global__ void kagg_gates_kernel(const float* __restrict__ GW, const float* __restrict__ GB,
                                  float* __restrict__ out) {
    __shared__ float red[1024];
    __shared__ float kag[1024];
    int t = threadIdx.x;
    float s = 0.f;
    #pragma unroll 8
    for (int p = 0; p < 128; ++p) s += g_kagg_part[p][t];
    kag[t] = s * (1.0f / (float)BROWS);
    __syncthreads();
    for (int g = 0; g < 3; ++g) {
        red[t] = kag[t] * GW[g * D + t];
        __syncthreads();
        for (int st = 512; st > 0; st >>= 1) {
            if (t < st) red[t] += red[t + st];
            __syncthreads();
        }
        if (t == 0) {
            float z  = red[0] + GB[g];
            float sg = 1.0f / (1.0f + expf(-z));
            g_scalars[g] = sg;
            out[GATES_OFF + g] = sg;
        }
        __syncthreads();
    }
}

// ======= shared GEMM body pieces (4 warps, 64x64 warp tile, k64 chunks) =======
#define FRAG_SETUP()                                              \
    const int laneRowA = (lane & 7) | (lane & 8);                 \
    const int selA = lane >> 4;                                   \
    const int laneRowB = (lane & 7) | ((lane & 16) >> 1);         \
    const int selB = (lane >> 3) & 1;                             \
    uint32_t offA[4], swA4[4];                                    \
    _Pragma("unroll")                                             \
    for (int mt = 0; mt < 4; ++mt) {                              \
        int row = wm + mt * 16 + laneRowA;                        \
        offA[mt] = row * 128;                                     \
        swA4[mt] = row & 7;                                       \
    }                                                             \
    uint32_t offB[4], swB4[4];                                    \
    _Pragma("unroll")                                             \
    for (int np = 0; np < 4; ++np) {                              \
        int row = wn + np * 16 + laneRowB;                        \
        offB[np] = row * 128;                                     \
        swB4[np] = row & 7;                                       \
    }

#define CHUNK_COMPUTE(abase, bbase)                                                   \
    _Pragma("unroll")                                                                 \
    for (int ks = 0; ks < 4; ++ks) {                                                  \
        const int g0 = ks * 2;                                                        \
        uint32_t a[4][4], b[4][4];                                                    \
        _Pragma("unroll")                                                             \
        for (int mt = 0; mt < 4; ++mt)                                                \
            ldsm_x4(a[mt][0], a[mt][1], a[mt][2], a[mt][3],                           \
                    (abase) + offA[mt] + ((((uint32_t)(g0 + selA)) ^ swA4[mt]) << 4));\
        _Pragma("unroll")                                                             \
        for (int np = 0; np < 4; ++np)                                                \
            ldsm_x4(b[np][0], b[np][1], b[np][2], b[np][3],                           \
                    (bbase) + offB[np] + ((((uint32_t)(g0 + selB)) ^ swB4[np]) << 4));\
        _Pragma("unroll")                                                             \
        for (int mt = 0; mt < 4; ++mt)                                                \
            _Pragma("unroll")                                                         \
            for (int nt = 0; nt < 8; ++nt) {                                          \
                const int np = nt >> 1, lo = (nt & 1) * 2;                            \
                mma_f16(acc[mt][nt][0], acc[mt][nt][1], acc[mt][nt][2], acc[mt][nt][3],\
                        a[mt][0], a[mt][1], a[mt][2], a[mt][3], b[np][lo], b[np][lo + 1]);\
            }                                                                         \
    }

#define STAGE_CHUNK(stagebase, srcA, srcB)                                            \
    _Pragma("unroll")                                                                 \
    for (int it = 0; it < 8; ++it) {                                                  \
        int row = it * 16 + srow;                                                     \
        uint32_t wo = (uint32_t)(row * 32 + ((sg ^ (row & 7)) << 2));                 \
        cp16((stagebase) + wo * 4, (srcA) + (size_t)row * srcStrideA);                \
        cp16((stagebase) + (B_OFF_WORDS + wo) * 4, (srcB) + (size_t)row * srcStrideB);\
    }

// ---------------- GEMM1 (fp16, 64x64 warp tile): retrieved = K @ W^T ----------------
__global__ __launch_bounds__(128, 2) void gemm1_f16_kernel(
    const float* __restrict__ V, float* __restrict__ out) {
    extern __shared__ uint32_t sm1[];
    __shared__ float wred[4];
    const uint32_t sb = smem_u32(sm1);

    const int tid = threadIdx.x;
    const int warp = tid >> 5, lane = tid & 31;
    const int t4 = lane >> 2, tm4 = lane & 3;
    const int n0 = blockIdx.x * 128;
    const int m0 = blockIdx.y * 128;
    const int wm = (warp >> 1) * 64;
    const int wn = (warp & 1) * 64;

    float acc[4][8][4];
    #pragma unroll
    for (int i = 0; i < 4; ++i)
        #pragma unroll
        for (int j = 0; j < 8; ++j)
            #pragma unroll
            for (int r = 0; r < 4; ++r) acc[i][j][r] = 0.f;

    FRAG_SETUP();

    const int srow = tid >> 3, sg = tid & 7;
    const size_t srcStrideA = D, srcStrideB = D;
    const __half* gA = g_k_h + (size_t)m0 * D + sg * 8;
    const __half* gB = g_w_h + (size_t)n0 * D + sg * 8;

    #pragma unroll
    for (int s = 0; s < 2; ++s) {
        STAGE_CHUNK(sb + s * (STAGE_WORDS * 4), gA + s * 64, gB + s * 64);
        CP_COMMIT();
    }

    const int NCH = D / 64;   // 16 chunks
    for (int c = 0; c < NCH; ++c) {
        const int buf = c % 3;
        CP_WAIT1();
        __syncthreads();
        if (c + 2 < NCH) {
            const int nb = (c + 2) % 3;
            STAGE_CHUNK(sb + nb * (STAGE_WORDS * 4), gA + (c + 2) * 64, gB + (c + 2) * 64);
        }
        CP_COMMIT();

        const uint32_t abase = sb + buf * (STAGE_WORDS * 4);
        const uint32_t bbase = abase + B_OFF_WORDS * 4;
        CHUNK_COMPUTE(abase, bbase);
    }

    // ---- Epilogue ----
    CP_WAIT0();
    __syncthreads();   // all warps done reading pipeline smem; safe to reuse for repack

    // Phase A: retrieved (fp32, gmem) + loss partial + diff pairs -> smem [cc/2][136]
    float lsum = 0.f;
    #pragma unroll
    for (int mt = 0; mt < 4; ++mt) {
        #pragma unroll
        for (int nt = 0; nt < 8; ++nt) {
            int r   = wm + mt * 16 + t4;          // local b-row
            int ccl = wn + nt * 8 + 2 * tm4;      // local i-col (even)
            int rg = m0 + r, cg = n0 + ccl;
            size_t e0 = (size_t)rg * D + cg;
            size_t e1 = (size_t)(rg + 8) * D + cg;
            float2 v0 = *(const float2*)(V + e0);
            float2 v1 = *(const float2*)(V + e1);
            float2 c0 = make_float2(acc[mt][nt][0], acc[mt][nt][1]);
            float2 c1 = make_float2(acc[mt][nt][2], acc[mt][nt][3]);
            *(float2*)(out + RET_OFF + e0) = c0;
            *(float2*)(out + RET_OFF + e1) = c1;
            float d0 = c0.x - v0.x, d1 = c0.y - v0.y;
            float d2 = c1.x - v1.x, d3 = c1.y - v1.y;
            int wrow = ccl >> 1;
            sm1[wrow * 136 + r]     = pack_half(d0, d1);   // (i=ccl lo, i=ccl+1 hi) @ b=r
            sm1[wrow * 136 + r + 8] = pack_half(d2, d3);   // @ b=r+8
            lsum += d0 * d0 + d1 * d1 + d2 * d2 + d3 * d3;
        }
    }
    #pragma unroll
    for (int o = 16; o > 0; o >>= 1) lsum += __shfl_xor_sync(0xffffffffu, lsum, o);
    if (lane == 0) wred[warp] = lsum;
    __syncthreads();

    // Phase B: coalesced diffT writes (each warp handles rows warp, warp+4, ...)
    for (int row = warp; row < 128; row += 4) {
        uint4 w = *(uint4*)&sm1[(row >> 1) * 136 + lane * 4];
        uint32_t sel = (row & 1) ? 0x7632u : 0x5410u;
        uint32_t lo = __byte_perm(w.x, w.y, sel);
        uint32_t hi = __byte_perm(w.z, w.w, sel);
        *(uint2*)&g_diffT_h[(size_t)(n0 + row) * BROWS + m0 + lane * 4] = make_uint2(lo, hi);
    }

    if (tid == 0)
        g_loss_part[blockIdx.y * 8 + blockIdx.x] = wred[0] + wred[1] + wred[2] + wred[3];
}

// ---------------- GEMM2 (fp16, 64x64 warp tile): grad_part[z] = diffT @ kT^T ----------------
__global__ __launch_bounds__(128, 2) void gemm2_f16_kernel() {
    extern __shared__ uint32_t sm2[];
    const uint32_t sb = smem_u32(sm2);

    const int tid = threadIdx.x;
    const int warp = tid >> 5, lane = tid & 31;
    const int t4 = lane >> 2, tm4 = lane & 3;
    const int j0 = blockIdx.x * 128;
    const int i0 = blockIdx.y * 128;
    const int z  = blockIdx.z;
    const int b0z = z * (BROWS / 4);
    const int wm = (warp >> 1) * 64;   // i
    const int wn = (warp & 1) * 64;    // j

    float acc[4][8][4];
    #pragma unroll
    for (int i = 0; i < 4; ++i)
        #pragma unroll
        for (int j = 0; j < 8; ++j)
            #pragma unroll
            for (int r = 0; r < 4; ++r) acc[i][j][r] = 0.f;

    FRAG_SETUP();

    const int srow = tid >> 3, sg = tid & 7;
    const size_t srcStrideA = BROWS, srcStrideB = BROWS;
    const __half* gA = g_diffT_h + (size_t)i0 * BROWS + b0z + sg * 8;
    const __half* gB = g_kT_h    + (size_t)j0 * BROWS + b0z + sg * 8;

    #pragma unroll
    for (int s = 0; s < 2; ++s) {
        STAGE_CHUNK(sb + s * (STAGE_WORDS * 4), gA + s * 64, gB + s * 64);
        CP_COMMIT();
    }

    const int NCH = (BROWS / 4) / 64;   // 64 chunks
    for (int c = 0; c < NCH; ++c) {
        const int buf = c % 3;
        CP_WAIT1();
        __syncthreads();
        if (c + 2 < NCH) {
            const int nb = (c + 2) % 3;
            STAGE_CHUNK(sb + nb * (STAGE_WORDS * 4), gA + (c + 2) * 64, gB + (c + 2) * 64);
        }
        CP_COMMIT();

        const uint32_t abase = sb + buf * (STAGE_WORDS * 4);
        const uint32_t bbase = abase + B_OFF_WORDS * 4;
        CHUNK_COMPUTE(abase, bbase);
    }

    float* gp = g_grad_part[z];
    #pragma unroll
    for (int mt = 0; mt < 4; ++mt) {
        #pragma unroll
        for (int nt = 0; nt < 8; ++nt) {
            int r  = i0 + wm + mt * 16 + t4;
            int cc = j0 + wn + nt * 8 + 2 * tm4;
            *(float2*)(gp + (size_t)r * D + cc)       = make_float2(acc[mt][nt][0], acc[mt][nt][1]);
            *(float2*)(gp + (size_t)(r + 8) * D + cc) = make_float2(acc[mt][nt][2], acc[mt][nt][3]);
        }
    }
}

// ---------------- momentum (+ loss finalize in block 0, + fused norm) ----------------
__global__ void momentum_prep_kernel(const float* __restrict__ MOM, float* __restrict__ out) {
    __shared__ float red[256];
    __shared__ int amLast;
    int tid = threadIdx.x;
    int t = blockIdx.x * 256 + tid;

    if (blockIdx.x == 0) {   // loss reduce (independent work)
        float ls = g_loss_part[tid] + g_loss_part[tid + 256] +
                   g_loss_part[tid + 512] + g_loss_part[tid + 768];
        red[tid] = ls;
        __syncthreads();
        for (int s = 128; s > 0; s >>= 1) {
            if (tid < s) red[tid] += red[tid + s];
            __syncthreads();
        }
        if (tid == 0) out[LOSS_OFF] = red[0] / (float)(BROWS * D);
        __syncthreads();
    }

    float eta = g_scalars[1], theta = g_scalars[2];
    float lr_th = TTT_LR * theta;
    float nsum = 0.f;
    #pragma unroll
    for (int it = 0; it < 16; ++it) {
        int e = t + it * 65536;
        float g = (g_grad_part[0][e] + g_grad_part[1][e] +
                   g_grad_part[2][e] + g_grad_part[3][e]) * TWO_OVER_N;
        float gc = fminf(1.0f, fmaxf(-1.0f, g));
        float nm = eta * MOM[e] - lr_th * gc;
        g_nm_raw[e] = nm;
        nsum += nm * nm;
    }
    red[tid] = nsum;
    __syncthreads();
    for (int s = 128; s > 0; s >>= 1) {
        if (tid < s) red[tid] += red[tid + s];
        __syncthreads();
    }
    if (tid == 0) g_norm_part[0][blockIdx.x] = red[0];
    __threadfence();
    if (tid == 0) amLast = (atomicAdd(&g_ctr[0], 1) == 255);
    __syncthreads();
    if (amLast) {
        red[tid] = g_norm_part[0][tid];
        __syncthreads();
        for (int s = 128; s > 0; s >>= 1) {
            if (tid < s) red[tid] += red[tid + s];
            __syncthreads();
        }
        if (tid == 0) {
            float n = sqrtf(red[0]);
            g_scalars[4] = (n > MEM_MAX_NORM) ? (MEM_MAX_NORM / (n + 1e-8f)) : 1.0f;
            g_ctr[0] = 0;
        }
    }
}

// ---------------- weight (+ fused norm) ----------------
__global__ void weight_prep_kernel(const float* __restrict__ MW, float* __restrict__ out) {
    __shared__ float red[256];
    __shared__ int amLast;
    int tid = threadIdx.x;
    int t = blockIdx.x * 256 + tid;
    float alpha = g_scalars[0];
    float sm = g_scalars[4];
    float one_m_a = 1.0f - alpha;
    float wsum = 0.f;
    #pragma unroll
    for (int it = 0; it < 16; ++it) {
        int e = t + it * 65536;
        float nm = g_nm_raw[e] * sm;
        out[NM_OFF + e] = nm;
        float w = one_m_a * MW[e] + nm;
        g_w_raw[e] = w;
        wsum += w * w;
    }
    red[tid] = wsum;
    __syncthreads();
    for (int s = 128; s > 0; s >>= 1) {
        if (tid < s) red[tid] += red[tid + s];
        __syncthreads();
    }
    if (tid == 0) g_norm_part[1][blockIdx.x] = red[0];
    __threadfence();
    if (tid == 0) amLast = (atomicAdd(&g_ctr[1], 1) == 255);
    __syncthreads();
    if (amLast) {
        red[tid] = g_norm_part[1][tid];
        __syncthreads();
        for (int s = 128; s > 0; s >>= 1) {
            if (tid < s) red[tid] += red[tid + s];
            __syncthreads();
        }
        if (tid == 0) {
            float n = sqrtf(red[0]);
            g_scalars[5] = (n > MEM_MAX_NORM) ? (MEM_MAX_NORM / (n + 1e-8f)) : 1.0f;
            g_ctr[1] = 0;
        }
    }
}

__global__ void final_w_kernel(float* __restrict__ out) {
    int t = blockIdx.x * 256 + threadIdx.x;
    float sw = g_scalars[5];
    #pragma unroll
    for (int it = 0; it < 16; ++it) {
        int e = t + it * 65536;
        out[W_OFF + e] = g_w_raw[e] * sw;
    }
}

// ---------------- launch ----------------
extern "C" void kernel_launch(void* const* d_in, const int* in_sizes, int n_in,
                              void* d_out, int out_size) {
    const float* k    = (const float*)d_in[0];
    const float* v    = (const float*)d_in[1];
    const float* memw = (const float*)d_in[2];
    const float* gw   = (const float*)d_in[3];
    const float* gb   = (const float*)d_in[4];
    const float* mom  = (const float*)d_in[5];
    float* out = (float*)d_out;

    const int g_smem = 3 * STAGE_WORDS * 4;   // 98304
    cudaFuncSetAttribute(gemm1_f16_kernel, cudaFuncAttributeMaxDynamicSharedMemorySize, g_smem);
    cudaFuncSetAttribute(gemm2_f16_kernel, cudaFuncAttributeMaxDynamicSharedMemorySize, g_smem);

    prep_w_kernel<<<2048, 256>>>(memw);
    colsum_prep_kernel<<<dim3(8, 128), 256>>>(k);
    kagg_gates_kernel<<<1, 1024>>>(gw, gb, out);
    gemm1_f16_kernel<<<dim3(8, 128), 128, g_smem>>>(v, out);   // launch #4 -> ncu capture
    gemm2_f16_kernel<<<dim3(8, 8, 4), 128, g_smem>>>();
    momentum_prep_kernel<<<256, 256>>>(mom, out);
    weight_prep_kernel<<<256, 256>>>(memw, out);
    final_w_kernel<<<256, 256>>>(out);
}

// round 10
// speedup vs baseline: 7.0120x; 1.0020x over previous
#include <cuda_runtime.h>
#include <cuda_fp16.h>
#include <math.h>
#include <stdint.h>

// Problem constants
#define BROWS 16384
#define D     1024

// Output layout: retrieved (B*D) | loss (1) | new_weight (D*D) | new_momentum (D*D) | gates (3)
#define RET_OFF   0
#define LOSS_OFF  (BROWS * D)
#define W_OFF     (LOSS_OFF + 1)              // odd -> scalar stores only
#define NM_OFF    (W_OFF + D * D)             // odd -> scalar stores only
#define GATES_OFF (NM_OFF + D * D)

#define MEM_MAX_NORM 5.0f
#define TTT_LR 0.005f
#define TWO_OVER_N (2.0f / (float)(BROWS * D))

// ---------------- device scratch (static, no runtime allocation) ----------------
__device__ float g_kagg_part[128][D];
__device__ float g_scalars[8];        // 0:alpha 1:eta 2:theta 4:scale_m 5:scale_w
__device__ float g_loss_part[1024];
__device__ float g_grad_part[4][D * D];   // split-B partials for GEMM2 (16 MB)
__device__ float g_nm_raw[D * D];
__device__ float g_w_raw[D * D];
__device__ float g_norm_part[2][256];
__device__ int   g_ctr[2];
__device__ __half g_k_h[BROWS * D];        // fp16 K, row-major [b][c] (32 MB)
__device__ __half g_w_h[D * D];            // fp16 W, row-major [n][k] (2 MB)
__device__ __half g_kT_h[D * BROWS];       // fp16 K^T [c][b] (32 MB)
__device__ __half g_diffT_h[D * BROWS];    // fp16 (retrieved-V)^T [i][b] (32 MB)

// ================= PTX helpers (family-portable, sm_80+) =================
__device__ __forceinline__ uint32_t pack_half(float a, float b) {
    __half2 h = __floats2half2_rn(a, b);
    return *(uint32_t*)&h;
}
__device__ __forceinline__ void mma_f16(float& c0, float& c1, float& c2, float& c3,
                                        uint32_t a0, uint32_t a1, uint32_t a2, uint32_t a3,
                                        uint32_t b0, uint32_t b1) {
    asm volatile(
        "mma.sync.aligned.m16n8k16.row.col.f32.f16.f16.f32 "
        "{%0,%1,%2,%3}, {%4,%5,%6,%7}, {%8,%9}, {%0,%1,%2,%3};"
        : "+f"(c0), "+f"(c1), "+f"(c2), "+f"(c3)
        : "r"(a0), "r"(a1), "r"(a2), "r"(a3), "r"(b0), "r"(b1));
}
__device__ __forceinline__ void ldsm_x4(uint32_t& r0, uint32_t& r1, uint32_t& r2, uint32_t& r3,
                                        uint32_t addr) {
    asm volatile("ldmatrix.sync.aligned.m8n8.x4.shared.b16 {%0,%1,%2,%3}, [%4];"
                 : "=r"(r0), "=r"(r1), "=r"(r2), "=r"(r3) : "r"(addr));
}
__device__ __forceinline__ uint32_t smem_u32(const void* p) {
    uint32_t a;
    asm("{ .reg .u64 t; cvta.to.shared.u64 t, %1; cvt.u32.u64 %0, t; }" : "=r"(a) : "l"(p));
    return a;
}
__device__ __forceinline__ void cp16(uint32_t dst, const void* src) {
    asm volatile("cp.async.cg.shared.global [%0], [%1], 16;" :: "r"(dst), "l"(src));
}
#define CP_COMMIT() asm volatile("cp.async.commit_group;" ::: "memory")
#define CP_WAIT1()  asm volatile("cp.async.wait_group 1;" ::: "memory")
#define CP_WAIT0()  asm volatile("cp.async.wait_group 0;" ::: "memory")

// K-chunk 64: stage = A(128x64 half = 16KB) + B(16KB) = 32KB = 8192 words
#define STAGE_WORDS 8192
#define B_OFF_WORDS 4096

// ---------------- prep: fp16(W) ----------------
__global__ void prep_w_kernel(const float* __restrict__ W) {
    int e = (blockIdx.x * 256 + threadIdx.x) * 2;
    float2 w2 = *(const float2*)(W + e);
    *(uint32_t*)(&g_w_h[e]) = pack_half(w2.x, w2.y);
}

// ---------------- colsum + fp16(K) + fp16 K^T (smem-tiled transpose) ----------------
__global__ __launch_bounds__(256) void colsum_prep_kernel(const float* __restrict__ K) {
    __shared__ uint32_t st[128 * 64];
    __shared__ float red2[256];
    const int t  = threadIdx.x;
    const int cl = t & 127, rq = t >> 7;
    const int c  = blockIdx.x * 128 + cl;
    const int r0 = blockIdx.y * 128;

    float s = 0.f, prev = 0.f;
    #pragma unroll 4
    for (int i = 0; i < 64; ++i) {
        int r = r0 + rq * 64 + i;
        float kv = K[(size_t)r * D + c];
        s += kv;
        g_k_h[(size_t)r * D + c] = __float2half_rn(kv);
        if (i & 1) {
            int r2 = rq * 32 + (i >> 1);
            st[cl * 64 + (r2 ^ (cl & 31))] = pack_half(prev, kv);
        } else prev = kv;
    }
    red2[t] = s;
    __syncthreads();
    if (t < 128) g_kagg_part[blockIdx.y][blockIdx.x * 128 + t] = red2[t] + red2[t + 128];

    uint32_t* kTw = (uint32_t*)g_kT_h;
    size_t dstbase = ((size_t)(blockIdx.x * 128 + cl) * BROWS + r0) / 2 + rq * 32;
    #pragma unroll
    for (int q4 = 0; q4 < 32; q4 += 4) {
        uint4 vv;
        vv.x = st[cl * 64 + ((rq * 32 + q4 + 0) ^ (cl & 31))];
        vv.y = st[cl * 64 + ((rq * 32 + q4 + 1) ^ (cl & 31))];
        vv.z = st[cl * 64 + ((rq * 32 + q4 + 2) ^ (cl & 31))];
        vv.w = st[cl * 64 + ((rq * 32 + q4 + 3) ^ (cl & 31))];
        *(uint4*)(kTw + dstbase + q4) = vv;
    }
}

// ---------------- fused kagg + gates ----------------
__global__ void kagg_gates_kernel(const float* __restrict__ GW, const float* __restrict__ GB,
                                  float* __restrict__ out) {
    __shared__ float red[1024];
    __shared__ float kag[1024];
    int t = threadIdx.x;
    float s = 0.f;
    #pragma unroll 8
    for (int p = 0; p < 128; ++p) s += g_kagg_part[p][t];
    kag[t] = s * (1.0f / (float)BROWS);
    __syncthreads();
    for (int g = 0; g < 3; ++g) {
        red[t] = kag[t] * GW[g * D + t];
        __syncthreads();
        for (int st = 512; st > 0; st >>= 1) {
            if (t < st) red[t] += red[t + st];
            __syncthreads();
        }
        if (t == 0) {
            float z  = red[0] + GB[g];
            float sg = 1.0f / (1.0f + expf(-z));
            g_scalars[g] = sg;
            out[GATES_OFF + g] = sg;
        }
        __syncthreads();
    }
}

// ======= shared GEMM body pieces (4 warps, 64x64 warp tile, k64 chunks) =======
#define FRAG_SETUP()                                              \
    const int laneRowA = (lane & 7) | (lane & 8);                 \
    const int selA = lane >> 4;                                   \
    const int laneRowB = (lane & 7) | ((lane & 16) >> 1);         \
    const int selB = (lane >> 3) & 1;                             \
    uint32_t offA[4], swA4[4];                                    \
    _Pragma("unroll")                                             \
    for (int mt = 0; mt < 4; ++mt) {                              \
        int row = wm + mt * 16 + laneRowA;                        \
        offA[mt] = row * 128;                                     \
        swA4[mt] = row & 7;                                       \
    }                                                             \
    uint32_t offB[4], swB4[4];                                    \
    _Pragma("unroll")                                             \
    for (int np = 0; np < 4; ++np) {                              \
        int row = wn + np * 16 + laneRowB;                        \
        offB[np] = row * 128;                                     \
        swB4[np] = row & 7;                                       \
    }                                                             \
    uint32_t afr[2][4][4], bfr[2][4][4];

// fragment load for k-group g0 into register buffer `buf`
#define LDFR(abase, bbase, buf, g0)                                                   \
    do {                                                                              \
        _Pragma("unroll")                                                             \
        for (int mt = 0; mt < 4; ++mt)                                                \
            ldsm_x4(afr[buf][mt][0], afr[buf][mt][1], afr[buf][mt][2], afr[buf][mt][3],\
                    (abase) + offA[mt] + ((((uint32_t)((g0) + selA)) ^ swA4[mt]) << 4));\
        _Pragma("unroll")                                                             \
        for (int np = 0; np < 4; ++np)                                                \
            ldsm_x4(bfr[buf][np][0], bfr[buf][np][1], bfr[buf][np][2], bfr[buf][np][3],\
                    (bbase) + offB[np] + ((((uint32_t)((g0) + selB)) ^ swB4[np]) << 4));\
    } while (0)

// register-pipelined chunk: load ks+1 frags before computing ks
#define CHUNK_COMPUTE(abase, bbase)                                                   \
    do {                                                                              \
        LDFR(abase, bbase, 0, 0);                                                     \
        _Pragma("unroll")                                                             \
        for (int ks = 0; ks < 4; ++ks) {                                              \
            const int cur = ks & 1;                                                   \
            if (ks < 3) LDFR(abase, bbase, (ks + 1) & 1, (ks + 1) * 2);               \
            _Pragma("unroll")                                                         \
            for (int mt = 0; mt < 4; ++mt)                                            \
                _Pragma("unroll")                                                     \
                for (int nt = 0; nt < 8; ++nt) {                                      \
                    const int np = nt >> 1, lo = (nt & 1) * 2;                        \
                    mma_f16(acc[mt][nt][0], acc[mt][nt][1], acc[mt][nt][2], acc[mt][nt][3],\
                            afr[cur][mt][0], afr[cur][mt][1], afr[cur][mt][2], afr[cur][mt][3],\
                            bfr[cur][np][lo], bfr[cur][np][lo + 1]);                  \
                }                                                                     \
        }                                                                             \
    } while (0)

#define STAGE_CHUNK(stagebase, srcA, srcB)                                            \
    _Pragma("unroll")                                                                 \
    for (int it = 0; it < 8; ++it) {                                                  \
        int row = it * 16 + srow;                                                     \
        uint32_t wo = (uint32_t)(row * 32 + ((sg ^ (row & 7)) << 2));                 \
        cp16((stagebase) + wo * 4, (srcA) + (size_t)row * srcStrideA);                \
        cp16((stagebase) + (B_OFF_WORDS + wo) * 4, (srcB) + (size_t)row * srcStrideB);\
    }

// ---------------- GEMM1 (fp16, 64x64 warp tile): retrieved = K @ W^T ----------------
__global__ __launch_bounds__(128, 2) void gemm1_f16_kernel(
    const float* __restrict__ V, float* __restrict__ out) {
    extern __shared__ uint32_t sm1[];
    __shared__ float wred[4];
    const uint32_t sb = smem_u32(sm1);

    const int tid = threadIdx.x;
    const int warp = tid >> 5, lane = tid & 31;
    const int t4 = lane >> 2, tm4 = lane & 3;
    const int n0 = blockIdx.x * 128;
    const int m0 = blockIdx.y * 128;
    const int wm = (warp >> 1) * 64;
    const int wn = (warp & 1) * 64;

    float acc[4][8][4];
    #pragma unroll
    for (int i = 0; i < 4; ++i)
        #pragma unroll
        for (int j = 0; j < 8; ++j)
            #pragma unroll
            for (int r = 0; r < 4; ++r) acc[i][j][r] = 0.f;

    FRAG_SETUP();

    const int srow = tid >> 3, sg = tid & 7;
    const size_t srcStrideA = D, srcStrideB = D;
    const __half* gA = g_k_h + (size_t)m0 * D + sg * 8;
    const __half* gB = g_w_h + (size_t)n0 * D + sg * 8;

    #pragma unroll
    for (int s = 0; s < 2; ++s) {
        STAGE_CHUNK(sb + s * (STAGE_WORDS * 4), gA + s * 64, gB + s * 64);
        CP_COMMIT();
    }

    const int NCH = D / 64;   // 16 chunks
    for (int c = 0; c < NCH; ++c) {
        const int buf = c % 3;
        CP_WAIT1();
        __syncthreads();
        if (c + 2 < NCH) {
            const int nb = (c + 2) % 3;
            STAGE_CHUNK(sb + nb * (STAGE_WORDS * 4), gA + (c + 2) * 64, gB + (c + 2) * 64);
        }
        CP_COMMIT();

        const uint32_t abase = sb + buf * (STAGE_WORDS * 4);
        const uint32_t bbase = abase + B_OFF_WORDS * 4;
        CHUNK_COMPUTE(abase, bbase);
    }

    // ---- Epilogue ----
    CP_WAIT0();
    __syncthreads();   // all warps done reading pipeline smem; safe to reuse for repack

    // Phase A: retrieved (fp32, gmem) + loss partial + diff pairs -> smem [cc/2][136]
    float lsum = 0.f;
    #pragma unroll
    for (int mt = 0; mt < 4; ++mt) {
        #pragma unroll
        for (int nt = 0; nt < 8; ++nt) {
            int r   = wm + mt * 16 + t4;          // local b-row
            int ccl = wn + nt * 8 + 2 * tm4;      // local i-col (even)
            int rg = m0 + r, cg = n0 + ccl;
            size_t e0 = (size_t)rg * D + cg;
            size_t e1 = (size_t)(rg + 8) * D + cg;
            float2 v0 = *(const float2*)(V + e0);
            float2 v1 = *(const float2*)(V + e1);
            float2 c0 = make_float2(acc[mt][nt][0], acc[mt][nt][1]);
            float2 c1 = make_float2(acc[mt][nt][2], acc[mt][nt][3]);
            *(float2*)(out + RET_OFF + e0) = c0;
            *(float2*)(out + RET_OFF + e1) = c1;
            float d0 = c0.x - v0.x, d1 = c0.y - v0.y;
            float d2 = c1.x - v1.x, d3 = c1.y - v1.y;
            int wrow = ccl >> 1;
            sm1[wrow * 136 + r]     = pack_half(d0, d1);   // (i=ccl lo, i=ccl+1 hi) @ b=r
            sm1[wrow * 136 + r + 8] = pack_half(d2, d3);   // @ b=r+8
            lsum += d0 * d0 + d1 * d1 + d2 * d2 + d3 * d3;
        }
    }
    #pragma unroll
    for (int o = 16; o > 0; o >>= 1) lsum += __shfl_xor_sync(0xffffffffu, lsum, o);
    if (lane == 0) wred[warp] = lsum;
    __syncthreads();

    // Phase B: coalesced diffT writes (each warp handles rows warp, warp+4, ...)
    for (int row = warp; row < 128; row += 4) {
        uint4 w = *(uint4*)&sm1[(row >> 1) * 136 + lane * 4];
        uint32_t sel = (row & 1) ? 0x7632u : 0x5410u;
        uint32_t lo = __byte_perm(w.x, w.y, sel);
        uint32_t hi = __byte_perm(w.z, w.w, sel);
        *(uint2*)&g_diffT_h[(size_t)(n0 + row) * BROWS + m0 + lane * 4] = make_uint2(lo, hi);
    }

    if (tid == 0)
        g_loss_part[blockIdx.y * 8 + blockIdx.x] = wred[0] + wred[1] + wred[2] + wred[3];
}

// ---------------- GEMM2 (fp16, 64x64 warp tile): grad_part[z] = diffT @ kT^T ----------------
__global__ __launch_bounds__(128, 2) void gemm2_f16_kernel() {
    extern __shared__ uint32_t sm2[];
    const uint32_t sb = smem_u32(sm2);

    const int tid = threadIdx.x;
    const int warp = tid >> 5, lane = tid & 31;
    const int t4 = lane >> 2, tm4 = lane & 3;
    const int j0 = blockIdx.x * 128;
    const int i0 = blockIdx.y * 128;
    const int z  = blockIdx.z;
    const int b0z = z * (BROWS / 4);
    const int wm = (warp >> 1) * 64;   // i
    const int wn = (warp & 1) * 64;    // j

    float acc[4][8][4];
    #pragma unroll
    for (int i = 0; i < 4; ++i)
        #pragma unroll
        for (int j = 0; j < 8; ++j)
            #pragma unroll
            for (int r = 0; r < 4; ++r) acc[i][j][r] = 0.f;

    FRAG_SETUP();

    const int srow = tid >> 3, sg = tid & 7;
    const size_t srcStrideA = BROWS, srcStrideB = BROWS;
    const __half* gA = g_diffT_h + (size_t)i0 * BROWS + b0z + sg * 8;
    const __half* gB = g_kT_h    + (size_t)j0 * BROWS + b0z + sg * 8;

    #pragma unroll
    for (int s = 0; s < 2; ++s) {
        STAGE_CHUNK(sb + s * (STAGE_WORDS * 4), gA + s * 64, gB + s * 64);
        CP_COMMIT();
    }

    const int NCH = (BROWS / 4) / 64;   // 64 chunks
    for (int c = 0; c < NCH; ++c) {
        const int buf = c % 3;
        CP_WAIT1();
        __syncthreads();
        if (c + 2 < NCH) {
            const int nb = (c + 2) % 3;
            STAGE_CHUNK(sb + nb * (STAGE_WORDS * 4), gA + (c + 2) * 64, gB + (c + 2) * 64);
        }
        CP_COMMIT();

        const uint32_t abase = sb + buf * (STAGE_WORDS * 4);
        const uint32_t bbase = abase + B_OFF_WORDS * 4;
        CHUNK_COMPUTE(abase, bbase);
    }

    float* gp = g_grad_part[z];
    #pragma unroll
    for (int mt = 0; mt < 4; ++mt) {
        #pragma unroll
        for (int nt = 0; nt < 8; ++nt) {
            int r  = i0 + wm + mt * 16 + t4;
            int cc = j0 + wn + nt * 8 + 2 * tm4;
            *(float2*)(gp + (size_t)r * D + cc)       = make_float2(acc[mt][nt][0], acc[mt][nt][1]);
            *(float2*)(gp + (size_t)(r + 8) * D + cc) = make_float2(acc[mt][nt][2], acc[mt][nt][3]);
        }
    }
}

// ---------------- momentum (+ loss finalize in block 0, + fused norm) ----------------
__global__ void momentum_prep_kernel(const float* __restrict__ MOM, float* __restrict__ out) {
    __shared__ float red[256];
    __shared__ int amLast;
    int tid = threadIdx.x;
    int t = blockIdx.x * 256 + tid;

    if (blockIdx.x == 0) {   // loss reduce (independent work)
        float ls = g_loss_part[tid] + g_loss_part[tid + 256] +
                   g_loss_part[tid + 512] + g_loss_part[tid + 768];
        red[tid] = ls;
        __syncthreads();
        for (int s = 128; s > 0; s >>= 1) {
            if (tid < s) red[tid] += red[tid + s];
            __syncthreads();
        }
        if (tid == 0) out[LOSS_OFF] = red[0] / (float)(BROWS * D);
        __syncthreads();
    }

    float eta = g_scalars[1], theta = g_scalars[2];
    float lr_th = TTT_LR * theta;
    float nsum = 0.f;
    #pragma unroll
    for (int it = 0; it < 16; ++it) {
        int e = t + it * 65536;
        float g = (g_grad_part[0][e] + g_grad_part[1][e] +
                   g_grad_part[2][e] + g_grad_part[3][e]) * TWO_OVER_N;
        float gc = fminf(1.0f, fmaxf(-1.0f, g));
        float nm = eta * MOM[e] - lr_th * gc;
        g_nm_raw[e] = nm;
        nsum += nm * nm;
    }
    red[tid] = nsum;
    __syncthreads();
    for (int s = 128; s > 0; s >>= 1) {
        if (tid < s) red[tid] += red[tid + s];
        __syncthreads();
    }
    if (tid == 0) g_norm_part[0][blockIdx.x] = red[0];
    __threadfence();
    if (tid == 0) amLast = (atomicAdd(&g_ctr[0], 1) == 255);
    __syncthreads();
    if (amLast) {
        red[tid] = g_norm_part[0][tid];
        __syncthreads();
        for (int s = 128; s > 0; s >>= 1) {
            if (tid < s) red[tid] += red[tid + s];
            __syncthreads();
        }
        if (tid == 0) {
            float n = sqrtf(red[0]);
            g_scalars[4] = (n > MEM_MAX_NORM) ? (MEM_MAX_NORM / (n + 1e-8f)) : 1.0f;
            g_ctr[0] = 0;
        }
    }
}

// ---------------- weight (+ fused norm) ----------------
__global__ void weight_prep_kernel(const float* __restrict__ MW, float* __restrict__ out) {
    __shared__ float red[256];
    __shared__ int amLast;
    int tid = threadIdx.x;
    int t = blockIdx.x * 256 + tid;
    float alpha = g_scalars[0];
    float sm = g_scalars[4];
    float one_m_a = 1.0f - alpha;
    float wsum = 0.f;
    #pragma unroll
    for (int it = 0; it < 16; ++it) {
        int e = t + it * 65536;
        float nm = g_nm_raw[e] * sm;
        out[NM_OFF + e] = nm;
        float w = one_m_a * MW[e] + nm;
        g_w_raw[e] = w;
        wsum += w * w;
    }
    red[tid] = wsum;
    __syncthreads();
    for (int s = 128; s > 0; s >>= 1) {
        if (tid < s) red[tid] += red[tid + s];
        __syncthreads();
    }
    if (tid == 0) g_norm_part[1][blockIdx.x] = red[0];
    __threadfence();
    if (tid == 0) amLast = (atomicAdd(&g_ctr[1], 1) == 255);
    __syncthreads();
    if (amLast) {
        red[tid] = g_norm_part[1][tid];
        __syncthreads();
        for (int s = 128; s > 0; s >>= 1) {
            if (tid < s) red[tid] += red[tid + s];
            __syncthreads();
        }
        if (tid == 0) {
            float n = sqrtf(red[0]);
            g_scalars[5] = (n > MEM_MAX_NORM) ? (MEM_MAX_NORM / (n + 1e-8f)) : 1.0f;
            g_ctr[1] = 0;
        }
    }
}

__global__ void final_w_kernel(float* __restrict__ out) {
    int t = blockIdx.x * 256 + threadIdx.x;
    float sw = g_scalars[5];
    #pragma unroll
    for (int it = 0; it < 16; ++it) {
        int e = t + it * 65536;
        out[W_OFF + e] = g_w_raw[e] * sw;
    }
}

// ---------------- launch ----------------
extern "C" void kernel_launch(void* const* d_in, const int* in_sizes, int n_in,
                              void* d_out, int out_size) {
    const float* k    = (const float*)d_in[0];
    const float* v    = (const float*)d_in[1];
    const float* memw = (const float*)d_in[2];
    const float* gw   = (const float*)d_in[3];
    const float* gb   = (const float*)d_in[4];
    const float* mom  = (const float*)d_in[5];
    float* out = (float*)d_out;

    const int g_smem = 3 * STAGE_WORDS * 4;   // 98304
    cudaFuncSetAttribute(gemm1_f16_kernel, cudaFuncAttributeMaxDynamicSharedMemorySize, g_smem);
    cudaFuncSetAttribute(gemm2_f16_kernel, cudaFuncAttributeMaxDynamicSharedMemorySize, g_smem);

    prep_w_kernel<<<2048, 256>>>(memw);
    colsum_prep_kernel<<<dim3(8, 128), 256>>>(k);
    kagg_gates_kernel<<<1, 1024>>>(gw, gb, out);
    gemm1_f16_kernel<<<dim3(8, 128), 128, g_smem>>>(v, out);   // launch #4 -> ncu capture
    gemm2_f16_kernel<<<dim3(8, 8, 4), 128, g_smem>>>();
    momentum_prep_kernel<<<256, 256>>>(mom, out);
    weight_prep_kernel<<<256, 256>>>(memw, out);
    final_w_kernel<<<256, 256>>>(out);
}

// round 11
// speedup vs baseline: 7.0652x; 1.0076x over previous
#include <cuda_runtime.h>
#include <cuda_fp16.h>
#include <math.h>
#include <stdint.h>

// Problem constants
#define BROWS 16384
#define D     1024

// Output layout: retrieved (B*D) | loss (1) | new_weight (D*D) | new_momentum (D*D) | gates (3)
#define RET_OFF   0
#define LOSS_OFF  (BROWS * D)
#define W_OFF     (LOSS_OFF + 1)              // odd -> scalar stores only
#define NM_OFF    (W_OFF + D * D)             // odd -> scalar stores only
#define GATES_OFF (NM_OFF + D * D)

#define MEM_MAX_NORM 5.0f
#define TTT_LR 0.005f
#define TWO_OVER_N (2.0f / (float)(BROWS * D))

// ---------------- device scratch (static, no runtime allocation) ----------------
__device__ float g_kagg_part[128][D];
__device__ float g_scalars[8];        // 0:alpha 1:eta 2:theta 4:scale_m 5:scale_w
__device__ float g_loss_part[1024];
__device__ float g_grad_part[4][D * D];   // split-B partials for GEMM2 (16 MB)
__device__ float g_norm_part[2][256];
__device__ volatile int g_ctr[2];         // 0..255 counting; -1 = scale ready (reset by kagg_gates)
__device__ __half g_k_h[BROWS * D];        // fp16 K, row-major [b][c] (32 MB)
__device__ __half g_w_h[D * D];            // fp16 W, row-major [n][k] (2 MB)
__device__ __half g_kT_h[D * BROWS];       // fp16 K^T [c][b] (32 MB)
__device__ __half g_diffT_h[D * BROWS];    // fp16 (retrieved-V)^T [i][b] (32 MB)

// ================= PTX helpers (family-portable, sm_80+) =================
__device__ __forceinline__ uint32_t pack_half(float a, float b) {
    __half2 h = __floats2half2_rn(a, b);
    return *(uint32_t*)&h;
}
__device__ __forceinline__ void mma_f16(float& c0, float& c1, float& c2, float& c3,
                                        uint32_t a0, uint32_t a1, uint32_t a2, uint32_t a3,
                                        uint32_t b0, uint32_t b1) {
    asm volatile(
        "mma.sync.aligned.m16n8k16.row.col.f32.f16.f16.f32 "
        "{%0,%1,%2,%3}, {%4,%5,%6,%7}, {%8,%9}, {%0,%1,%2,%3};"
        : "+f"(c0), "+f"(c1), "+f"(c2), "+f"(c3)
        : "r"(a0), "r"(a1), "r"(a2), "r"(a3), "r"(b0), "r"(b1));
}
__device__ __forceinline__ void ldsm_x4(uint32_t& r0, uint32_t& r1, uint32_t& r2, uint32_t& r3,
                                        uint32_t addr) {
    asm volatile("ldmatrix.sync.aligned.m8n8.x4.shared.b16 {%0,%1,%2,%3}, [%4];"
                 : "=r"(r0), "=r"(r1), "=r"(r2), "=r"(r3) : "r"(addr));
}
__device__ __forceinline__ uint32_t smem_u32(const void* p) {
    uint32_t a;
    asm("{ .reg .u64 t; cvta.to.shared.u64 t, %1; cvt.u32.u64 %0, t; }" : "=r"(a) : "l"(p));
    return a;
}
__device__ __forceinline__ void cp16(uint32_t dst, const void* src) {
    asm volatile("cp.async.cg.shared.global [%0], [%1], 16;" :: "r"(dst), "l"(src));
}
#define CP_COMMIT() asm volatile("cp.async.commit_group;" ::: "memory")
#define CP_WAIT1()  asm volatile("cp.async.wait_group 1;" ::: "memory")
#define CP_WAIT0()  asm volatile("cp.async.wait_group 0;" ::: "memory")

// K-chunk 64: stage = A(128x64 half = 16KB) + B(16KB) = 32KB = 8192 words
#define STAGE_WORDS 8192
#define B_OFF_WORDS 4096

// ---------------- colsum + fp16(K) + fp16 K^T + fp16(W) (fused prep) ----------------
__global__ __launch_bounds__(256) void colsum_prep_kernel(const float* __restrict__ K,
                                                          const float* __restrict__ W) {
    if (blockIdx.y == 128) {   // W conversion blocks (8 x 256 threads cover 1M elements)
        int base = (blockIdx.x * 256 + threadIdx.x) * 2;
        #pragma unroll
        for (int it = 0; it < 256; ++it) {
            int e = base + it * 4096;
            float2 w2 = *(const float2*)(W + e);
            *(uint32_t*)(&g_w_h[e]) = pack_half(w2.x, w2.y);
        }
        return;
    }
    __shared__ uint32_t st[128 * 64];
    __shared__ float red2[256];
    const int t  = threadIdx.x;
    const int cl = t & 127, rq = t >> 7;
    const int c  = blockIdx.x * 128 + cl;
    const int r0 = blockIdx.y * 128;

    float s = 0.f, prev = 0.f;
    #pragma unroll 4
    for (int i = 0; i < 64; ++i) {
        int r = r0 + rq * 64 + i;
        float kv = K[(size_t)r * D + c];
        s += kv;
        g_k_h[(size_t)r * D + c] = __float2half_rn(kv);
        if (i & 1) {
            int r2 = rq * 32 + (i >> 1);
            st[cl * 64 + (r2 ^ (cl & 31))] = pack_half(prev, kv);
        } else prev = kv;
    }
    red2[t] = s;
    __syncthreads();
    if (t < 128) g_kagg_part[blockIdx.y][blockIdx.x * 128 + t] = red2[t] + red2[t + 128];

    uint32_t* kTw = (uint32_t*)g_kT_h;
    size_t dstbase = ((size_t)(blockIdx.x * 128 + cl) * BROWS + r0) / 2 + rq * 32;
    #pragma unroll
    for (int q4 = 0; q4 < 32; q4 += 4) {
        uint4 vv;
        vv.x = st[cl * 64 + ((rq * 32 + q4 + 0) ^ (cl & 31))];
        vv.y = st[cl * 64 + ((rq * 32 + q4 + 1) ^ (cl & 31))];
        vv.z = st[cl * 64 + ((rq * 32 + q4 + 2) ^ (cl & 31))];
        vv.w = st[cl * 64 + ((rq * 32 + q4 + 3) ^ (cl & 31))];
        *(uint4*)(kTw + dstbase + q4) = vv;
    }
}

// ---------------- fused kagg + gates (+ counter reset for graph replay) ----------------
__global__ void kagg_gates_kernel(const float* __restrict__ GW, const float* __restrict__ GB,
                                  float* __restrict__ out) {
    __shared__ float red[1024];
    __shared__ float kag[1024];
    int t = threadIdx.x;
    if (t == 0) { g_ctr[0] = 0; g_ctr[1] = 0; }
    float s = 0.f;
    #pragma unroll 8
    for (int p = 0; p < 128; ++p) s += g_kagg_part[p][t];
    kag[t] = s * (1.0f / (float)BROWS);
    __syncthreads();
    for (int g = 0; g < 3; ++g) {
        red[t] = kag[t] * GW[g * D + t];
        __syncthreads();
        for (int st = 512; st > 0; st >>= 1) {
            if (t < st) red[t] += red[t + st];
            __syncthreads();
        }
        if (t == 0) {
            float z  = red[0] + GB[g];
            float sg = 1.0f / (1.0f + expf(-z));
            g_scalars[g] = sg;
            out[GATES_OFF + g] = sg;
        }
        __syncthreads();
    }
}

// ======= shared GEMM body pieces (4 warps, 64x64 warp tile, k64 chunks) =======
#define FRAG_SETUP()                                              \
    const int laneRowA = (lane & 7) | (lane & 8);                 \
    const int selA = lane >> 4;                                   \
    const int laneRowB = (lane & 7) | ((lane & 16) >> 1);         \
    const int selB = (lane >> 3) & 1;                             \
    uint32_t offA[4], swA4[4];                                    \
    _Pragma("unroll")                                             \
    for (int mt = 0; mt < 4; ++mt) {                              \
        int row = wm + mt * 16 + laneRowA;                        \
        offA[mt] = row * 128;                                     \
        swA4[mt] = row & 7;                                       \
    }                                                             \
    uint32_t offB[4], swB4[4];                                    \
    _Pragma("unroll")                                             \
    for (int np = 0; np < 4; ++np) {                              \
        int row = wn + np * 16 + laneRowB;                        \
        offB[np] = row * 128;                                     \
        swB4[np] = row & 7;                                       \
    }

#define CHUNK_COMPUTE(abase, bbase)                                                   \
    _Pragma("unroll")                                                                 \
    for (int ks = 0; ks < 4; ++ks) {                                                  \
        const int g0 = ks * 2;                                                        \
        uint32_t a[4][4], b[4][4];                                                    \
        _Pragma("unroll")                                                             \
        for (int mt = 0; mt < 4; ++mt)                                                \
            ldsm_x4(a[mt][0], a[mt][1], a[mt][2], a[mt][3],                           \
                    (abase) + offA[mt] + ((((uint32_t)(g0 + selA)) ^ swA4[mt]) << 4));\
        _Pragma("unroll")                                                             \
        for (int np = 0; np < 4; ++np)                                                \
            ldsm_x4(b[np][0], b[np][1], b[np][2], b[np][3],                           \
                    (bbase) + offB[np] + ((((uint32_t)(g0 + selB)) ^ swB4[np]) << 4));\
        _Pragma("unroll")                                                             \
        for (int mt = 0; mt < 4; ++mt)                                                \
            _Pragma("unroll")                                                         \
            for (int nt = 0; nt < 8; ++nt) {                                          \
                const int np = nt >> 1, lo = (nt & 1) * 2;                            \
                mma_f16(acc[mt][nt][0], acc[mt][nt][1], acc[mt][nt][2], acc[mt][nt][3],\
                        a[mt][0], a[mt][1], a[mt][2], a[mt][3], b[np][lo], b[np][lo + 1]);\
            }                                                                         \
    }

#define STAGE_CHUNK(stagebase, srcA, srcB)                                            \
    _Pragma("unroll")                                                                 \
    for (int it = 0; it < 8; ++it) {                                                  \
        int row = it * 16 + srow;                                                     \
        uint32_t wo = (uint32_t)(row * 32 + ((sg ^ (row & 7)) << 2));                 \
        cp16((stagebase) + wo * 4, (srcA) + (size_t)row * srcStrideA);                \
        cp16((stagebase) + (B_OFF_WORDS + wo) * 4, (srcB) + (size_t)row * srcStrideB);\
    }

// ---------------- GEMM1 (fp16, 64x64 warp tile): retrieved = K @ W^T ----------------
__global__ __launch_bounds__(128, 2) void gemm1_f16_kernel(
    const float* __restrict__ V, float* __restrict__ out) {
    extern __shared__ uint32_t sm1[];
    __shared__ float wred[4];
    const uint32_t sb = smem_u32(sm1);

    const int tid = threadIdx.x;
    const int warp = tid >> 5, lane = tid & 31;
    const int t4 = lane >> 2, tm4 = lane & 3;
    const int n0 = blockIdx.x * 128;
    const int m0 = blockIdx.y * 128;
    const int wm = (warp >> 1) * 64;
    const int wn = (warp & 1) * 64;

    float acc[4][8][4];
    #pragma unroll
    for (int i = 0; i < 4; ++i)
        #pragma unroll
        for (int j = 0; j < 8; ++j)
            #pragma unroll
            for (int r = 0; r < 4; ++r) acc[i][j][r] = 0.f;

    FRAG_SETUP();

    const int srow = tid >> 3, sg = tid & 7;
    const size_t srcStrideA = D, srcStrideB = D;
    const __half* gA = g_k_h + (size_t)m0 * D + sg * 8;
    const __half* gB = g_w_h + (size_t)n0 * D + sg * 8;

    #pragma unroll
    for (int s = 0; s < 2; ++s) {
        STAGE_CHUNK(sb + s * (STAGE_WORDS * 4), gA + s * 64, gB + s * 64);
        CP_COMMIT();
    }

    const int NCH = D / 64;   // 16 chunks
    for (int c = 0; c < NCH; ++c) {
        const int buf = c % 3;
        CP_WAIT1();
        __syncthreads();
        if (c + 2 < NCH) {
            const int nb = (c + 2) % 3;
            STAGE_CHUNK(sb + nb * (STAGE_WORDS * 4), gA + (c + 2) * 64, gB + (c + 2) * 64);
        }
        CP_COMMIT();

        const uint32_t abase = sb + buf * (STAGE_WORDS * 4);
        const uint32_t bbase = abase + B_OFF_WORDS * 4;
        CHUNK_COMPUTE(abase, bbase);
    }

    // ---- Epilogue ----
    CP_WAIT0();
    __syncthreads();   // pipeline smem free; reuse for diff repack

    float lsum = 0.f;
    #pragma unroll
    for (int mt = 0; mt < 4; ++mt) {
        #pragma unroll
        for (int nt = 0; nt < 8; ++nt) {
            int r   = wm + mt * 16 + t4;
            int ccl = wn + nt * 8 + 2 * tm4;
            int rg = m0 + r, cg = n0 + ccl;
            size_t e0 = (size_t)rg * D + cg;
            size_t e1 = (size_t)(rg + 8) * D + cg;
            float2 v0 = *(const float2*)(V + e0);
            float2 v1 = *(const float2*)(V + e1);
            float2 c0 = make_float2(acc[mt][nt][0], acc[mt][nt][1]);
            float2 c1 = make_float2(acc[mt][nt][2], acc[mt][nt][3]);
            *(float2*)(out + RET_OFF + e0) = c0;
            *(float2*)(out + RET_OFF + e1) = c1;
            float d0 = c0.x - v0.x, d1 = c0.y - v0.y;
            float d2 = c1.x - v1.x, d3 = c1.y - v1.y;
            int wrow = ccl >> 1;
            sm1[wrow * 136 + r]     = pack_half(d0, d1);
            sm1[wrow * 136 + r + 8] = pack_half(d2, d3);
            lsum += d0 * d0 + d1 * d1 + d2 * d2 + d3 * d3;
        }
    }
    #pragma unroll
    for (int o = 16; o > 0; o >>= 1) lsum += __shfl_xor_sync(0xffffffffu, lsum, o);
    if (lane == 0) wred[warp] = lsum;
    __syncthreads();

    for (int row = warp; row < 128; row += 4) {
        uint4 w = *(uint4*)&sm1[(row >> 1) * 136 + lane * 4];
        uint32_t sel = (row & 1) ? 0x7632u : 0x5410u;
        uint32_t lo = __byte_perm(w.x, w.y, sel);
        uint32_t hi = __byte_perm(w.z, w.w, sel);
        *(uint2*)&g_diffT_h[(size_t)(n0 + row) * BROWS + m0 + lane * 4] = make_uint2(lo, hi);
    }

    if (tid == 0)
        g_loss_part[blockIdx.y * 8 + blockIdx.x] = wred[0] + wred[1] + wred[2] + wred[3];
}

// ---------------- GEMM2 (fp16, 64x64 warp tile): grad_part[z] = diffT @ kT^T ----------------
__global__ __launch_bounds__(128, 2) void gemm2_f16_kernel() {
    extern __shared__ uint32_t sm2[];
    const uint32_t sb = smem_u32(sm2);

    const int tid = threadIdx.x;
    const int warp = tid >> 5, lane = tid & 31;
    const int t4 = lane >> 2, tm4 = lane & 3;
    const int j0 = blockIdx.x * 128;
    const int i0 = blockIdx.y * 128;
    const int z  = blockIdx.z;
    const int b0z = z * (BROWS / 4);
    const int wm = (warp >> 1) * 64;   // i
    const int wn = (warp & 1) * 64;    // j

    float acc[4][8][4];
    #pragma unroll
    for (int i = 0; i < 4; ++i)
        #pragma unroll
        for (int j = 0; j < 8; ++j)
            #pragma unroll
            for (int r = 0; r < 4; ++r) acc[i][j][r] = 0.f;

    FRAG_SETUP();

    const int srow = tid >> 3, sg = tid & 7;
    const size_t srcStrideA = BROWS, srcStrideB = BROWS;
    const __half* gA = g_diffT_h + (size_t)i0 * BROWS + b0z + sg * 8;
    const __half* gB = g_kT_h    + (size_t)j0 * BROWS + b0z + sg * 8;

    #pragma unroll
    for (int s = 0; s < 2; ++s) {
        STAGE_CHUNK(sb + s * (STAGE_WORDS * 4), gA + s * 64, gB + s * 64);
        CP_COMMIT();
    }

    const int NCH = (BROWS / 4) / 64;   // 64 chunks
    for (int c = 0; c < NCH; ++c) {
        const int buf = c % 3;
        CP_WAIT1();
        __syncthreads();
        if (c + 2 < NCH) {
            const int nb = (c + 2) % 3;
            STAGE_CHUNK(sb + nb * (STAGE_WORDS * 4), gA + (c + 2) * 64, gB + (c + 2) * 64);
        }
        CP_COMMIT();

        const uint32_t abase = sb + buf * (STAGE_WORDS * 4);
        const uint32_t bbase = abase + B_OFF_WORDS * 4;
        CHUNK_COMPUTE(abase, bbase);
    }

    float* gp = g_grad_part[z];
    #pragma unroll
    for (int mt = 0; mt < 4; ++mt) {
        #pragma unroll
        for (int nt = 0; nt < 8; ++nt) {
            int r  = i0 + wm + mt * 16 + t4;
            int cc = j0 + wn + nt * 8 + 2 * tm4;
            *(float2*)(gp + (size_t)r * D + cc)       = make_float2(acc[mt][nt][0], acc[mt][nt][1]);
            *(float2*)(gp + (size_t)(r + 8) * D + cc) = make_float2(acc[mt][nt][2], acc[mt][nt][3]);
        }
    }
}

// ---------------- fused update: loss + momentum + norm + weight + norm + final ----------------
// 256 blocks x 256 threads (all resident: <=2 blocks/SM). Grid-wide sync via
// last-block reduction + flag (g_ctr[i] -> -1). Counters pre-reset by kagg_gates.
__global__ __launch_bounds__(256) void fused_update_kernel(
    const float* __restrict__ MOM, const float* __restrict__ MW, float* __restrict__ out) {
    __shared__ float red[256];
    __shared__ int amLast;
    const int tid = threadIdx.x;
    const int t = blockIdx.x * 256 + tid;

    if (blockIdx.x == 0) {   // loss reduce (independent of grad)
        float ls = g_loss_part[tid] + g_loss_part[tid + 256] +
                   g_loss_part[tid + 512] + g_loss_part[tid + 768];
        red[tid] = ls;
        __syncthreads();
        for (int s = 128; s > 0; s >>= 1) {
            if (tid < s) red[tid] += red[tid + s];
            __syncthreads();
        }
        if (tid == 0) out[LOSS_OFF] = red[0] / (float)(BROWS * D);
        __syncthreads();
    }

    const float eta = g_scalars[1], theta = g_scalars[2];
    const float lr_th = TTT_LR * theta;
    const float one_m_a = 1.0f - g_scalars[0];

    // Phase 1: nm in registers + norm partial
    float nm[16];
    float nsum = 0.f;
    #pragma unroll
    for (int it = 0; it < 16; ++it) {
        int e = t + it * 65536;
        float g = (g_grad_part[0][e] + g_grad_part[1][e] +
                   g_grad_part[2][e] + g_grad_part[3][e]) * TWO_OVER_N;
        float gc = fminf(1.0f, fmaxf(-1.0f, g));
        nm[it] = eta * MOM[e] - lr_th * gc;
        nsum += nm[it] * nm[it];
    }
    red[tid] = nsum;
    __syncthreads();
    for (int s = 128; s > 0; s >>= 1) {
        if (tid < s) red[tid] += red[tid + s];
        __syncthreads();
    }
    if (tid == 0) {
        g_norm_part[0][blockIdx.x] = red[0];
        __threadfence();
        amLast = (atomicAdd((int*)&g_ctr[0], 1) == 255);
    }
    __syncthreads();
    if (amLast) {
        red[tid] = g_norm_part[0][tid];
        __syncthreads();
        for (int s = 128; s > 0; s >>= 1) {
            if (tid < s) red[tid] += red[tid + s];
            __syncthreads();
        }
        if (tid == 0) {
            float n = sqrtf(red[0]);
            g_scalars[4] = (n > MEM_MAX_NORM) ? (MEM_MAX_NORM / (n + 1e-8f)) : 1.0f;
            __threadfence();
            g_ctr[0] = -1;   // release
        }
    }
    if (tid == 0) { while (g_ctr[0] >= 0) { } }
    __syncthreads();
    __threadfence();
    const float sm_ = g_scalars[4];

    // Phase 2: nm output, w in registers + norm partial
    float w[16];
    float wsum = 0.f;
    #pragma unroll
    for (int it = 0; it < 16; ++it) {
        int e = t + it * 65536;
        float nmv = nm[it] * sm_;
        out[NM_OFF + e] = nmv;
        w[it] = one_m_a * MW[e] + nmv;
        wsum += w[it] * w[it];
    }
    red[tid] = wsum;
    __syncthreads();
    for (int s = 128; s > 0; s >>= 1) {
        if (tid < s) red[tid] += red[tid + s];
        __syncthreads();
    }
    if (tid == 0) {
        g_norm_part[1][blockIdx.x] = red[0];
        __threadfence();
        amLast = (atomicAdd((int*)&g_ctr[1], 1) == 255);
    }
    __syncthreads();
    if (amLast) {
        red[tid] = g_norm_part[1][tid];
        __syncthreads();
        for (int s = 128; s > 0; s >>= 1) {
            if (tid < s) red[tid] += red[tid + s];
            __syncthreads();
        }
        if (tid == 0) {
            float n = sqrtf(red[0]);
            g_scalars[5] = (n > MEM_MAX_NORM) ? (MEM_MAX_NORM / (n + 1e-8f)) : 1.0f;
            __threadfence();
            g_ctr[1] = -1;   // release
        }
    }
    if (tid == 0) { while (g_ctr[1] >= 0) { } }
    __syncthreads();
    __threadfence();
    const float sw = g_scalars[5];

    #pragma unroll
    for (int it = 0; it < 16; ++it) {
        int e = t + it * 65536;
        out[W_OFF + e] = w[it] * sw;
    }
}

// ---------------- launch ----------------
extern "C" void kernel_launch(void* const* d_in, const int* in_sizes, int n_in,
                              void* d_out, int out_size) {
    const float* k    = (const float*)d_in[0];
    const float* v    = (const float*)d_in[1];
    const float* memw = (const float*)d_in[2];
    const float* gw   = (const float*)d_in[3];
    const float* gb   = (const float*)d_in[4];
    const float* mom  = (const float*)d_in[5];
    float* out = (float*)d_out;

    const int g_smem = 3 * STAGE_WORDS * 4;   // 98304
    cudaFuncSetAttribute(gemm1_f16_kernel, cudaFuncAttributeMaxDynamicSharedMemorySize, g_smem);
    cudaFuncSetAttribute(gemm2_f16_kernel, cudaFuncAttributeMaxDynamicSharedMemorySize, g_smem);

    colsum_prep_kernel<<<dim3(8, 129), 256>>>(k, memw);       // + fused W conversion
    kagg_gates_kernel<<<1, 1024>>>(gw, gb, out);              // + counter reset
    gemm1_f16_kernel<<<dim3(8, 128), 128, g_smem>>>(v, out);
    gemm2_f16_kernel<<<dim3(8, 8, 4), 128, g_smem>>>();       // launch #4 -> ncu capture
    fused_update_kernel<<<256, 256>>>(mom, memw, out);
}